// round 1
// baseline (speedup 1.0000x reference)
#include <cuda_runtime.h>

// Problem constants
#define B_SZ   4
#define N_SEQ  2048
#define HEADS  16
#define EDIM   64
#define KDIM   1024
#define M_TOT  (B_SZ * N_SEQ)          // 8192
#define HID    (HEADS * EDIM)          // 1024

// Scratch (device globals — no allocation allowed)
__device__ float g_q  [B_SZ * HEADS * N_SEQ * EDIM];   // [b,h,n,e]  32MB
__device__ float g_k  [B_SZ * HEADS * N_SEQ * EDIM];
__device__ float g_v  [B_SZ * HEADS * N_SEQ * EDIM];
__device__ float g_att[M_TOT * HID];                   // [b,n,h*e]  32MB

// ---------------------------------------------------------------------------
// Generic NT GEMM:  C[m, c] = sum_k X[m,k] * W[c,k]   (both K-contiguous)
// 64x64 block tile, BK=16, 256 threads, 4x4 microtile.
// MODE 0: write Q proj into g_q  ([b,h,n,e] scatter)
// MODE 1: write KV proj into g_k / g_v
// MODE 2: read g_att as X, add bias, write to out [m, c]
// ---------------------------------------------------------------------------
template <int MODE>
__global__ __launch_bounds__(256) void gemm_nt(const float* __restrict__ X,
                                               const float* __restrict__ W,
                                               const float* __restrict__ bias,
                                               float* __restrict__ out)
{
    __shared__ float As[16][68];   // [k][m], padded (68*4B = 272B, 16B-aligned rows)
    __shared__ float Bs[16][68];   // [k][c]

    const float* Xp = (MODE == 2) ? g_att : X;

    const int tid  = threadIdx.x;
    const int ty   = tid >> 4;     // 0..15  (row group)
    const int tx   = tid & 15;     // 0..15  (col group)
    const int lrow = tid >> 2;     // 0..63  (load row)
    const int lq   = tid & 3;      // 0..3   (load k-quad)

    const int rowBase = blockIdx.y * 64;
    const int colBase = blockIdx.x * 64;

    float acc[4][4];
#pragma unroll
    for (int i = 0; i < 4; i++)
#pragma unroll
        for (int j = 0; j < 4; j++) acc[i][j] = 0.f;

    const float* aptr = Xp + (size_t)(rowBase + lrow) * KDIM + lq * 4;
    const float* bptr = W  + (size_t)(colBase + lrow) * KDIM + lq * 4;

    for (int ko = 0; ko < KDIM; ko += 16) {
        float4 av = *(const float4*)(aptr + ko);
        float4 bv = *(const float4*)(bptr + ko);
        As[lq * 4 + 0][lrow] = av.x;
        As[lq * 4 + 1][lrow] = av.y;
        As[lq * 4 + 2][lrow] = av.z;
        As[lq * 4 + 3][lrow] = av.w;
        Bs[lq * 4 + 0][lrow] = bv.x;
        Bs[lq * 4 + 1][lrow] = bv.y;
        Bs[lq * 4 + 2][lrow] = bv.z;
        Bs[lq * 4 + 3][lrow] = bv.w;
        __syncthreads();

#pragma unroll
        for (int kk = 0; kk < 16; kk++) {
            float4 a = *(const float4*)&As[kk][ty * 4];
            float4 b = *(const float4*)&Bs[kk][tx * 4];
            acc[0][0] += a.x * b.x; acc[0][1] += a.x * b.y; acc[0][2] += a.x * b.z; acc[0][3] += a.x * b.w;
            acc[1][0] += a.y * b.x; acc[1][1] += a.y * b.y; acc[1][2] += a.y * b.z; acc[1][3] += a.y * b.w;
            acc[2][0] += a.z * b.x; acc[2][1] += a.z * b.y; acc[2][2] += a.z * b.z; acc[2][3] += a.z * b.w;
            acc[3][0] += a.w * b.x; acc[3][1] += a.w * b.y; acc[3][2] += a.w * b.z; acc[3][3] += a.w * b.w;
        }
        __syncthreads();
    }

    // Epilogue
    const int c = colBase + tx * 4;
#pragma unroll
    for (int i = 0; i < 4; i++) {
        const int m = rowBase + ty * 4 + i;
        float4 v = make_float4(acc[i][0], acc[i][1], acc[i][2], acc[i][3]);
        if (MODE == 0) {
            const int b = m >> 11, n = m & 2047;
            const int h = c >> 6,  e = c & 63;
            *(float4*)&g_q[(((size_t)(b * HEADS + h) * N_SEQ + n) << 6) + e] = v;
        } else if (MODE == 1) {
            const int b = m >> 11, n = m & 2047;
            if (c < HID) {
                const int h = c >> 6, e = c & 63;
                *(float4*)&g_k[(((size_t)(b * HEADS + h) * N_SEQ + n) << 6) + e] = v;
            } else {
                const int c2 = c - HID;
                const int h = c2 >> 6, e = c2 & 63;
                *(float4*)&g_v[(((size_t)(b * HEADS + h) * N_SEQ + n) << 6) + e] = v;
            }
        } else {
            const float4 bb = *(const float4*)&bias[c];
            v.x += bb.x; v.y += bb.y; v.z += bb.z; v.w += bb.w;
            *(float4*)&out[(size_t)m * HID + c] = v;
        }
    }
}

// ---------------------------------------------------------------------------
// Flash attention (fp32, online softmax).
// grid = (N_SEQ/64, B*HEADS), 256 threads. Q tile 64x64 resident; loop over
// 32 K/V tiles of 64 rows. S-GEMM + softmax + P@V GEMM (P reuses K's smem).
// ---------------------------------------------------------------------------
__global__ __launch_bounds__(256) void attn_kernel()
{
    extern __shared__ float sm[];
    float* Qs = sm;                  // [64][68]  (transposed: [e][r])
    float* Ks = sm + 64 * 68;        // [64][68]  ([e][c]) — reused as Ps ([kk][r])
    float* Vs = sm + 2 * 64 * 68;    // [64][64]  ([kk][e])

    const int tid = threadIdx.x;
    const int ty  = tid >> 4;        // 0..15
    const int tx  = tid & 15;        // 0..15

    const int bh = blockIdx.y;       // b*16 + h
    const int b  = bh >> 4;
    const int h  = bh & 15;
    const int qRowBase = blockIdx.x * 64;
    const size_t bhbase = (size_t)bh * N_SEQ * EDIM;

    // Load Q tile (transposed into Qs[e][r])
#pragma unroll
    for (int rep = 0; rep < 4; rep++) {
        int idx = rep * 256 + tid;
        int r = idx >> 4;            // 0..63
        int g = idx & 15;            // float4 group over e
        float4 qv = *(const float4*)&g_q[bhbase + (size_t)(qRowBase + r) * EDIM + g * 4];
        Qs[(g * 4 + 0) * 68 + r] = qv.x;
        Qs[(g * 4 + 1) * 68 + r] = qv.y;
        Qs[(g * 4 + 2) * 68 + r] = qv.z;
        Qs[(g * 4 + 3) * 68 + r] = qv.w;
    }

    float o[4][4];
    float mrow[4], lrow_[4];
#pragma unroll
    for (int i = 0; i < 4; i++) {
        mrow[i] = -1e30f; lrow_[i] = 0.f;
#pragma unroll
        for (int j = 0; j < 4; j++) o[i][j] = 0.f;
    }

    for (int kt = 0; kt < N_SEQ / 64; kt++) {
        __syncthreads();   // prior iteration readers (and Q store on iter 0) done

        // Load K (transposed) and V (direct) tiles
#pragma unroll
        for (int rep = 0; rep < 4; rep++) {
            int idx = rep * 256 + tid;
            int r = idx >> 4;
            int g = idx & 15;
            size_t goff = bhbase + (size_t)(kt * 64 + r) * EDIM + g * 4;
            float4 kv = *(const float4*)&g_k[goff];
            Ks[(g * 4 + 0) * 68 + r] = kv.x;
            Ks[(g * 4 + 1) * 68 + r] = kv.y;
            Ks[(g * 4 + 2) * 68 + r] = kv.z;
            Ks[(g * 4 + 3) * 68 + r] = kv.w;
            float4 vv = *(const float4*)&g_v[goff];
            *(float4*)&Vs[r * 64 + g * 4] = vv;
        }
        __syncthreads();

        // S = Q @ K^T  (64x64x64)
        float s[4][4];
#pragma unroll
        for (int i = 0; i < 4; i++)
#pragma unroll
            for (int j = 0; j < 4; j++) s[i][j] = 0.f;
#pragma unroll 8
        for (int e = 0; e < 64; e++) {
            float4 a = *(const float4*)&Qs[e * 68 + ty * 4];
            float4 bq = *(const float4*)&Ks[e * 68 + tx * 4];
            s[0][0] += a.x * bq.x; s[0][1] += a.x * bq.y; s[0][2] += a.x * bq.z; s[0][3] += a.x * bq.w;
            s[1][0] += a.y * bq.x; s[1][1] += a.y * bq.y; s[1][2] += a.y * bq.z; s[1][3] += a.y * bq.w;
            s[2][0] += a.z * bq.x; s[2][1] += a.z * bq.y; s[2][2] += a.z * bq.z; s[2][3] += a.z * bq.w;
            s[3][0] += a.w * bq.x; s[3][1] += a.w * bq.y; s[3][2] += a.w * bq.z; s[3][3] += a.w * bq.w;
        }

        // Online softmax (rows ty*4+i; 16 tx-threads per row reduce via shfl)
        float p[4][4];
#pragma unroll
        for (int i = 0; i < 4; i++) {
            float lm = -1e30f;
#pragma unroll
            for (int j = 0; j < 4; j++) { s[i][j] *= 0.125f; lm = fmaxf(lm, s[i][j]); }
#pragma unroll
            for (int msk = 1; msk < 16; msk <<= 1)
                lm = fmaxf(lm, __shfl_xor_sync(0xffffffffu, lm, msk));
            float mnew = fmaxf(mrow[i], lm);
            float corr = __expf(mrow[i] - mnew);
            float ls = 0.f;
#pragma unroll
            for (int j = 0; j < 4; j++) { p[i][j] = __expf(s[i][j] - mnew); ls += p[i][j]; }
#pragma unroll
            for (int msk = 1; msk < 16; msk <<= 1)
                ls += __shfl_xor_sync(0xffffffffu, ls, msk);
            lrow_[i] = lrow_[i] * corr + ls;
            mrow[i] = mnew;
#pragma unroll
            for (int j = 0; j < 4; j++) o[i][j] *= corr;
        }

        __syncthreads();   // all threads done reading Ks

        // Write P into Ks buffer as Ps[kk][r]
#pragma unroll
        for (int i = 0; i < 4; i++)
#pragma unroll
            for (int j = 0; j < 4; j++)
                Ks[(tx * 4 + j) * 68 + (ty * 4 + i)] = p[i][j];
        __syncthreads();

        // O += P @ V  (64x64x64)
#pragma unroll 8
        for (int kk = 0; kk < 64; kk++) {
            float4 a = *(const float4*)&Ks[kk * 68 + ty * 4];
            float4 bv = *(const float4*)&Vs[kk * 64 + tx * 4];
            o[0][0] += a.x * bv.x; o[0][1] += a.x * bv.y; o[0][2] += a.x * bv.z; o[0][3] += a.x * bv.w;
            o[1][0] += a.y * bv.x; o[1][1] += a.y * bv.y; o[1][2] += a.y * bv.z; o[1][3] += a.y * bv.w;
            o[2][0] += a.z * bv.x; o[2][1] += a.z * bv.y; o[2][2] += a.z * bv.z; o[2][3] += a.z * bv.w;
            o[3][0] += a.w * bv.x; o[3][1] += a.w * bv.y; o[3][2] += a.w * bv.z; o[3][3] += a.w * bv.w;
        }
    }

    // Finalize: O / l, write [b, n, h*64 + e]
#pragma unroll
    for (int i = 0; i < 4; i++) {
        float inv = 1.f / lrow_[i];
        int n = qRowBase + ty * 4 + i;
        float4 v = make_float4(o[i][0] * inv, o[i][1] * inv, o[i][2] * inv, o[i][3] * inv);
        *(float4*)&g_att[(size_t)(b * N_SEQ + n) * HID + h * EDIM + tx * 4] = v;
    }
}

// ---------------------------------------------------------------------------
extern "C" void kernel_launch(void* const* d_in, const int* in_sizes, int n_in,
                              void* d_out, int out_size)
{
    (void)in_sizes; (void)n_in; (void)out_size;
    const float* x     = (const float*)d_in[0];
    const float* w_q   = (const float*)d_in[1];
    const float* w_kv  = (const float*)d_in[2];
    const float* w_out = (const float*)d_in[3];
    const float* b_out = (const float*)d_in[4];
    float* out = (float*)d_out;

    const int attn_smem = (2 * 64 * 68 + 64 * 64) * 4;   // 51200 B
    cudaFuncSetAttribute(attn_kernel, cudaFuncAttributeMaxDynamicSharedMemorySize, attn_smem);

    // Q projection:  [8192,1024] x [1024,1024]^T
    gemm_nt<0><<<dim3(HID / 64, M_TOT / 64), 256>>>(x, w_q, nullptr, nullptr);
    // KV projection: [8192,1024] x [2048,1024]^T
    gemm_nt<1><<<dim3(2 * HID / 64, M_TOT / 64), 256>>>(x, w_kv, nullptr, nullptr);
    // Attention
    attn_kernel<<<dim3(N_SEQ / 64, B_SZ * HEADS), 256, attn_smem>>>();
    // Output projection + bias
    gemm_nt<2><<<dim3(HID / 64, M_TOT / 64), 256>>>(nullptr, w_out, b_out, out);
}

// round 4
// speedup vs baseline: 1.3732x; 1.3732x over previous
#include <cuda_runtime.h>
#include <cuda_bf16.h>
#include <cstdint>

// Problem constants
#define B_SZ   4
#define N_SEQ  2048
#define HEADS  16
#define EDIM   64
#define KDIM   1024
#define M_TOT  (B_SZ * N_SEQ)          // 8192
#define HID    (HEADS * EDIM)          // 1024

// ---------------------------------------------------------------------------
// Scratch (device globals — no allocation allowed)
// ---------------------------------------------------------------------------
__device__ float g_q[B_SZ * HEADS * N_SEQ * EDIM];   // [b,h,n,e]
__device__ float g_k[B_SZ * HEADS * N_SEQ * EDIM];
__device__ float g_v[B_SZ * HEADS * N_SEQ * EDIM];

__device__ __nv_bfloat16 g_xh[M_TOT * KDIM],     g_xl[M_TOT * KDIM];
__device__ __nv_bfloat16 g_wqh[HID * KDIM],      g_wql[HID * KDIM];
__device__ __nv_bfloat16 g_wkvh[2 * HID * KDIM], g_wkvl[2 * HID * KDIM];
__device__ __nv_bfloat16 g_woh[HID * KDIM],      g_wol[HID * KDIM];
__device__ __nv_bfloat16 g_atth[M_TOT * HID],    g_attl[M_TOT * HID];

// ---------------------------------------------------------------------------
// Base-target-safe PTX helpers (sm_80+ features only)
// ---------------------------------------------------------------------------
__device__ __forceinline__ uint32_t smem_u32(const void* p) {
    uint32_t a;
    asm("{ .reg .u64 t; cvta.to.shared.u64 t, %1; cvt.u32.u64 %0, t; }" : "=r"(a) : "l"(p));
    return a;
}

#define CP16(s, g) \
    asm volatile("cp.async.cg.shared.global [%0], [%1], 16;" :: "r"(s), "l"(g) : "memory")
#define CPCOMMIT() asm volatile("cp.async.commit_group;" ::: "memory")
#define CPWAIT(n)  asm volatile("cp.async.wait_group %0;" :: "n"(n) : "memory")

#define LDSM4(R, addr)                                                            \
    asm volatile("ldmatrix.sync.aligned.m8n8.x4.shared.b16 {%0,%1,%2,%3}, [%4];"  \
        : "=r"((R)[0]), "=r"((R)[1]), "=r"((R)[2]), "=r"((R)[3]) : "r"(addr))
#define LDSM2(R, addr)                                                            \
    asm volatile("ldmatrix.sync.aligned.m8n8.x2.shared.b16 {%0,%1}, [%2];"        \
        : "=r"((R)[0]), "=r"((R)[1]) : "r"(addr))

#define MMA16816(d, a, b)                                                         \
    asm volatile("mma.sync.aligned.m16n8k16.row.col.f32.bf16.bf16.f32 "           \
        "{%0,%1,%2,%3}, {%4,%5,%6,%7}, {%8,%9}, {%0,%1,%2,%3};"                   \
        : "+f"((d)[0]), "+f"((d)[1]), "+f"((d)[2]), "+f"((d)[3])                  \
        : "r"((a)[0]), "r"((a)[1]), "r"((a)[2]), "r"((a)[3]),                     \
          "r"((b)[0]), "r"((b)[1]))

// ---------------------------------------------------------------------------
// Split fp32 -> (hi, lo) bf16 pairs
// ---------------------------------------------------------------------------
__global__ __launch_bounds__(256) void split_bf16_k(const float* __restrict__ s,
                                                    __nv_bfloat16* __restrict__ hi,
                                                    __nv_bfloat16* __restrict__ lo, int n4)
{
    int i = blockIdx.x * 256 + threadIdx.x;
    if (i >= n4) return;
    float4 v = ((const float4*)s)[i];
    __nv_bfloat16 h0 = __float2bfloat16(v.x), h1 = __float2bfloat16(v.y);
    __nv_bfloat16 h2 = __float2bfloat16(v.z), h3 = __float2bfloat16(v.w);
    __nv_bfloat16 l0 = __float2bfloat16(v.x - __bfloat162float(h0));
    __nv_bfloat16 l1 = __float2bfloat16(v.y - __bfloat162float(h1));
    __nv_bfloat16 l2 = __float2bfloat16(v.z - __bfloat162float(h2));
    __nv_bfloat16 l3 = __float2bfloat16(v.w - __bfloat162float(h3));
    ((__nv_bfloat162*)hi)[i * 2 + 0] = __halves2bfloat162(h0, h1);
    ((__nv_bfloat162*)hi)[i * 2 + 1] = __halves2bfloat162(h2, h3);
    ((__nv_bfloat162*)lo)[i * 2 + 0] = __halves2bfloat162(l0, l1);
    ((__nv_bfloat162*)lo)[i * 2 + 1] = __halves2bfloat162(l2, l3);
}

// ---------------------------------------------------------------------------
// mma.sync GEMM: C[m,c] = sum_k A[m,k]*B[c,k], emulated fp32 via split bf16
// (D = Ah*Bh + Ah*Bl + Al*Bh, fp32 accum).
// 128x128 block tile, 8 warps (2x4), 64x32 warp tile, K-chunk 32,
// 3-stage cp.async pipeline, smem row stride 40 bf16 (ldmatrix conflict-free).
// Each thread copies a FULL 32B row-segment (2x cp.async 16B) per matrix.
// MODE 0: -> g_q scatter   MODE 1: -> g_k/g_v scatter   MODE 2: -> out + bias
// ---------------------------------------------------------------------------
#define STR     40
#define MATB    (128 * STR * 2)        // 10240 bytes per matrix per stage
#define STAGEB  (4 * MATB)             // 40960
#define STAGES  3
#define NKC     (KDIM / 32)            // 32 k-chunks

template <int MODE>
__global__ __launch_bounds__(256, 1) void gemm_mma(
    const __nv_bfloat16* __restrict__ Agh, const __nv_bfloat16* __restrict__ Agl,
    const __nv_bfloat16* __restrict__ Bgh, const __nv_bfloat16* __restrict__ Bgl,
    const float* __restrict__ bias, float* __restrict__ out)
{
    extern __shared__ char dsm[];
    const uint32_t sb0 = smem_u32(dsm);

    const int tid  = threadIdx.x;
    const int wid  = tid >> 5;
    const int lane = tid & 31;
    const int wm   = wid >> 2;          // 0..1
    const int wn   = wid & 3;           // 0..3
    const int rowBase = blockIdx.y * 128;
    const int colBase = blockIdx.x * 128;

    // Per-thread cp.async task: row lr (0..127), 32B half lh (0..1).
    // Each thread copies 16 consecutive elements (32B) = 2 x CP16.
    const int lr  = tid >> 1;
    const int lh  = tid & 1;
    const uint32_t soff = (uint32_t)(lr * STR + lh * 16) * 2;   // bytes
    const size_t gAoff = (size_t)(rowBase + lr) * KDIM + lh * 16;
    const size_t gBoff = (size_t)(colBase + lr) * KDIM + lh * 16;

    // ldmatrix lane offsets (bytes)
    const uint32_t aoff = (uint32_t)((lane & 15) * STR + ((lane >> 4) << 3)) * 2;
    const uint32_t boff = (uint32_t)((lane & 7) * STR + (((lane >> 3) & 1) << 3)) * 2;

    float acc[4][4][4];
#pragma unroll
    for (int mi = 0; mi < 4; mi++)
#pragma unroll
        for (int ni = 0; ni < 4; ni++)
#pragma unroll
            for (int q = 0; q < 4; q++) acc[mi][ni][q] = 0.f;

#define LOAD_STAGE(st, ko)                                                   \
    do {                                                                     \
        CP16((st) +            soff,      Agh + gAoff + (ko));               \
        CP16((st) +            soff + 16, Agh + gAoff + (ko) + 8);           \
        CP16((st) + 1 * MATB + soff,      Agl + gAoff + (ko));               \
        CP16((st) + 1 * MATB + soff + 16, Agl + gAoff + (ko) + 8);           \
        CP16((st) + 2 * MATB + soff,      Bgh + gBoff + (ko));               \
        CP16((st) + 2 * MATB + soff + 16, Bgh + gBoff + (ko) + 8);           \
        CP16((st) + 3 * MATB + soff,      Bgl + gBoff + (ko));               \
        CP16((st) + 3 * MATB + soff + 16, Bgl + gBoff + (ko) + 8);           \
        CPCOMMIT();                                                          \
    } while (0)

    // ---- pipeline prologue: issue stages 0..STAGES-2 ----
#pragma unroll
    for (int s = 0; s < STAGES - 1; s++) {
        LOAD_STAGE(sb0 + s * STAGEB, (size_t)s * 32);
    }

    for (int kc = 0; kc < NKC; kc++) {
        const int pre = kc + STAGES - 1;
        if (pre < NKC) {
            LOAD_STAGE(sb0 + (pre % STAGES) * STAGEB, (size_t)pre * 32);
            CPWAIT(2);
        } else if (kc + 2 == NKC) {
            CPWAIT(1);
        } else {
            CPWAIT(0);
        }
        __syncthreads();

        const uint32_t st = sb0 + (kc % STAGES) * STAGEB;
        const uint32_t sAh = st, sAl = st + MATB, sBh = st + 2 * MATB, sBl = st + 3 * MATB;

#pragma unroll
        for (int ks = 0; ks < 2; ks++) {
            const uint32_t kso = (uint32_t)(ks * 16) * 2;

            uint32_t bh[4][2], bl[4][2];
#pragma unroll
            for (int ni = 0; ni < 4; ni++) {
                const uint32_t nb = (uint32_t)((wn * 32 + ni * 8) * STR) * 2 + kso;
                LDSM2(bh[ni], sBh + nb + boff);
                LDSM2(bl[ni], sBl + nb + boff);
            }
#pragma unroll
            for (int mi = 0; mi < 4; mi++) {
                const uint32_t mb = (uint32_t)((wm * 64 + mi * 16) * STR) * 2 + kso;
                uint32_t ah[4], al[4];
                LDSM4(ah, sAh + mb + aoff);
                LDSM4(al, sAl + mb + aoff);
#pragma unroll
                for (int ni = 0; ni < 4; ni++) {
                    MMA16816(acc[mi][ni], ah, bh[ni]);
                    MMA16816(acc[mi][ni], ah, bl[ni]);
                    MMA16816(acc[mi][ni], al, bh[ni]);
                }
            }
        }
        __syncthreads();   // buffer reuse guard
    }

    // ---- epilogue ----
    const int qrow = lane >> 2;        // 0..7
    const int qcol = lane & 3;         // 0..3
#pragma unroll
    for (int mi = 0; mi < 4; mi++) {
#pragma unroll
        for (int ni = 0; ni < 4; ni++) {
            const int c  = colBase + wn * 32 + ni * 8 + qcol * 2;
            const int m0 = rowBase + wm * 64 + mi * 16 + qrow;
            const int m1 = m0 + 8;
            float2 v0 = make_float2(acc[mi][ni][0], acc[mi][ni][1]);
            float2 v1 = make_float2(acc[mi][ni][2], acc[mi][ni][3]);
            if (MODE == 0) {
                const int h = c >> 6, e = c & 63;
                const int b0 = m0 >> 11, n0 = m0 & 2047;
                const int b1 = m1 >> 11, n1 = m1 & 2047;
                *(float2*)&g_q[(((size_t)(b0 * HEADS + h) * N_SEQ + n0) << 6) + e] = v0;
                *(float2*)&g_q[(((size_t)(b1 * HEADS + h) * N_SEQ + n1) << 6) + e] = v1;
            } else if (MODE == 1) {
                const int b0 = m0 >> 11, n0 = m0 & 2047;
                const int b1 = m1 >> 11, n1 = m1 & 2047;
                if (c < HID) {
                    const int h = c >> 6, e = c & 63;
                    *(float2*)&g_k[(((size_t)(b0 * HEADS + h) * N_SEQ + n0) << 6) + e] = v0;
                    *(float2*)&g_k[(((size_t)(b1 * HEADS + h) * N_SEQ + n1) << 6) + e] = v1;
                } else {
                    const int c2 = c - HID;
                    const int h = c2 >> 6, e = c2 & 63;
                    *(float2*)&g_v[(((size_t)(b0 * HEADS + h) * N_SEQ + n0) << 6) + e] = v0;
                    *(float2*)&g_v[(((size_t)(b1 * HEADS + h) * N_SEQ + n1) << 6) + e] = v1;
                }
            } else {
                const float2 bb = *(const float2*)&bias[c];
                v0.x += bb.x; v0.y += bb.y;
                v1.x += bb.x; v1.y += bb.y;
                *(float2*)&out[(size_t)m0 * HID + c] = v0;
                *(float2*)&out[(size_t)m1 * HID + c] = v1;
            }
        }
    }
}

// ---------------------------------------------------------------------------
// Flash attention (fp32, online softmax). Epilogue writes split-bf16 for the
// out-projection GEMM.
// ---------------------------------------------------------------------------
__global__ __launch_bounds__(256) void attn_kernel()
{
    extern __shared__ float sm[];
    float* Qs = sm;                  // [64][68]  ([e][r])
    float* Ks = sm + 64 * 68;        // [64][68]  ([e][c]) — reused as Ps ([kk][r])
    float* Vs = sm + 2 * 64 * 68;    // [64][64]  ([kk][e])

    const int tid = threadIdx.x;
    const int ty  = tid >> 4;
    const int tx  = tid & 15;

    const int bh = blockIdx.y;
    const int b  = bh >> 4;
    const int h  = bh & 15;
    const int qRowBase = blockIdx.x * 64;
    const size_t bhbase = (size_t)bh * N_SEQ * EDIM;

#pragma unroll
    for (int rep = 0; rep < 4; rep++) {
        int idx = rep * 256 + tid;
        int r = idx >> 4;
        int g = idx & 15;
        float4 qv = *(const float4*)&g_q[bhbase + (size_t)(qRowBase + r) * EDIM + g * 4];
        Qs[(g * 4 + 0) * 68 + r] = qv.x;
        Qs[(g * 4 + 1) * 68 + r] = qv.y;
        Qs[(g * 4 + 2) * 68 + r] = qv.z;
        Qs[(g * 4 + 3) * 68 + r] = qv.w;
    }

    float o[4][4];
    float mrow[4], lrow_[4];
#pragma unroll
    for (int i = 0; i < 4; i++) {
        mrow[i] = -1e30f; lrow_[i] = 0.f;
#pragma unroll
        for (int j = 0; j < 4; j++) o[i][j] = 0.f;
    }

    for (int kt = 0; kt < N_SEQ / 64; kt++) {
        __syncthreads();

#pragma unroll
        for (int rep = 0; rep < 4; rep++) {
            int idx = rep * 256 + tid;
            int r = idx >> 4;
            int g = idx & 15;
            size_t goff = bhbase + (size_t)(kt * 64 + r) * EDIM + g * 4;
            float4 kv = *(const float4*)&g_k[goff];
            Ks[(g * 4 + 0) * 68 + r] = kv.x;
            Ks[(g * 4 + 1) * 68 + r] = kv.y;
            Ks[(g * 4 + 2) * 68 + r] = kv.z;
            Ks[(g * 4 + 3) * 68 + r] = kv.w;
            float4 vv = *(const float4*)&g_v[goff];
            *(float4*)&Vs[r * 64 + g * 4] = vv;
        }
        __syncthreads();

        float s[4][4];
#pragma unroll
        for (int i = 0; i < 4; i++)
#pragma unroll
            for (int j = 0; j < 4; j++) s[i][j] = 0.f;
#pragma unroll 8
        for (int e = 0; e < 64; e++) {
            float4 a = *(const float4*)&Qs[e * 68 + ty * 4];
            float4 bq = *(const float4*)&Ks[e * 68 + tx * 4];
            s[0][0] += a.x * bq.x; s[0][1] += a.x * bq.y; s[0][2] += a.x * bq.z; s[0][3] += a.x * bq.w;
            s[1][0] += a.y * bq.x; s[1][1] += a.y * bq.y; s[1][2] += a.y * bq.z; s[1][3] += a.y * bq.w;
            s[2][0] += a.z * bq.x; s[2][1] += a.z * bq.y; s[2][2] += a.z * bq.z; s[2][3] += a.z * bq.w;
            s[3][0] += a.w * bq.x; s[3][1] += a.w * bq.y; s[3][2] += a.w * bq.z; s[3][3] += a.w * bq.w;
        }

        float p[4][4];
#pragma unroll
        for (int i = 0; i < 4; i++) {
            float lm = -1e30f;
#pragma unroll
            for (int j = 0; j < 4; j++) { s[i][j] *= 0.125f; lm = fmaxf(lm, s[i][j]); }
#pragma unroll
            for (int msk = 1; msk < 16; msk <<= 1)
                lm = fmaxf(lm, __shfl_xor_sync(0xffffffffu, lm, msk));
            float mnew = fmaxf(mrow[i], lm);
            float corr = __expf(mrow[i] - mnew);
            float ls = 0.f;
#pragma unroll
            for (int j = 0; j < 4; j++) { p[i][j] = __expf(s[i][j] - mnew); ls += p[i][j]; }
#pragma unroll
            for (int msk = 1; msk < 16; msk <<= 1)
                ls += __shfl_xor_sync(0xffffffffu, ls, msk);
            lrow_[i] = lrow_[i] * corr + ls;
            mrow[i] = mnew;
#pragma unroll
            for (int j = 0; j < 4; j++) o[i][j] *= corr;
        }

        __syncthreads();

#pragma unroll
        for (int i = 0; i < 4; i++)
#pragma unroll
            for (int j = 0; j < 4; j++)
                Ks[(tx * 4 + j) * 68 + (ty * 4 + i)] = p[i][j];
        __syncthreads();

#pragma unroll 8
        for (int kk = 0; kk < 64; kk++) {
            float4 a = *(const float4*)&Ks[kk * 68 + ty * 4];
            float4 bv = *(const float4*)&Vs[kk * 64 + tx * 4];
            o[0][0] += a.x * bv.x; o[0][1] += a.x * bv.y; o[0][2] += a.x * bv.z; o[0][3] += a.x * bv.w;
            o[1][0] += a.y * bv.x; o[1][1] += a.y * bv.y; o[1][2] += a.y * bv.z; o[1][3] += a.y * bv.w;
            o[2][0] += a.z * bv.x; o[2][1] += a.z * bv.y; o[2][2] += a.z * bv.z; o[2][3] += a.z * bv.w;
            o[3][0] += a.w * bv.x; o[3][1] += a.w * bv.y; o[3][2] += a.w * bv.z; o[3][3] += a.w * bv.w;
        }
    }

    // Finalize: O / l, split to bf16 hi/lo at [b, n, h*64 + e]
#pragma unroll
    for (int i = 0; i < 4; i++) {
        float inv = 1.f / lrow_[i];
        int n = qRowBase + ty * 4 + i;
        size_t base = (size_t)(b * N_SEQ + n) * HID + h * EDIM + tx * 4;
        float v0 = o[i][0] * inv, v1 = o[i][1] * inv, v2 = o[i][2] * inv, v3 = o[i][3] * inv;
        __nv_bfloat16 h0 = __float2bfloat16(v0), h1 = __float2bfloat16(v1);
        __nv_bfloat16 h2 = __float2bfloat16(v2), h3 = __float2bfloat16(v3);
        __nv_bfloat16 l0 = __float2bfloat16(v0 - __bfloat162float(h0));
        __nv_bfloat16 l1 = __float2bfloat16(v1 - __bfloat162float(h1));
        __nv_bfloat16 l2 = __float2bfloat16(v2 - __bfloat162float(h2));
        __nv_bfloat16 l3 = __float2bfloat16(v3 - __bfloat162float(h3));
        ((__nv_bfloat162*)&g_atth[base])[0] = __halves2bfloat162(h0, h1);
        ((__nv_bfloat162*)&g_atth[base])[1] = __halves2bfloat162(h2, h3);
        ((__nv_bfloat162*)&g_attl[base])[0] = __halves2bfloat162(l0, l1);
        ((__nv_bfloat162*)&g_attl[base])[1] = __halves2bfloat162(l2, l3);
    }
}

// ---------------------------------------------------------------------------
extern "C" void kernel_launch(void* const* d_in, const int* in_sizes, int n_in,
                              void* d_out, int out_size)
{
    (void)in_sizes; (void)n_in; (void)out_size;
    const float* x     = (const float*)d_in[0];
    const float* w_q   = (const float*)d_in[1];
    const float* w_kv  = (const float*)d_in[2];
    const float* w_out = (const float*)d_in[3];
    const float* b_out = (const float*)d_in[4];
    float* out = (float*)d_out;

    void *p_xh, *p_xl, *p_wqh, *p_wql, *p_wkvh, *p_wkvl, *p_woh, *p_wol, *p_ath, *p_atl;
    cudaGetSymbolAddress(&p_xh, g_xh);     cudaGetSymbolAddress(&p_xl, g_xl);
    cudaGetSymbolAddress(&p_wqh, g_wqh);   cudaGetSymbolAddress(&p_wql, g_wql);
    cudaGetSymbolAddress(&p_wkvh, g_wkvh); cudaGetSymbolAddress(&p_wkvl, g_wkvl);
    cudaGetSymbolAddress(&p_woh, g_woh);   cudaGetSymbolAddress(&p_wol, g_wol);
    cudaGetSymbolAddress(&p_ath, g_atth);  cudaGetSymbolAddress(&p_atl, g_attl);

    const int gemm_smem = STAGES * STAGEB;   // 122880
    cudaFuncSetAttribute(gemm_mma<0>, cudaFuncAttributeMaxDynamicSharedMemorySize, gemm_smem);
    cudaFuncSetAttribute(gemm_mma<1>, cudaFuncAttributeMaxDynamicSharedMemorySize, gemm_smem);
    cudaFuncSetAttribute(gemm_mma<2>, cudaFuncAttributeMaxDynamicSharedMemorySize, gemm_smem);
    const int attn_smem = (2 * 64 * 68 + 64 * 64) * 4;
    cudaFuncSetAttribute(attn_kernel, cudaFuncAttributeMaxDynamicSharedMemorySize, attn_smem);

    // 1) Split fp32 inputs into bf16 hi/lo
    split_bf16_k<<<(M_TOT * KDIM / 4 + 255) / 256, 256>>>(x, (__nv_bfloat16*)p_xh, (__nv_bfloat16*)p_xl, M_TOT * KDIM / 4);
    split_bf16_k<<<(HID * KDIM / 4 + 255) / 256, 256>>>(w_q, (__nv_bfloat16*)p_wqh, (__nv_bfloat16*)p_wql, HID * KDIM / 4);
    split_bf16_k<<<(2 * HID * KDIM / 4 + 255) / 256, 256>>>(w_kv, (__nv_bfloat16*)p_wkvh, (__nv_bfloat16*)p_wkvl, 2 * HID * KDIM / 4);
    split_bf16_k<<<(HID * KDIM / 4 + 255) / 256, 256>>>(w_out, (__nv_bfloat16*)p_woh, (__nv_bfloat16*)p_wol, HID * KDIM / 4);

    // 2) Projections (mma.sync bf16-split)
    gemm_mma<0><<<dim3(HID / 128, M_TOT / 128), 256, gemm_smem>>>(
        (const __nv_bfloat16*)p_xh, (const __nv_bfloat16*)p_xl,
        (const __nv_bfloat16*)p_wqh, (const __nv_bfloat16*)p_wql, nullptr, nullptr);
    gemm_mma<1><<<dim3(2 * HID / 128, M_TOT / 128), 256, gemm_smem>>>(
        (const __nv_bfloat16*)p_xh, (const __nv_bfloat16*)p_xl,
        (const __nv_bfloat16*)p_wkvh, (const __nv_bfloat16*)p_wkvl, nullptr, nullptr);

    // 3) Attention (fp32 SIMT)
    attn_kernel<<<dim3(N_SEQ / 64, B_SZ * HEADS), 256, attn_smem>>>();

    // 4) Output projection + bias (mma.sync bf16-split)
    gemm_mma<2><<<dim3(HID / 128, M_TOT / 128), 256, gemm_smem>>>(
        (const __nv_bfloat16*)p_ath, (const __nv_bfloat16*)p_atl,
        (const __nv_bfloat16*)p_woh, (const __nv_bfloat16*)p_wol, b_out, out);
}

// round 5
// speedup vs baseline: 2.7999x; 2.0390x over previous
#include <cuda_runtime.h>
#include <cuda_bf16.h>
#include <cstdint>

// Problem constants
#define B_SZ   4
#define N_SEQ  2048
#define HEADS  16
#define EDIM   64
#define KDIM   1024
#define M_TOT  (B_SZ * N_SEQ)          // 8192
#define HID    (HEADS * EDIM)          // 1024
#define BH     (B_SZ * HEADS)          // 64

// ---------------------------------------------------------------------------
// Scratch (device globals — no allocation allowed)
// ---------------------------------------------------------------------------
__device__ __nv_bfloat16 g_xh[M_TOT * KDIM],     g_xl[M_TOT * KDIM];
__device__ __nv_bfloat16 g_wqh[HID * KDIM],      g_wql[HID * KDIM];
__device__ __nv_bfloat16 g_wkvh[2 * HID * KDIM], g_wkvl[2 * HID * KDIM];
__device__ __nv_bfloat16 g_woh[HID * KDIM],      g_wol[HID * KDIM];
__device__ __nv_bfloat16 g_atth[M_TOT * HID],    g_attl[M_TOT * HID];

// Split-bf16 Q/K ([bh, n, e]) and V transposed ([bh, e, n])
__device__ __nv_bfloat16 g_qh[BH * N_SEQ * EDIM], g_ql[BH * N_SEQ * EDIM];
__device__ __nv_bfloat16 g_kh[BH * N_SEQ * EDIM], g_kl[BH * N_SEQ * EDIM];
__device__ __nv_bfloat16 g_vth[BH * EDIM * N_SEQ], g_vtl[BH * EDIM * N_SEQ];

// ---------------------------------------------------------------------------
// Base-target-safe PTX helpers (sm_80+ features only)
// ---------------------------------------------------------------------------
__device__ __forceinline__ uint32_t smem_u32(const void* p) {
    uint32_t a;
    asm("{ .reg .u64 t; cvta.to.shared.u64 t, %1; cvt.u32.u64 %0, t; }" : "=r"(a) : "l"(p));
    return a;
}

#define CP16(s, g) \
    asm volatile("cp.async.cg.shared.global [%0], [%1], 16;" :: "r"(s), "l"(g) : "memory")
#define CPCOMMIT() asm volatile("cp.async.commit_group;" ::: "memory")
#define CPWAIT(n)  asm volatile("cp.async.wait_group %0;" :: "n"(n) : "memory")

#define LDSM4(R, addr)                                                            \
    asm volatile("ldmatrix.sync.aligned.m8n8.x4.shared.b16 {%0,%1,%2,%3}, [%4];"  \
        : "=r"((R)[0]), "=r"((R)[1]), "=r"((R)[2]), "=r"((R)[3]) : "r"(addr))
#define LDSM2(R, addr)                                                            \
    asm volatile("ldmatrix.sync.aligned.m8n8.x2.shared.b16 {%0,%1}, [%2];"        \
        : "=r"((R)[0]), "=r"((R)[1]) : "r"(addr))

#define MMA16816(d, a, b)                                                         \
    asm volatile("mma.sync.aligned.m16n8k16.row.col.f32.bf16.bf16.f32 "           \
        "{%0,%1,%2,%3}, {%4,%5,%6,%7}, {%8,%9}, {%0,%1,%2,%3};"                   \
        : "+f"((d)[0]), "+f"((d)[1]), "+f"((d)[2]), "+f"((d)[3])                  \
        : "r"((a)[0]), "r"((a)[1]), "r"((a)[2]), "r"((a)[3]),                     \
          "r"((b)[0]), "r"((b)[1]))

// split pair of fp32 into packed bf16 hi / lo words
__device__ __forceinline__ void split2(float a, float b, uint32_t& h2, uint32_t& l2) {
    __nv_bfloat162 hh = __floats2bfloat162_rn(a, b);
    float fa = __bfloat162float(hh.x), fb = __bfloat162float(hh.y);
    __nv_bfloat162 ll = __floats2bfloat162_rn(a - fa, b - fb);
    h2 = *(uint32_t*)&hh;
    l2 = *(uint32_t*)&ll;
}

// ---------------------------------------------------------------------------
// Split fp32 -> (hi, lo) bf16 pairs
// ---------------------------------------------------------------------------
__global__ __launch_bounds__(256) void split_bf16_k(const float* __restrict__ s,
                                                    __nv_bfloat16* __restrict__ hi,
                                                    __nv_bfloat16* __restrict__ lo, int n4)
{
    int i = blockIdx.x * 256 + threadIdx.x;
    if (i >= n4) return;
    float4 v = ((const float4*)s)[i];
    uint32_t h0, l0, h1, l1;
    split2(v.x, v.y, h0, l0);
    split2(v.z, v.w, h1, l1);
    ((uint32_t*)hi)[i * 2 + 0] = h0;
    ((uint32_t*)hi)[i * 2 + 1] = h1;
    ((uint32_t*)lo)[i * 2 + 0] = l0;
    ((uint32_t*)lo)[i * 2 + 1] = l1;
}

// ---------------------------------------------------------------------------
// mma.sync GEMM: C[m,c] = sum_k A[m,k]*B[c,k], emulated fp32 via split bf16.
// 128x128 block tile, 8 warps (2x4), 64x32 warp tile, K-chunk 32, 3-stage
// cp.async pipeline, smem row stride 40 bf16.
// MODE 0: Q proj -> split-bf16 g_qh/g_ql (scaled by 0.125)
// MODE 1: KV proj -> split-bf16 g_kh/g_kl, g_vth/g_vtl (V transposed)
// MODE 2: out proj -> fp32 out + bias
// ---------------------------------------------------------------------------
#define STR     40
#define MATB    (128 * STR * 2)        // 10240 bytes per matrix per stage
#define STAGEB  (4 * MATB)             // 40960
#define STAGES  3
#define NKC     (KDIM / 32)            // 32 k-chunks

template <int MODE>
__global__ __launch_bounds__(256, 1) void gemm_mma(
    const __nv_bfloat16* __restrict__ Agh, const __nv_bfloat16* __restrict__ Agl,
    const __nv_bfloat16* __restrict__ Bgh, const __nv_bfloat16* __restrict__ Bgl,
    const float* __restrict__ bias, float* __restrict__ out)
{
    extern __shared__ char dsm[];
    const uint32_t sb0 = smem_u32(dsm);

    const int tid  = threadIdx.x;
    const int wid  = tid >> 5;
    const int lane = tid & 31;
    const int wm   = wid >> 2;          // 0..1
    const int wn   = wid & 3;           // 0..3
    const int rowBase = blockIdx.y * 128;
    const int colBase = blockIdx.x * 128;

    const int lr  = tid >> 1;
    const int lh  = tid & 1;
    const uint32_t soff = (uint32_t)(lr * STR + lh * 16) * 2;
    const size_t gAoff = (size_t)(rowBase + lr) * KDIM + lh * 16;
    const size_t gBoff = (size_t)(colBase + lr) * KDIM + lh * 16;

    const uint32_t aoff = (uint32_t)((lane & 15) * STR + ((lane >> 4) << 3)) * 2;
    const uint32_t boff = (uint32_t)((lane & 7) * STR + (((lane >> 3) & 1) << 3)) * 2;

    float acc[4][4][4];
#pragma unroll
    for (int mi = 0; mi < 4; mi++)
#pragma unroll
        for (int ni = 0; ni < 4; ni++)
#pragma unroll
            for (int q = 0; q < 4; q++) acc[mi][ni][q] = 0.f;

#define LOAD_STAGE(st, ko)                                                   \
    do {                                                                     \
        CP16((st) +            soff,      Agh + gAoff + (ko));               \
        CP16((st) +            soff + 16, Agh + gAoff + (ko) + 8);           \
        CP16((st) + 1 * MATB + soff,      Agl + gAoff + (ko));               \
        CP16((st) + 1 * MATB + soff + 16, Agl + gAoff + (ko) + 8);           \
        CP16((st) + 2 * MATB + soff,      Bgh + gBoff + (ko));               \
        CP16((st) + 2 * MATB + soff + 16, Bgh + gBoff + (ko) + 8);           \
        CP16((st) + 3 * MATB + soff,      Bgl + gBoff + (ko));               \
        CP16((st) + 3 * MATB + soff + 16, Bgl + gBoff + (ko) + 8);           \
        CPCOMMIT();                                                          \
    } while (0)

#pragma unroll
    for (int s = 0; s < STAGES - 1; s++) {
        LOAD_STAGE(sb0 + s * STAGEB, (size_t)s * 32);
    }

    for (int kc = 0; kc < NKC; kc++) {
        const int pre = kc + STAGES - 1;
        if (pre < NKC) {
            LOAD_STAGE(sb0 + (pre % STAGES) * STAGEB, (size_t)pre * 32);
            CPWAIT(2);
        } else if (kc + 2 == NKC) {
            CPWAIT(1);
        } else {
            CPWAIT(0);
        }
        __syncthreads();

        const uint32_t st = sb0 + (kc % STAGES) * STAGEB;
        const uint32_t sAh = st, sAl = st + MATB, sBh = st + 2 * MATB, sBl = st + 3 * MATB;

#pragma unroll
        for (int ks = 0; ks < 2; ks++) {
            const uint32_t kso = (uint32_t)(ks * 16) * 2;

            uint32_t bh[4][2], bl[4][2];
#pragma unroll
            for (int ni = 0; ni < 4; ni++) {
                const uint32_t nb = (uint32_t)((wn * 32 + ni * 8) * STR) * 2 + kso;
                LDSM2(bh[ni], sBh + nb + boff);
                LDSM2(bl[ni], sBl + nb + boff);
            }
#pragma unroll
            for (int mi = 0; mi < 4; mi++) {
                const uint32_t mb = (uint32_t)((wm * 64 + mi * 16) * STR) * 2 + kso;
                uint32_t ah[4], al[4];
                LDSM4(ah, sAh + mb + aoff);
                LDSM4(al, sAl + mb + aoff);
#pragma unroll
                for (int ni = 0; ni < 4; ni++) {
                    MMA16816(acc[mi][ni], ah, bh[ni]);
                    MMA16816(acc[mi][ni], ah, bl[ni]);
                    MMA16816(acc[mi][ni], al, bh[ni]);
                }
            }
        }
        __syncthreads();
    }

    // ---- epilogue ----
    const int qrow = lane >> 2;
    const int qcol = lane & 3;
#pragma unroll
    for (int mi = 0; mi < 4; mi++) {
#pragma unroll
        for (int ni = 0; ni < 4; ni++) {
            const int c  = colBase + wn * 32 + ni * 8 + qcol * 2;
            const int m0 = rowBase + wm * 64 + mi * 16 + qrow;
            const int m1 = m0 + 8;
            float2 v0 = make_float2(acc[mi][ni][0], acc[mi][ni][1]);
            float2 v1 = make_float2(acc[mi][ni][2], acc[mi][ni][3]);
            const int b0 = m0 >> 11, n0 = m0 & 2047;
            const int b1 = m1 >> 11, n1 = m1 & 2047;
            if (MODE == 0) {
                // Q: scale by 1/8 (exact), split, [bh, n, e]
                const int h = c >> 6, e = c & 63;
                const size_t i0 = ((size_t)(b0 * HEADS + h) * N_SEQ + n0) * EDIM + e;
                const size_t i1 = ((size_t)(b1 * HEADS + h) * N_SEQ + n1) * EDIM + e;
                uint32_t h2, l2;
                split2(v0.x * 0.125f, v0.y * 0.125f, h2, l2);
                *(uint32_t*)&g_qh[i0] = h2; *(uint32_t*)&g_ql[i0] = l2;
                split2(v1.x * 0.125f, v1.y * 0.125f, h2, l2);
                *(uint32_t*)&g_qh[i1] = h2; *(uint32_t*)&g_ql[i1] = l2;
            } else if (MODE == 1) {
                if (c < HID) {
                    // K: split, [bh, n, e]
                    const int h = c >> 6, e = c & 63;
                    const size_t i0 = ((size_t)(b0 * HEADS + h) * N_SEQ + n0) * EDIM + e;
                    const size_t i1 = ((size_t)(b1 * HEADS + h) * N_SEQ + n1) * EDIM + e;
                    uint32_t h2, l2;
                    split2(v0.x, v0.y, h2, l2);
                    *(uint32_t*)&g_kh[i0] = h2; *(uint32_t*)&g_kl[i0] = l2;
                    split2(v1.x, v1.y, h2, l2);
                    *(uint32_t*)&g_kh[i1] = h2; *(uint32_t*)&g_kl[i1] = l2;
                } else {
                    // V: split, TRANSPOSED [bh, e, n]
                    const int c2 = c - HID;
                    const int h = c2 >> 6, e = c2 & 63;
                    const int bh0 = b0 * HEADS + h, bh1 = b1 * HEADS + h;
                    float vals[4] = {v0.x, v0.y, v1.x, v1.y};
                    int es[4] = {e, e + 1, e, e + 1};
                    int bhs[4] = {bh0, bh0, bh1, bh1};
                    int ns[4] = {n0, n0, n1, n1};
#pragma unroll
                    for (int q = 0; q < 4; q++) {
                        const size_t idx = ((size_t)bhs[q] * EDIM + es[q]) * N_SEQ + ns[q];
                        __nv_bfloat16 hv = __float2bfloat16(vals[q]);
                        g_vth[idx] = hv;
                        g_vtl[idx] = __float2bfloat16(vals[q] - __bfloat162float(hv));
                    }
                }
            } else {
                const float2 bb = *(const float2*)&bias[c];
                v0.x += bb.x; v0.y += bb.y;
                v1.x += bb.x; v1.y += bb.y;
                *(float2*)&out[(size_t)m0 * HID + c] = v0;
                *(float2*)&out[(size_t)m1 * HID + c] = v1;
            }
        }
    }
}

// ---------------------------------------------------------------------------
// Tensor-core flash attention (split-bf16, fp32 accum, online softmax).
// grid = (N_SEQ/128, BH), 256 threads (8 warps x 16 Q-rows).
// K/V tiles of 64 keys, double-buffered cp.async.
// S = Qh*Kh + Qh*Kl + Ql*Kh ; O += Ph*Vh + Ph*Vl + Pl*Vh.
// ---------------------------------------------------------------------------
#define ASTR  72                       // smem row stride in bf16 (144 B)
#define AMATB (64 * ASTR * 2)          // 9216 bytes per matrix
#define ASTGB (4 * AMATB)              // 36864 per stage
#define NT    (N_SEQ / 64)             // 32 key tiles

__global__ __launch_bounds__(256, 1) void attn_mma()
{
    extern __shared__ char dsm[];
    const uint32_t sb = smem_u32(dsm);

    const int tid  = threadIdx.x;
    const int wid  = tid >> 5;
    const int lane = tid & 31;
    const int qg   = lane >> 2;          // 0..7
    const int tig  = lane & 3;           // 0..3

    const int bh    = blockIdx.y;
    const int qbase = blockIdx.x * 128 + wid * 16;
    const size_t kvbase = (size_t)bh * N_SEQ * EDIM;   // same for K ([n,e]) and Vt ([e,n])

    // ---- Q fragments (A operand), resident in registers ----
    uint32_t qhf[4][4], qlf[4][4];
    {
        const size_t q0 = kvbase + (size_t)(qbase + qg) * EDIM;       // row qg
        const size_t q8 = q0 + 8 * EDIM;                              // row qg+8
#pragma unroll
        for (int kc = 0; kc < 4; kc++) {
            const int col = kc * 16 + tig * 2;
            qhf[kc][0] = *(const uint32_t*)&g_qh[q0 + col];
            qhf[kc][1] = *(const uint32_t*)&g_qh[q8 + col];
            qhf[kc][2] = *(const uint32_t*)&g_qh[q0 + col + 8];
            qhf[kc][3] = *(const uint32_t*)&g_qh[q8 + col + 8];
            qlf[kc][0] = *(const uint32_t*)&g_ql[q0 + col];
            qlf[kc][1] = *(const uint32_t*)&g_ql[q8 + col];
            qlf[kc][2] = *(const uint32_t*)&g_ql[q0 + col + 8];
            qlf[kc][3] = *(const uint32_t*)&g_ql[q8 + col + 8];
        }
    }

    float oacc[8][4];
#pragma unroll
    for (int ne = 0; ne < 8; ne++)
#pragma unroll
        for (int q = 0; q < 4; q++) oacc[ne][q] = 0.f;
    float m0 = -1e30f, m1 = -1e30f, lp0 = 0.f, lp1 = 0.f;

    // smem matrix offsets within a stage
    const uint32_t OKH = 0, OKL = AMATB, OVH = 2 * AMATB, OVL = 3 * AMATB;

    // cp.async: per matrix, 64 rows x 8 chunks of 16B; 512 chunks / 256 thr = 2 each
#define AT_LOAD(stg, kt)                                                        \
    do {                                                                        \
        _Pragma("unroll")                                                       \
        for (int t = 0; t < 2; t++) {                                           \
            const int idx = tid + t * 256;                                      \
            const int r = idx >> 3, ch = idx & 7;                               \
            const uint32_t so = (stg) + (uint32_t)(r * 144 + ch * 16);          \
            const size_t kg = kvbase + (size_t)((kt) * 64 + r) * EDIM + ch * 8; \
            const size_t vg = kvbase + (size_t)r * N_SEQ + (kt) * 64 + ch * 8;  \
            CP16(so + OKH, g_kh  + kg);                                         \
            CP16(so + OKL, g_kl  + kg);                                         \
            CP16(so + OVH, g_vth + vg);                                         \
            CP16(so + OVL, g_vtl + vg);                                         \
        }                                                                       \
        CPCOMMIT();                                                             \
    } while (0)

    AT_LOAD(sb, 0);

    const uint32_t lmoff = (uint32_t)((lane & 7) * ASTR + (((lane >> 3) & 1) << 3)) * 2;

    for (int kt = 0; kt < NT; kt++) {
        if (kt + 1 < NT) {
            AT_LOAD(sb + ((kt + 1) & 1) * ASTGB, kt + 1);
            CPWAIT(1);
        } else {
            CPWAIT(0);
        }
        __syncthreads();

        const uint32_t stg = sb + (kt & 1) * ASTGB;

        // ---- S = Q @ K^T (fp32 acc via 3-term split) ----
        float sacc[8][4];
#pragma unroll
        for (int nt = 0; nt < 8; nt++)
#pragma unroll
            for (int q = 0; q < 4; q++) sacc[nt][q] = 0.f;

#pragma unroll
        for (int kc = 0; kc < 4; kc++) {
            const uint32_t kso = (uint32_t)(kc * 16) * 2;
#pragma unroll
            for (int nt = 0; nt < 8; nt++) {
                uint32_t kh2[2], kl2[2];
                const uint32_t off = (uint32_t)(nt * 8 * ASTR) * 2 + kso + lmoff;
                LDSM2(kh2, stg + OKH + off);
                LDSM2(kl2, stg + OKL + off);
                MMA16816(sacc[nt], qhf[kc], kh2);
                MMA16816(sacc[nt], qhf[kc], kl2);
                MMA16816(sacc[nt], qlf[kc], kh2);
            }
        }

        // ---- online softmax (rows qg, qg+8) ----
        float mx0 = -1e30f, mx1 = -1e30f;
#pragma unroll
        for (int nt = 0; nt < 8; nt++) {
            mx0 = fmaxf(mx0, fmaxf(sacc[nt][0], sacc[nt][1]));
            mx1 = fmaxf(mx1, fmaxf(sacc[nt][2], sacc[nt][3]));
        }
        mx0 = fmaxf(mx0, __shfl_xor_sync(0xffffffffu, mx0, 1));
        mx0 = fmaxf(mx0, __shfl_xor_sync(0xffffffffu, mx0, 2));
        mx1 = fmaxf(mx1, __shfl_xor_sync(0xffffffffu, mx1, 1));
        mx1 = fmaxf(mx1, __shfl_xor_sync(0xffffffffu, mx1, 2));

        const float mn0 = fmaxf(m0, mx0), mn1 = fmaxf(m1, mx1);
        const float corr0 = __expf(m0 - mn0), corr1 = __expf(m1 - mn1);
        m0 = mn0; m1 = mn1;

        float ls0 = 0.f, ls1 = 0.f;
#pragma unroll
        for (int nt = 0; nt < 8; nt++) {
            sacc[nt][0] = __expf(sacc[nt][0] - mn0);
            sacc[nt][1] = __expf(sacc[nt][1] - mn0);
            sacc[nt][2] = __expf(sacc[nt][2] - mn1);
            sacc[nt][3] = __expf(sacc[nt][3] - mn1);
            ls0 += sacc[nt][0] + sacc[nt][1];
            ls1 += sacc[nt][2] + sacc[nt][3];
        }
        lp0 = lp0 * corr0 + ls0;
        lp1 = lp1 * corr1 + ls1;

#pragma unroll
        for (int ne = 0; ne < 8; ne++) {
            oacc[ne][0] *= corr0; oacc[ne][1] *= corr0;
            oacc[ne][2] *= corr1; oacc[ne][3] *= corr1;
        }

        // ---- pack P (A-fragments for PV), split hi/lo ----
        uint32_t phf[4][4], plf[4][4];
#pragma unroll
        for (int kc = 0; kc < 4; kc++) {
            split2(sacc[2 * kc][0],     sacc[2 * kc][1],     phf[kc][0], plf[kc][0]);
            split2(sacc[2 * kc][2],     sacc[2 * kc][3],     phf[kc][1], plf[kc][1]);
            split2(sacc[2 * kc + 1][0], sacc[2 * kc + 1][1], phf[kc][2], plf[kc][2]);
            split2(sacc[2 * kc + 1][2], sacc[2 * kc + 1][3], phf[kc][3], plf[kc][3]);
        }

        // ---- O += P @ V ----
#pragma unroll
        for (int kc = 0; kc < 4; kc++) {
            const uint32_t kso = (uint32_t)(kc * 16) * 2;
#pragma unroll
            for (int ne = 0; ne < 8; ne++) {
                uint32_t vh2[2], vl2[2];
                const uint32_t off = (uint32_t)(ne * 8 * ASTR) * 2 + kso + lmoff;
                LDSM2(vh2, stg + OVH + off);
                LDSM2(vl2, stg + OVL + off);
                MMA16816(oacc[ne], phf[kc], vh2);
                MMA16816(oacc[ne], phf[kc], vl2);
                MMA16816(oacc[ne], plf[kc], vh2);
            }
        }
        __syncthreads();   // compute done before next AT_LOAD overwrites this buffer
    }

    // ---- finalize: O / l, split to bf16 hi/lo at [b, n, h*64 + e] ----
    lp0 += __shfl_xor_sync(0xffffffffu, lp0, 1);
    lp0 += __shfl_xor_sync(0xffffffffu, lp0, 2);
    lp1 += __shfl_xor_sync(0xffffffffu, lp1, 1);
    lp1 += __shfl_xor_sync(0xffffffffu, lp1, 2);
    const float inv0 = 1.f / lp0, inv1 = 1.f / lp1;

    const int b = bh >> 4, h = bh & 15;
    const int n0 = qbase + qg, n1 = n0 + 8;
    const size_t o0 = (size_t)(b * N_SEQ + n0) * HID + h * EDIM;
    const size_t o1 = (size_t)(b * N_SEQ + n1) * HID + h * EDIM;
#pragma unroll
    for (int ne = 0; ne < 8; ne++) {
        const int e = ne * 8 + tig * 2;
        uint32_t h2, l2;
        split2(oacc[ne][0] * inv0, oacc[ne][1] * inv0, h2, l2);
        *(uint32_t*)&g_atth[o0 + e] = h2; *(uint32_t*)&g_attl[o0 + e] = l2;
        split2(oacc[ne][2] * inv1, oacc[ne][3] * inv1, h2, l2);
        *(uint32_t*)&g_atth[o1 + e] = h2; *(uint32_t*)&g_attl[o1 + e] = l2;
    }
}

// ---------------------------------------------------------------------------
extern "C" void kernel_launch(void* const* d_in, const int* in_sizes, int n_in,
                              void* d_out, int out_size)
{
    (void)in_sizes; (void)n_in; (void)out_size;
    const float* x     = (const float*)d_in[0];
    const float* w_q   = (const float*)d_in[1];
    const float* w_kv  = (const float*)d_in[2];
    const float* w_out = (const float*)d_in[3];
    const float* b_out = (const float*)d_in[4];
    float* out = (float*)d_out;

    void *p_xh, *p_xl, *p_wqh, *p_wql, *p_wkvh, *p_wkvl, *p_woh, *p_wol, *p_ath, *p_atl;
    cudaGetSymbolAddress(&p_xh, g_xh);     cudaGetSymbolAddress(&p_xl, g_xl);
    cudaGetSymbolAddress(&p_wqh, g_wqh);   cudaGetSymbolAddress(&p_wql, g_wql);
    cudaGetSymbolAddress(&p_wkvh, g_wkvh); cudaGetSymbolAddress(&p_wkvl, g_wkvl);
    cudaGetSymbolAddress(&p_woh, g_woh);   cudaGetSymbolAddress(&p_wol, g_wol);
    cudaGetSymbolAddress(&p_ath, g_atth);  cudaGetSymbolAddress(&p_atl, g_attl);

    const int gemm_smem = STAGES * STAGEB;   // 122880
    cudaFuncSetAttribute(gemm_mma<0>, cudaFuncAttributeMaxDynamicSharedMemorySize, gemm_smem);
    cudaFuncSetAttribute(gemm_mma<1>, cudaFuncAttributeMaxDynamicSharedMemorySize, gemm_smem);
    cudaFuncSetAttribute(gemm_mma<2>, cudaFuncAttributeMaxDynamicSharedMemorySize, gemm_smem);
    const int attn_smem = 2 * ASTGB;         // 73728
    cudaFuncSetAttribute(attn_mma, cudaFuncAttributeMaxDynamicSharedMemorySize, attn_smem);

    // 1) Split fp32 inputs into bf16 hi/lo
    split_bf16_k<<<(M_TOT * KDIM / 4 + 255) / 256, 256>>>(x, (__nv_bfloat16*)p_xh, (__nv_bfloat16*)p_xl, M_TOT * KDIM / 4);
    split_bf16_k<<<(HID * KDIM / 4 + 255) / 256, 256>>>(w_q, (__nv_bfloat16*)p_wqh, (__nv_bfloat16*)p_wql, HID * KDIM / 4);
    split_bf16_k<<<(2 * HID * KDIM / 4 + 255) / 256, 256>>>(w_kv, (__nv_bfloat16*)p_wkvh, (__nv_bfloat16*)p_wkvl, 2 * HID * KDIM / 4);
    split_bf16_k<<<(HID * KDIM / 4 + 255) / 256, 256>>>(w_out, (__nv_bfloat16*)p_woh, (__nv_bfloat16*)p_wol, HID * KDIM / 4);

    // 2) Projections (mma.sync bf16-split) -> split-bf16 Q/K/V
    gemm_mma<0><<<dim3(HID / 128, M_TOT / 128), 256, gemm_smem>>>(
        (const __nv_bfloat16*)p_xh, (const __nv_bfloat16*)p_xl,
        (const __nv_bfloat16*)p_wqh, (const __nv_bfloat16*)p_wql, nullptr, nullptr);
    gemm_mma<1><<<dim3(2 * HID / 128, M_TOT / 128), 256, gemm_smem>>>(
        (const __nv_bfloat16*)p_xh, (const __nv_bfloat16*)p_xl,
        (const __nv_bfloat16*)p_wkvh, (const __nv_bfloat16*)p_wkvl, nullptr, nullptr);

    // 3) Attention (mma.sync bf16-split flash attention)
    attn_mma<<<dim3(N_SEQ / 128, BH), 256, attn_smem>>>();

    // 4) Output projection + bias (mma.sync bf16-split)
    gemm_mma<2><<<dim3(HID / 128, M_TOT / 128), 256, gemm_smem>>>(
        (const __nv_bfloat16*)p_ath, (const __nv_bfloat16*)p_atl,
        (const __nv_bfloat16*)p_woh, (const __nv_bfloat16*)p_wol, b_out, out);
}

// round 6
// speedup vs baseline: 2.9015x; 1.0363x over previous
#include <cuda_runtime.h>
#include <cuda_bf16.h>
#include <cstdint>

// Problem constants
#define B_SZ   4
#define N_SEQ  2048
#define HEADS  16
#define EDIM   64
#define KDIM   1024
#define M_TOT  (B_SZ * N_SEQ)          // 8192
#define HID    (HEADS * EDIM)          // 1024
#define BH     (B_SZ * HEADS)          // 64

// ---------------------------------------------------------------------------
// Scratch (device globals — no allocation allowed)
// ---------------------------------------------------------------------------
__device__ __nv_bfloat16 g_xh[M_TOT * KDIM],     g_xl[M_TOT * KDIM];
__device__ __nv_bfloat16 g_wqh[HID * KDIM],      g_wql[HID * KDIM];
__device__ __nv_bfloat16 g_wkvh[2 * HID * KDIM], g_wkvl[2 * HID * KDIM];
__device__ __nv_bfloat16 g_woh[HID * KDIM],      g_wol[HID * KDIM];
__device__ __nv_bfloat16 g_atth[M_TOT * HID],    g_attl[M_TOT * HID];

// Split-bf16 Q/K ([bh, n, e]) and V transposed ([bh, e, n])
__device__ __nv_bfloat16 g_qh[BH * N_SEQ * EDIM], g_ql[BH * N_SEQ * EDIM];
__device__ __nv_bfloat16 g_kh[BH * N_SEQ * EDIM], g_kl[BH * N_SEQ * EDIM];
__device__ __nv_bfloat16 g_vth[BH * EDIM * N_SEQ], g_vtl[BH * EDIM * N_SEQ];

// ---------------------------------------------------------------------------
// Base-target-safe PTX helpers (sm_80+ features only)
// ---------------------------------------------------------------------------
__device__ __forceinline__ uint32_t smem_u32(const void* p) {
    uint32_t a;
    asm("{ .reg .u64 t; cvta.to.shared.u64 t, %1; cvt.u32.u64 %0, t; }" : "=r"(a) : "l"(p));
    return a;
}

#define CP16(s, g) \
    asm volatile("cp.async.cg.shared.global [%0], [%1], 16;" :: "r"(s), "l"(g) : "memory")
#define CPCOMMIT() asm volatile("cp.async.commit_group;" ::: "memory")
#define CPWAIT(n)  asm volatile("cp.async.wait_group %0;" :: "n"(n) : "memory")

#define LDSM4(R, addr)                                                            \
    asm volatile("ldmatrix.sync.aligned.m8n8.x4.shared.b16 {%0,%1,%2,%3}, [%4];"  \
        : "=r"((R)[0]), "=r"((R)[1]), "=r"((R)[2]), "=r"((R)[3]) : "r"(addr))

#define MMA16816(d, a, b)                                                         \
    asm volatile("mma.sync.aligned.m16n8k16.row.col.f32.bf16.bf16.f32 "           \
        "{%0,%1,%2,%3}, {%4,%5,%6,%7}, {%8,%9}, {%0,%1,%2,%3};"                   \
        : "+f"((d)[0]), "+f"((d)[1]), "+f"((d)[2]), "+f"((d)[3])                  \
        : "r"((a)[0]), "r"((a)[1]), "r"((a)[2]), "r"((a)[3]),                     \
          "r"((b)[0]), "r"((b)[1]))

// split pair of fp32 into packed bf16 hi / lo words
__device__ __forceinline__ void split2(float a, float b, uint32_t& h2, uint32_t& l2) {
    __nv_bfloat162 hh = __floats2bfloat162_rn(a, b);
    float fa = __bfloat162float(hh.x), fb = __bfloat162float(hh.y);
    __nv_bfloat162 ll = __floats2bfloat162_rn(a - fa, b - fb);
    h2 = *(uint32_t*)&hh;
    l2 = *(uint32_t*)&ll;
}

// ---------------------------------------------------------------------------
// Split fp32 -> (hi, lo) bf16 pairs
// ---------------------------------------------------------------------------
__global__ __launch_bounds__(256) void split_bf16_k(const float* __restrict__ s,
                                                    __nv_bfloat16* __restrict__ hi,
                                                    __nv_bfloat16* __restrict__ lo, int n4)
{
    int i = blockIdx.x * 256 + threadIdx.x;
    if (i >= n4) return;
    float4 v = ((const float4*)s)[i];
    uint32_t h0, l0, h1, l1;
    split2(v.x, v.y, h0, l0);
    split2(v.z, v.w, h1, l1);
    ((uint32_t*)hi)[i * 2 + 0] = h0;
    ((uint32_t*)hi)[i * 2 + 1] = h1;
    ((uint32_t*)lo)[i * 2 + 0] = l0;
    ((uint32_t*)lo)[i * 2 + 1] = l1;
}

// ---------------------------------------------------------------------------
// mma.sync GEMM: C[m,c] = sum_k A[m,k]*B[c,k], emulated fp32 via split bf16.
// 128x128 block tile, 8 warps (2x4), 64x32 warp tile, K-chunk 32, 4-stage
// cp.async pipeline with ONE __syncthreads per chunk, B via paired ldmatrix.x4.
// MODE 0: Q proj -> split-bf16 g_qh/g_ql (scaled by 0.125)
// MODE 1: KV proj -> split-bf16 g_kh/g_kl, g_vth/g_vtl (V transposed)
// MODE 2: out proj -> fp32 out + bias
// ---------------------------------------------------------------------------
#define STR     40
#define MATB    (128 * STR * 2)        // 10240 bytes per matrix per stage
#define STAGEB  (4 * MATB)             // 40960
#define STAGES  4
#define NKC     (KDIM / 32)            // 32 k-chunks

template <int MODE>
__global__ __launch_bounds__(256, 1) void gemm_mma(
    const __nv_bfloat16* __restrict__ Agh, const __nv_bfloat16* __restrict__ Agl,
    const __nv_bfloat16* __restrict__ Bgh, const __nv_bfloat16* __restrict__ Bgl,
    const float* __restrict__ bias, float* __restrict__ out)
{
    extern __shared__ char dsm[];
    const uint32_t sb0 = smem_u32(dsm);

    const int tid  = threadIdx.x;
    const int wid  = tid >> 5;
    const int lane = tid & 31;
    const int wm   = wid >> 2;          // 0..1
    const int wn   = wid & 3;           // 0..3
    const int rowBase = blockIdx.y * 128;
    const int colBase = blockIdx.x * 128;

    const int lr  = tid >> 1;
    const int lh  = tid & 1;
    const uint32_t soff = (uint32_t)(lr * STR + lh * 16) * 2;
    const size_t gAoff = (size_t)(rowBase + lr) * KDIM + lh * 16;
    const size_t gBoff = (size_t)(colBase + lr) * KDIM + lh * 16;

    // ldmatrix lane offsets (bytes): A x4 (16 rows x k-halves), B x4 (16 n-rows x k-halves)
    const uint32_t aoff  = (uint32_t)((lane & 15) * STR + ((lane >> 4) << 3)) * 2;
    const uint32_t boff4 = (uint32_t)(((lane & 7) + ((lane >> 4) << 3)) * STR
                                      + (((lane >> 3) & 1) << 3)) * 2;

    float acc[4][4][4];
#pragma unroll
    for (int mi = 0; mi < 4; mi++)
#pragma unroll
        for (int ni = 0; ni < 4; ni++)
#pragma unroll
            for (int q = 0; q < 4; q++) acc[mi][ni][q] = 0.f;

#define LOAD_STAGE(st, ko)                                                   \
    do {                                                                     \
        CP16((st) +            soff,      Agh + gAoff + (ko));               \
        CP16((st) +            soff + 16, Agh + gAoff + (ko) + 8);           \
        CP16((st) + 1 * MATB + soff,      Agl + gAoff + (ko));               \
        CP16((st) + 1 * MATB + soff + 16, Agl + gAoff + (ko) + 8);           \
        CP16((st) + 2 * MATB + soff,      Bgh + gBoff + (ko));               \
        CP16((st) + 2 * MATB + soff + 16, Bgh + gBoff + (ko) + 8);           \
        CP16((st) + 3 * MATB + soff,      Bgl + gBoff + (ko));               \
        CP16((st) + 3 * MATB + soff + 16, Bgl + gBoff + (ko) + 8);           \
        CPCOMMIT();                                                          \
    } while (0)

    // prologue: stages 0..2
#pragma unroll
    for (int s = 0; s < STAGES - 1; s++) {
        LOAD_STAGE(sb0 + s * STAGEB, (size_t)s * 32);
    }

    for (int kc = 0; kc < NKC; kc++) {
        // wait for buffer kc (in-flight groups at top: min(3, NKC-kc))
        if (kc + 3 <= NKC)      CPWAIT(2);
        else if (kc + 2 == NKC) CPWAIT(1);
        else                    CPWAIT(0);
        __syncthreads();   // all warps done computing kc-1 -> safe to overwrite its buffer

        const int pre = kc + STAGES - 1;
        if (pre < NKC) LOAD_STAGE(sb0 + (pre & 3) * STAGEB, (size_t)pre * 32);

        const uint32_t st = sb0 + (kc & 3) * STAGEB;
        const uint32_t sAh = st, sAl = st + MATB, sBh = st + 2 * MATB, sBl = st + 3 * MATB;

#pragma unroll
        for (int ks = 0; ks < 2; ks++) {
            const uint32_t kso = (uint32_t)(ks * 16) * 2;

            // B fragments: 2 paired x4 loads cover 4 n-tiles (hi and lo)
            uint32_t bh4[2][4], bl4[2][4];
#pragma unroll
            for (int p = 0; p < 2; p++) {
                const uint32_t nb = (uint32_t)((wn * 32 + p * 16) * STR) * 2 + kso;
                LDSM4(bh4[p], sBh + nb + boff4);
                LDSM4(bl4[p], sBl + nb + boff4);
            }
#pragma unroll
            for (int mi = 0; mi < 4; mi++) {
                const uint32_t mb = (uint32_t)((wm * 64 + mi * 16) * STR) * 2 + kso;
                uint32_t ah[4], al[4];
                LDSM4(ah, sAh + mb + aoff);
                LDSM4(al, sAl + mb + aoff);
#pragma unroll
                for (int ni = 0; ni < 4; ni++) {
                    uint32_t* bh = &bh4[ni >> 1][(ni & 1) * 2];
                    uint32_t* bl = &bl4[ni >> 1][(ni & 1) * 2];
                    MMA16816(acc[mi][ni], ah, bh);
                    MMA16816(acc[mi][ni], ah, bl);
                    MMA16816(acc[mi][ni], al, bh);
                }
            }
        }
    }

    // ---- epilogue ----
    const int qrow = lane >> 2;
    const int qcol = lane & 3;
#pragma unroll
    for (int mi = 0; mi < 4; mi++) {
#pragma unroll
        for (int ni = 0; ni < 4; ni++) {
            const int c  = colBase + wn * 32 + ni * 8 + qcol * 2;
            const int m0 = rowBase + wm * 64 + mi * 16 + qrow;
            const int m1 = m0 + 8;
            float2 v0 = make_float2(acc[mi][ni][0], acc[mi][ni][1]);
            float2 v1 = make_float2(acc[mi][ni][2], acc[mi][ni][3]);
            const int b0 = m0 >> 11, n0 = m0 & 2047;
            const int b1 = m1 >> 11, n1 = m1 & 2047;
            if (MODE == 0) {
                // Q: scale by 1/8 (exact), split, [bh, n, e]
                const int h = c >> 6, e = c & 63;
                const size_t i0 = ((size_t)(b0 * HEADS + h) * N_SEQ + n0) * EDIM + e;
                const size_t i1 = ((size_t)(b1 * HEADS + h) * N_SEQ + n1) * EDIM + e;
                uint32_t h2, l2;
                split2(v0.x * 0.125f, v0.y * 0.125f, h2, l2);
                *(uint32_t*)&g_qh[i0] = h2; *(uint32_t*)&g_ql[i0] = l2;
                split2(v1.x * 0.125f, v1.y * 0.125f, h2, l2);
                *(uint32_t*)&g_qh[i1] = h2; *(uint32_t*)&g_ql[i1] = l2;
            } else if (MODE == 1) {
                if (c < HID) {
                    // K: split, [bh, n, e]
                    const int h = c >> 6, e = c & 63;
                    const size_t i0 = ((size_t)(b0 * HEADS + h) * N_SEQ + n0) * EDIM + e;
                    const size_t i1 = ((size_t)(b1 * HEADS + h) * N_SEQ + n1) * EDIM + e;
                    uint32_t h2, l2;
                    split2(v0.x, v0.y, h2, l2);
                    *(uint32_t*)&g_kh[i0] = h2; *(uint32_t*)&g_kl[i0] = l2;
                    split2(v1.x, v1.y, h2, l2);
                    *(uint32_t*)&g_kh[i1] = h2; *(uint32_t*)&g_kl[i1] = l2;
                } else {
                    // V: split, TRANSPOSED [bh, e, n]
                    const int c2 = c - HID;
                    const int h = c2 >> 6, e = c2 & 63;
                    const int bh0 = b0 * HEADS + h, bh1 = b1 * HEADS + h;
                    float vals[4] = {v0.x, v0.y, v1.x, v1.y};
                    int es[4] = {e, e + 1, e, e + 1};
                    int bhs[4] = {bh0, bh0, bh1, bh1};
                    int ns[4] = {n0, n0, n1, n1};
#pragma unroll
                    for (int q = 0; q < 4; q++) {
                        const size_t idx = ((size_t)bhs[q] * EDIM + es[q]) * N_SEQ + ns[q];
                        __nv_bfloat16 hv = __float2bfloat16(vals[q]);
                        g_vth[idx] = hv;
                        g_vtl[idx] = __float2bfloat16(vals[q] - __bfloat162float(hv));
                    }
                }
            } else {
                const float2 bb = *(const float2*)&bias[c];
                v0.x += bb.x; v0.y += bb.y;
                v1.x += bb.x; v1.y += bb.y;
                *(float2*)&out[(size_t)m0 * HID + c] = v0;
                *(float2*)&out[(size_t)m1 * HID + c] = v1;
            }
        }
    }
}

// ---------------------------------------------------------------------------
// Tensor-core flash attention (split-bf16, fp32 accum, online softmax).
// grid = (N_SEQ/128, BH), 256 threads (8 warps x 16 Q-rows).
// K/V tiles of 64 keys, double-buffered cp.async, ONE sync per tile,
// K/V fragments via paired ldmatrix.x4.
// S = Qh*Kh + Qh*Kl + Ql*Kh ; O += Ph*Vh + Ph*Vl + Pl*Vh.
// ---------------------------------------------------------------------------
#define ASTR  72                       // smem row stride in bf16 (144 B)
#define AMATB (64 * ASTR * 2)          // 9216 bytes per matrix
#define ASTGB (4 * AMATB)              // 36864 per stage
#define NT    (N_SEQ / 64)             // 32 key tiles

__global__ __launch_bounds__(256, 1) void attn_mma()
{
    extern __shared__ char dsm[];
    const uint32_t sb = smem_u32(dsm);

    const int tid  = threadIdx.x;
    const int wid  = tid >> 5;
    const int lane = tid & 31;
    const int qg   = lane >> 2;          // 0..7
    const int tig  = lane & 3;           // 0..3

    const int bh    = blockIdx.y;
    const int qbase = blockIdx.x * 128 + wid * 16;
    const size_t kvbase = (size_t)bh * N_SEQ * EDIM;   // same for K ([n,e]) and Vt ([e,n])

    // ---- Q fragments (A operand), resident in registers ----
    uint32_t qhf[4][4], qlf[4][4];
    {
        const size_t q0 = kvbase + (size_t)(qbase + qg) * EDIM;
        const size_t q8 = q0 + 8 * EDIM;
#pragma unroll
        for (int kc = 0; kc < 4; kc++) {
            const int col = kc * 16 + tig * 2;
            qhf[kc][0] = *(const uint32_t*)&g_qh[q0 + col];
            qhf[kc][1] = *(const uint32_t*)&g_qh[q8 + col];
            qhf[kc][2] = *(const uint32_t*)&g_qh[q0 + col + 8];
            qhf[kc][3] = *(const uint32_t*)&g_qh[q8 + col + 8];
            qlf[kc][0] = *(const uint32_t*)&g_ql[q0 + col];
            qlf[kc][1] = *(const uint32_t*)&g_ql[q8 + col];
            qlf[kc][2] = *(const uint32_t*)&g_ql[q0 + col + 8];
            qlf[kc][3] = *(const uint32_t*)&g_ql[q8 + col + 8];
        }
    }

    float oacc[8][4];
#pragma unroll
    for (int ne = 0; ne < 8; ne++)
#pragma unroll
        for (int q = 0; q < 4; q++) oacc[ne][q] = 0.f;
    float m0 = -1e30f, m1 = -1e30f, lp0 = 0.f, lp1 = 0.f;

    const uint32_t OKH = 0, OKL = AMATB, OVH = 2 * AMATB, OVL = 3 * AMATB;

#define AT_LOAD(stg, kt)                                                        \
    do {                                                                        \
        _Pragma("unroll")                                                       \
        for (int t = 0; t < 2; t++) {                                           \
            const int idx = tid + t * 256;                                      \
            const int r = idx >> 3, ch = idx & 7;                               \
            const uint32_t so = (stg) + (uint32_t)(r * 144 + ch * 16);          \
            const size_t kg = kvbase + (size_t)((kt) * 64 + r) * EDIM + ch * 8; \
            const size_t vg = kvbase + (size_t)r * N_SEQ + (kt) * 64 + ch * 8;  \
            CP16(so + OKH, g_kh  + kg);                                         \
            CP16(so + OKL, g_kl  + kg);                                         \
            CP16(so + OVH, g_vth + vg);                                         \
            CP16(so + OVL, g_vtl + vg);                                         \
        }                                                                       \
        CPCOMMIT();                                                             \
    } while (0)

    AT_LOAD(sb, 0);

    // paired x4 B-operand offset (16 n-rows x k-halves)
    const uint32_t lm4 = (uint32_t)(((lane & 7) + ((lane >> 4) << 3)) * ASTR
                                    + (((lane >> 3) & 1) << 3)) * 2;

    for (int kt = 0; kt < NT; kt++) {
        CPWAIT(0);         // buffer kt complete
        __syncthreads();   // all warps done with buffer (kt-1) -> safe to overwrite
        if (kt + 1 < NT) AT_LOAD(sb + ((kt + 1) & 1) * ASTGB, kt + 1);

        const uint32_t stg = sb + (kt & 1) * ASTGB;

        // ---- S = Q @ K^T ----
        float sacc[8][4];
#pragma unroll
        for (int nt = 0; nt < 8; nt++)
#pragma unroll
            for (int q = 0; q < 4; q++) sacc[nt][q] = 0.f;

#pragma unroll
        for (int kc = 0; kc < 4; kc++) {
            const uint32_t kso = (uint32_t)(kc * 16) * 2;
#pragma unroll
            for (int ntp = 0; ntp < 4; ntp++) {
                uint32_t kh4[4], kl4[4];
                const uint32_t off = (uint32_t)(ntp * 16 * ASTR) * 2 + kso + lm4;
                LDSM4(kh4, stg + OKH + off);
                LDSM4(kl4, stg + OKL + off);
                MMA16816(sacc[2 * ntp],     qhf[kc], kh4);
                MMA16816(sacc[2 * ntp],     qhf[kc], kl4);
                MMA16816(sacc[2 * ntp],     qlf[kc], kh4);
                MMA16816(sacc[2 * ntp + 1], qhf[kc], (kh4 + 2));
                MMA16816(sacc[2 * ntp + 1], qhf[kc], (kl4 + 2));
                MMA16816(sacc[2 * ntp + 1], qlf[kc], (kh4 + 2));
            }
        }

        // ---- online softmax ----
        float mx0 = -1e30f, mx1 = -1e30f;
#pragma unroll
        for (int nt = 0; nt < 8; nt++) {
            mx0 = fmaxf(mx0, fmaxf(sacc[nt][0], sacc[nt][1]));
            mx1 = fmaxf(mx1, fmaxf(sacc[nt][2], sacc[nt][3]));
        }
        mx0 = fmaxf(mx0, __shfl_xor_sync(0xffffffffu, mx0, 1));
        mx0 = fmaxf(mx0, __shfl_xor_sync(0xffffffffu, mx0, 2));
        mx1 = fmaxf(mx1, __shfl_xor_sync(0xffffffffu, mx1, 1));
        mx1 = fmaxf(mx1, __shfl_xor_sync(0xffffffffu, mx1, 2));

        const float mn0 = fmaxf(m0, mx0), mn1 = fmaxf(m1, mx1);
        const float corr0 = __expf(m0 - mn0), corr1 = __expf(m1 - mn1);
        m0 = mn0; m1 = mn1;

        float ls0 = 0.f, ls1 = 0.f;
#pragma unroll
        for (int nt = 0; nt < 8; nt++) {
            sacc[nt][0] = __expf(sacc[nt][0] - mn0);
            sacc[nt][1] = __expf(sacc[nt][1] - mn0);
            sacc[nt][2] = __expf(sacc[nt][2] - mn1);
            sacc[nt][3] = __expf(sacc[nt][3] - mn1);
            ls0 += sacc[nt][0] + sacc[nt][1];
            ls1 += sacc[nt][2] + sacc[nt][3];
        }
        lp0 = lp0 * corr0 + ls0;
        lp1 = lp1 * corr1 + ls1;

#pragma unroll
        for (int ne = 0; ne < 8; ne++) {
            oacc[ne][0] *= corr0; oacc[ne][1] *= corr0;
            oacc[ne][2] *= corr1; oacc[ne][3] *= corr1;
        }

        // ---- pack P (A-fragments for PV), split hi/lo ----
        uint32_t phf[4][4], plf[4][4];
#pragma unroll
        for (int kc = 0; kc < 4; kc++) {
            split2(sacc[2 * kc][0],     sacc[2 * kc][1],     phf[kc][0], plf[kc][0]);
            split2(sacc[2 * kc][2],     sacc[2 * kc][3],     phf[kc][1], plf[kc][1]);
            split2(sacc[2 * kc + 1][0], sacc[2 * kc + 1][1], phf[kc][2], plf[kc][2]);
            split2(sacc[2 * kc + 1][2], sacc[2 * kc + 1][3], phf[kc][3], plf[kc][3]);
        }

        // ---- O += P @ V ----
#pragma unroll
        for (int kc = 0; kc < 4; kc++) {
            const uint32_t kso = (uint32_t)(kc * 16) * 2;
#pragma unroll
            for (int nep = 0; nep < 4; nep++) {
                uint32_t vh4[4], vl4[4];
                const uint32_t off = (uint32_t)(nep * 16 * ASTR) * 2 + kso + lm4;
                LDSM4(vh4, stg + OVH + off);
                LDSM4(vl4, stg + OVL + off);
                MMA16816(oacc[2 * nep],     phf[kc], vh4);
                MMA16816(oacc[2 * nep],     phf[kc], vl4);
                MMA16816(oacc[2 * nep],     plf[kc], vh4);
                MMA16816(oacc[2 * nep + 1], phf[kc], (vh4 + 2));
                MMA16816(oacc[2 * nep + 1], phf[kc], (vl4 + 2));
                MMA16816(oacc[2 * nep + 1], plf[kc], (vh4 + 2));
            }
        }
    }

    // ---- finalize: O / l, split to bf16 hi/lo at [b, n, h*64 + e] ----
    lp0 += __shfl_xor_sync(0xffffffffu, lp0, 1);
    lp0 += __shfl_xor_sync(0xffffffffu, lp0, 2);
    lp1 += __shfl_xor_sync(0xffffffffu, lp1, 1);
    lp1 += __shfl_xor_sync(0xffffffffu, lp1, 2);
    const float inv0 = 1.f / lp0, inv1 = 1.f / lp1;

    const int b = bh >> 4, h = bh & 15;
    const int n0 = qbase + qg, n1 = n0 + 8;
    const size_t o0 = (size_t)(b * N_SEQ + n0) * HID + h * EDIM;
    const size_t o1 = (size_t)(b * N_SEQ + n1) * HID + h * EDIM;
#pragma unroll
    for (int ne = 0; ne < 8; ne++) {
        const int e = ne * 8 + tig * 2;
        uint32_t h2, l2;
        split2(oacc[ne][0] * inv0, oacc[ne][1] * inv0, h2, l2);
        *(uint32_t*)&g_atth[o0 + e] = h2; *(uint32_t*)&g_attl[o0 + e] = l2;
        split2(oacc[ne][2] * inv1, oacc[ne][3] * inv1, h2, l2);
        *(uint32_t*)&g_atth[o1 + e] = h2; *(uint32_t*)&g_attl[o1 + e] = l2;
    }
}

// ---------------------------------------------------------------------------
extern "C" void kernel_launch(void* const* d_in, const int* in_sizes, int n_in,
                              void* d_out, int out_size)
{
    (void)in_sizes; (void)n_in; (void)out_size;
    const float* x     = (const float*)d_in[0];
    const float* w_q   = (const float*)d_in[1];
    const float* w_kv  = (const float*)d_in[2];
    const float* w_out = (const float*)d_in[3];
    const float* b_out = (const float*)d_in[4];
    float* out = (float*)d_out;

    void *p_xh, *p_xl, *p_wqh, *p_wql, *p_wkvh, *p_wkvl, *p_woh, *p_wol, *p_ath, *p_atl;
    cudaGetSymbolAddress(&p_xh, g_xh);     cudaGetSymbolAddress(&p_xl, g_xl);
    cudaGetSymbolAddress(&p_wqh, g_wqh);   cudaGetSymbolAddress(&p_wql, g_wql);
    cudaGetSymbolAddress(&p_wkvh, g_wkvh); cudaGetSymbolAddress(&p_wkvl, g_wkvl);
    cudaGetSymbolAddress(&p_woh, g_woh);   cudaGetSymbolAddress(&p_wol, g_wol);
    cudaGetSymbolAddress(&p_ath, g_atth);  cudaGetSymbolAddress(&p_atl, g_attl);

    const int gemm_smem = STAGES * STAGEB;   // 163840
    cudaFuncSetAttribute(gemm_mma<0>, cudaFuncAttributeMaxDynamicSharedMemorySize, gemm_smem);
    cudaFuncSetAttribute(gemm_mma<1>, cudaFuncAttributeMaxDynamicSharedMemorySize, gemm_smem);
    cudaFuncSetAttribute(gemm_mma<2>, cudaFuncAttributeMaxDynamicSharedMemorySize, gemm_smem);
    const int attn_smem = 2 * ASTGB;         // 73728
    cudaFuncSetAttribute(attn_mma, cudaFuncAttributeMaxDynamicSharedMemorySize, attn_smem);

    // 1) Split fp32 inputs into bf16 hi/lo
    split_bf16_k<<<(M_TOT * KDIM / 4 + 255) / 256, 256>>>(x, (__nv_bfloat16*)p_xh, (__nv_bfloat16*)p_xl, M_TOT * KDIM / 4);
    split_bf16_k<<<(HID * KDIM / 4 + 255) / 256, 256>>>(w_q, (__nv_bfloat16*)p_wqh, (__nv_bfloat16*)p_wql, HID * KDIM / 4);
    split_bf16_k<<<(2 * HID * KDIM / 4 + 255) / 256, 256>>>(w_kv, (__nv_bfloat16*)p_wkvh, (__nv_bfloat16*)p_wkvl, 2 * HID * KDIM / 4);
    split_bf16_k<<<(HID * KDIM / 4 + 255) / 256, 256>>>(w_out, (__nv_bfloat16*)p_woh, (__nv_bfloat16*)p_wol, HID * KDIM / 4);

    // 2) Projections (mma.sync bf16-split) -> split-bf16 Q/K/V
    gemm_mma<0><<<dim3(HID / 128, M_TOT / 128), 256, gemm_smem>>>(
        (const __nv_bfloat16*)p_xh, (const __nv_bfloat16*)p_xl,
        (const __nv_bfloat16*)p_wqh, (const __nv_bfloat16*)p_wql, nullptr, nullptr);
    gemm_mma<1><<<dim3(2 * HID / 128, M_TOT / 128), 256, gemm_smem>>>(
        (const __nv_bfloat16*)p_xh, (const __nv_bfloat16*)p_xl,
        (const __nv_bfloat16*)p_wkvh, (const __nv_bfloat16*)p_wkvl, nullptr, nullptr);

    // 3) Attention (mma.sync bf16-split flash attention)
    attn_mma<<<dim3(N_SEQ / 128, BH), 256, attn_smem>>>();

    // 4) Output projection + bias (mma.sync bf16-split)
    gemm_mma<2><<<dim3(HID / 128, M_TOT / 128), 256, gemm_smem>>>(
        (const __nv_bfloat16*)p_ath, (const __nv_bfloat16*)p_atl,
        (const __nv_bfloat16*)p_woh, (const __nv_bfloat16*)p_wol, b_out, out);
}

// round 7
// speedup vs baseline: 3.4436x; 1.1868x over previous
#include <cuda_runtime.h>
#include <cuda_bf16.h>
#include <cuda_fp16.h>
#include <cstdint>

// Problem constants
#define B_SZ   4
#define N_SEQ  2048
#define HEADS  16
#define EDIM   64
#define KDIM   1024
#define M_TOT  (B_SZ * N_SEQ)          // 8192
#define HID    (HEADS * EDIM)          // 1024
#define BH     (B_SZ * HEADS)          // 64

// ---------------------------------------------------------------------------
// Scratch (device globals — no allocation allowed)
// ---------------------------------------------------------------------------
// fp16 2-split GEMM operands (A-side split, B-side hi-only)
__device__ __half g_xh[M_TOT * KDIM],  g_xl[M_TOT * KDIM];
__device__ __half g_wqh[HID * KDIM];
__device__ __half g_wkvh[2 * HID * KDIM];
__device__ __half g_woh[HID * KDIM];
__device__ __half g_atth[M_TOT * HID], g_attl[M_TOT * HID];

// bf16 3-split attention operands: Q/K ([bh, n, e]) and V transposed ([bh, e, n])
__device__ __nv_bfloat16 g_qh[BH * N_SEQ * EDIM], g_ql[BH * N_SEQ * EDIM];
__device__ __nv_bfloat16 g_kh[BH * N_SEQ * EDIM], g_kl[BH * N_SEQ * EDIM];
__device__ __nv_bfloat16 g_vth[BH * EDIM * N_SEQ], g_vtl[BH * EDIM * N_SEQ];

// ---------------------------------------------------------------------------
// Base-target-safe PTX helpers (sm_80+ features only)
// ---------------------------------------------------------------------------
__device__ __forceinline__ uint32_t smem_u32(const void* p) {
    uint32_t a;
    asm("{ .reg .u64 t; cvta.to.shared.u64 t, %1; cvt.u32.u64 %0, t; }" : "=r"(a) : "l"(p));
    return a;
}

#define CP16(s, g) \
    asm volatile("cp.async.cg.shared.global [%0], [%1], 16;" :: "r"(s), "l"(g) : "memory")
#define CPCOMMIT() asm volatile("cp.async.commit_group;" ::: "memory")
#define CPWAIT(n)  asm volatile("cp.async.wait_group %0;" :: "n"(n) : "memory")

#define LDSM4(R, addr)                                                            \
    asm volatile("ldmatrix.sync.aligned.m8n8.x4.shared.b16 {%0,%1,%2,%3}, [%4];"  \
        : "=r"((R)[0]), "=r"((R)[1]), "=r"((R)[2]), "=r"((R)[3]) : "r"(addr))

// bf16 mma (attention)
#define MMA16816(d, a, b)                                                         \
    asm volatile("mma.sync.aligned.m16n8k16.row.col.f32.bf16.bf16.f32 "           \
        "{%0,%1,%2,%3}, {%4,%5,%6,%7}, {%8,%9}, {%0,%1,%2,%3};"                   \
        : "+f"((d)[0]), "+f"((d)[1]), "+f"((d)[2]), "+f"((d)[3])                  \
        : "r"((a)[0]), "r"((a)[1]), "r"((a)[2]), "r"((a)[3]),                     \
          "r"((b)[0]), "r"((b)[1]))

// fp16 mma (projection GEMMs)
#define MMAH16816(d, a, b)                                                        \
    asm volatile("mma.sync.aligned.m16n8k16.row.col.f32.f16.f16.f32 "             \
        "{%0,%1,%2,%3}, {%4,%5,%6,%7}, {%8,%9}, {%0,%1,%2,%3};"                   \
        : "+f"((d)[0]), "+f"((d)[1]), "+f"((d)[2]), "+f"((d)[3])                  \
        : "r"((a)[0]), "r"((a)[1]), "r"((a)[2]), "r"((a)[3]),                     \
          "r"((b)[0]), "r"((b)[1]))

// split pair of fp32 into packed bf16 hi / lo words
__device__ __forceinline__ void split2(float a, float b, uint32_t& h2, uint32_t& l2) {
    __nv_bfloat162 hh = __floats2bfloat162_rn(a, b);
    float fa = __bfloat162float(hh.x), fb = __bfloat162float(hh.y);
    __nv_bfloat162 ll = __floats2bfloat162_rn(a - fa, b - fb);
    h2 = *(uint32_t*)&hh;
    l2 = *(uint32_t*)&ll;
}

// split pair of fp32 into packed fp16 hi / lo words
__device__ __forceinline__ void split2h(float a, float b, uint32_t& h2, uint32_t& l2) {
    __half2 hh = __floats2half2_rn(a, b);
    float fa = __low2float(hh), fb = __high2float(hh);
    __half2 ll = __floats2half2_rn(a - fa, b - fb);
    h2 = *(uint32_t*)&hh;
    l2 = *(uint32_t*)&ll;
}

// ---------------------------------------------------------------------------
// Split fp32 -> (hi, lo) fp16 pairs   /   fp32 -> fp16 (hi only)
// ---------------------------------------------------------------------------
__global__ __launch_bounds__(256) void split_f16_k(const float* __restrict__ s,
                                                   __half* __restrict__ hi,
                                                   __half* __restrict__ lo, int n4)
{
    int i = blockIdx.x * 256 + threadIdx.x;
    if (i >= n4) return;
    float4 v = ((const float4*)s)[i];
    uint32_t h0, l0, h1, l1;
    split2h(v.x, v.y, h0, l0);
    split2h(v.z, v.w, h1, l1);
    ((uint32_t*)hi)[i * 2 + 0] = h0;
    ((uint32_t*)hi)[i * 2 + 1] = h1;
    ((uint32_t*)lo)[i * 2 + 0] = l0;
    ((uint32_t*)lo)[i * 2 + 1] = l1;
}

__global__ __launch_bounds__(256) void tohalf_k(const float* __restrict__ s,
                                                __half* __restrict__ hi, int n4)
{
    int i = blockIdx.x * 256 + threadIdx.x;
    if (i >= n4) return;
    float4 v = ((const float4*)s)[i];
    ((__half2*)hi)[i * 2 + 0] = __floats2half2_rn(v.x, v.y);
    ((__half2*)hi)[i * 2 + 1] = __floats2half2_rn(v.z, v.w);
}

// ---------------------------------------------------------------------------
// mma.sync GEMM: C[m,c] = sum_k A[m,k]*B[c,k], fp16 2-term split
// (D = Ah*Bh + Al*Bh; B hi-only, err ~2^-12).
// 128x128 block tile, 8 warps (2x4), 64x32 warp tile, K-chunk 32, 4-stage
// cp.async pipeline, one __syncthreads per chunk, B via paired ldmatrix.x4.
// MODE 0: Q proj -> split-bf16 g_qh/g_ql (scaled by 0.125)
// MODE 1: KV proj -> split-bf16 g_kh/g_kl, g_vth/g_vtl (V transposed)
// MODE 2: out proj -> fp32 out + bias
// ---------------------------------------------------------------------------
#define STR     40
#define MATB    (128 * STR * 2)        // 10240 bytes per matrix per stage
#define STAGEB  (3 * MATB)             // 30720 (Ah, Al, Bh)
#define STAGES  4
#define NKC     (KDIM / 32)            // 32 k-chunks

template <int MODE>
__global__ __launch_bounds__(256, 1) void gemm_mma(
    const __half* __restrict__ Agh, const __half* __restrict__ Agl,
    const __half* __restrict__ Bgh,
    const float* __restrict__ bias, float* __restrict__ out)
{
    extern __shared__ char dsm[];
    const uint32_t sb0 = smem_u32(dsm);

    const int tid  = threadIdx.x;
    const int wid  = tid >> 5;
    const int lane = tid & 31;
    const int wm   = wid >> 2;          // 0..1
    const int wn   = wid & 3;           // 0..3
    const int rowBase = blockIdx.y * 128;
    const int colBase = blockIdx.x * 128;

    const int lr  = tid >> 1;
    const int lh  = tid & 1;
    const uint32_t soff = (uint32_t)(lr * STR + lh * 16) * 2;
    const size_t gAoff = (size_t)(rowBase + lr) * KDIM + lh * 16;
    const size_t gBoff = (size_t)(colBase + lr) * KDIM + lh * 16;

    const uint32_t aoff  = (uint32_t)((lane & 15) * STR + ((lane >> 4) << 3)) * 2;
    const uint32_t boff4 = (uint32_t)(((lane & 7) + ((lane >> 4) << 3)) * STR
                                      + (((lane >> 3) & 1) << 3)) * 2;

    float acc[4][4][4];
#pragma unroll
    for (int mi = 0; mi < 4; mi++)
#pragma unroll
        for (int ni = 0; ni < 4; ni++)
#pragma unroll
            for (int q = 0; q < 4; q++) acc[mi][ni][q] = 0.f;

#define LOAD_STAGE(st, ko)                                                   \
    do {                                                                     \
        CP16((st) +            soff,      Agh + gAoff + (ko));               \
        CP16((st) +            soff + 16, Agh + gAoff + (ko) + 8);           \
        CP16((st) + 1 * MATB + soff,      Agl + gAoff + (ko));               \
        CP16((st) + 1 * MATB + soff + 16, Agl + gAoff + (ko) + 8);           \
        CP16((st) + 2 * MATB + soff,      Bgh + gBoff + (ko));               \
        CP16((st) + 2 * MATB + soff + 16, Bgh + gBoff + (ko) + 8);           \
        CPCOMMIT();                                                          \
    } while (0)

    // prologue: stages 0..2
#pragma unroll
    for (int s = 0; s < STAGES - 1; s++) {
        LOAD_STAGE(sb0 + s * STAGEB, (size_t)s * 32);
    }

    for (int kc = 0; kc < NKC; kc++) {
        if (kc + 3 <= NKC)      CPWAIT(2);
        else if (kc + 2 == NKC) CPWAIT(1);
        else                    CPWAIT(0);
        __syncthreads();

        const int pre = kc + STAGES - 1;
        if (pre < NKC) LOAD_STAGE(sb0 + (pre & 3) * STAGEB, (size_t)pre * 32);

        const uint32_t st = sb0 + (kc & 3) * STAGEB;
        const uint32_t sAh = st, sAl = st + MATB, sBh = st + 2 * MATB;

#pragma unroll
        for (int ks = 0; ks < 2; ks++) {
            const uint32_t kso = (uint32_t)(ks * 16) * 2;

            uint32_t bh4[2][4];
#pragma unroll
            for (int p = 0; p < 2; p++) {
                const uint32_t nb = (uint32_t)((wn * 32 + p * 16) * STR) * 2 + kso;
                LDSM4(bh4[p], sBh + nb + boff4);
            }
#pragma unroll
            for (int mi = 0; mi < 4; mi++) {
                const uint32_t mb = (uint32_t)((wm * 64 + mi * 16) * STR) * 2 + kso;
                uint32_t ah[4], al[4];
                LDSM4(ah, sAh + mb + aoff);
                LDSM4(al, sAl + mb + aoff);
#pragma unroll
                for (int ni = 0; ni < 4; ni++) {
                    uint32_t* bh = &bh4[ni >> 1][(ni & 1) * 2];
                    MMAH16816(acc[mi][ni], ah, bh);
                    MMAH16816(acc[mi][ni], al, bh);
                }
            }
        }
    }

    // ---- epilogue ----
    const int qrow = lane >> 2;
    const int qcol = lane & 3;
#pragma unroll
    for (int mi = 0; mi < 4; mi++) {
#pragma unroll
        for (int ni = 0; ni < 4; ni++) {
            const int c  = colBase + wn * 32 + ni * 8 + qcol * 2;
            const int m0 = rowBase + wm * 64 + mi * 16 + qrow;
            const int m1 = m0 + 8;
            float2 v0 = make_float2(acc[mi][ni][0], acc[mi][ni][1]);
            float2 v1 = make_float2(acc[mi][ni][2], acc[mi][ni][3]);
            const int b0 = m0 >> 11, n0 = m0 & 2047;
            const int b1 = m1 >> 11, n1 = m1 & 2047;
            if (MODE == 0) {
                // Q: scale by 1/8 (exact), split to bf16, [bh, n, e]
                const int h = c >> 6, e = c & 63;
                const size_t i0 = ((size_t)(b0 * HEADS + h) * N_SEQ + n0) * EDIM + e;
                const size_t i1 = ((size_t)(b1 * HEADS + h) * N_SEQ + n1) * EDIM + e;
                uint32_t h2, l2;
                split2(v0.x * 0.125f, v0.y * 0.125f, h2, l2);
                *(uint32_t*)&g_qh[i0] = h2; *(uint32_t*)&g_ql[i0] = l2;
                split2(v1.x * 0.125f, v1.y * 0.125f, h2, l2);
                *(uint32_t*)&g_qh[i1] = h2; *(uint32_t*)&g_ql[i1] = l2;
            } else if (MODE == 1) {
                if (c < HID) {
                    // K: split to bf16, [bh, n, e]
                    const int h = c >> 6, e = c & 63;
                    const size_t i0 = ((size_t)(b0 * HEADS + h) * N_SEQ + n0) * EDIM + e;
                    const size_t i1 = ((size_t)(b1 * HEADS + h) * N_SEQ + n1) * EDIM + e;
                    uint32_t h2, l2;
                    split2(v0.x, v0.y, h2, l2);
                    *(uint32_t*)&g_kh[i0] = h2; *(uint32_t*)&g_kl[i0] = l2;
                    split2(v1.x, v1.y, h2, l2);
                    *(uint32_t*)&g_kh[i1] = h2; *(uint32_t*)&g_kl[i1] = l2;
                } else {
                    // V: split to bf16, TRANSPOSED [bh, e, n]
                    const int c2 = c - HID;
                    const int h = c2 >> 6, e = c2 & 63;
                    const int bh0 = b0 * HEADS + h, bh1 = b1 * HEADS + h;
                    float vals[4] = {v0.x, v0.y, v1.x, v1.y};
                    int es[4] = {e, e + 1, e, e + 1};
                    int bhs[4] = {bh0, bh0, bh1, bh1};
                    int ns[4] = {n0, n0, n1, n1};
#pragma unroll
                    for (int q = 0; q < 4; q++) {
                        const size_t idx = ((size_t)bhs[q] * EDIM + es[q]) * N_SEQ + ns[q];
                        __nv_bfloat16 hv = __float2bfloat16(vals[q]);
                        g_vth[idx] = hv;
                        g_vtl[idx] = __float2bfloat16(vals[q] - __bfloat162float(hv));
                    }
                }
            } else {
                const float2 bb = *(const float2*)&bias[c];
                v0.x += bb.x; v0.y += bb.y;
                v1.x += bb.x; v1.y += bb.y;
                *(float2*)&out[(size_t)m0 * HID + c] = v0;
                *(float2*)&out[(size_t)m1 * HID + c] = v1;
            }
        }
    }
}

// ---------------------------------------------------------------------------
// Tensor-core flash attention (split-bf16, fp32 accum, online softmax).
// grid = (N_SEQ/128, BH), 256 threads (8 warps x 16 Q-rows).
// K/V tiles of 64 keys, double-buffered cp.async, one sync per tile,
// K/V fragments via paired ldmatrix.x4.
// S = Qh*Kh + Qh*Kl + Ql*Kh ; O += Ph*Vh + Ph*Vl + Pl*Vh.
// Output staged as fp16 2-split for the out-projection.
// ---------------------------------------------------------------------------
#define ASTR  72                       // smem row stride in bf16 (144 B)
#define AMATB (64 * ASTR * 2)          // 9216 bytes per matrix
#define ASTGB (4 * AMATB)              // 36864 per stage
#define NT    (N_SEQ / 64)             // 32 key tiles

__global__ __launch_bounds__(256, 1) void attn_mma()
{
    extern __shared__ char dsm[];
    const uint32_t sb = smem_u32(dsm);

    const int tid  = threadIdx.x;
    const int wid  = tid >> 5;
    const int lane = tid & 31;
    const int qg   = lane >> 2;          // 0..7
    const int tig  = lane & 3;           // 0..3

    const int bh    = blockIdx.y;
    const int qbase = blockIdx.x * 128 + wid * 16;
    const size_t kvbase = (size_t)bh * N_SEQ * EDIM;

    // ---- Q fragments (A operand), resident in registers ----
    uint32_t qhf[4][4], qlf[4][4];
    {
        const size_t q0 = kvbase + (size_t)(qbase + qg) * EDIM;
        const size_t q8 = q0 + 8 * EDIM;
#pragma unroll
        for (int kc = 0; kc < 4; kc++) {
            const int col = kc * 16 + tig * 2;
            qhf[kc][0] = *(const uint32_t*)&g_qh[q0 + col];
            qhf[kc][1] = *(const uint32_t*)&g_qh[q8 + col];
            qhf[kc][2] = *(const uint32_t*)&g_qh[q0 + col + 8];
            qhf[kc][3] = *(const uint32_t*)&g_qh[q8 + col + 8];
            qlf[kc][0] = *(const uint32_t*)&g_ql[q0 + col];
            qlf[kc][1] = *(const uint32_t*)&g_ql[q8 + col];
            qlf[kc][2] = *(const uint32_t*)&g_ql[q0 + col + 8];
            qlf[kc][3] = *(const uint32_t*)&g_ql[q8 + col + 8];
        }
    }

    float oacc[8][4];
#pragma unroll
    for (int ne = 0; ne < 8; ne++)
#pragma unroll
        for (int q = 0; q < 4; q++) oacc[ne][q] = 0.f;
    float m0 = -1e30f, m1 = -1e30f, lp0 = 0.f, lp1 = 0.f;

    const uint32_t OKH = 0, OKL = AMATB, OVH = 2 * AMATB, OVL = 3 * AMATB;

#define AT_LOAD(stg, kt)                                                        \
    do {                                                                        \
        _Pragma("unroll")                                                       \
        for (int t = 0; t < 2; t++) {                                           \
            const int idx = tid + t * 256;                                      \
            const int r = idx >> 3, ch = idx & 7;                               \
            const uint32_t so = (stg) + (uint32_t)(r * 144 + ch * 16);          \
            const size_t kg = kvbase + (size_t)((kt) * 64 + r) * EDIM + ch * 8; \
            const size_t vg = kvbase + (size_t)r * N_SEQ + (kt) * 64 + ch * 8;  \
            CP16(so + OKH, g_kh  + kg);                                         \
            CP16(so + OKL, g_kl  + kg);                                         \
            CP16(so + OVH, g_vth + vg);                                         \
            CP16(so + OVL, g_vtl + vg);                                         \
        }                                                                       \
        CPCOMMIT();                                                             \
    } while (0)

    AT_LOAD(sb, 0);

    const uint32_t lm4 = (uint32_t)(((lane & 7) + ((lane >> 4) << 3)) * ASTR
                                    + (((lane >> 3) & 1) << 3)) * 2;

    for (int kt = 0; kt < NT; kt++) {
        CPWAIT(0);
        __syncthreads();
        if (kt + 1 < NT) AT_LOAD(sb + ((kt + 1) & 1) * ASTGB, kt + 1);

        const uint32_t stg = sb + (kt & 1) * ASTGB;

        // ---- S = Q @ K^T ----
        float sacc[8][4];
#pragma unroll
        for (int nt = 0; nt < 8; nt++)
#pragma unroll
            for (int q = 0; q < 4; q++) sacc[nt][q] = 0.f;

#pragma unroll
        for (int kc = 0; kc < 4; kc++) {
            const uint32_t kso = (uint32_t)(kc * 16) * 2;
#pragma unroll
            for (int ntp = 0; ntp < 4; ntp++) {
                uint32_t kh4[4], kl4[4];
                const uint32_t off = (uint32_t)(ntp * 16 * ASTR) * 2 + kso + lm4;
                LDSM4(kh4, stg + OKH + off);
                LDSM4(kl4, stg + OKL + off);
                MMA16816(sacc[2 * ntp],     qhf[kc], kh4);
                MMA16816(sacc[2 * ntp],     qhf[kc], kl4);
                MMA16816(sacc[2 * ntp],     qlf[kc], kh4);
                MMA16816(sacc[2 * ntp + 1], qhf[kc], (kh4 + 2));
                MMA16816(sacc[2 * ntp + 1], qhf[kc], (kl4 + 2));
                MMA16816(sacc[2 * ntp + 1], qlf[kc], (kh4 + 2));
            }
        }

        // ---- online softmax ----
        float mx0 = -1e30f, mx1 = -1e30f;
#pragma unroll
        for (int nt = 0; nt < 8; nt++) {
            mx0 = fmaxf(mx0, fmaxf(sacc[nt][0], sacc[nt][1]));
            mx1 = fmaxf(mx1, fmaxf(sacc[nt][2], sacc[nt][3]));
        }
        mx0 = fmaxf(mx0, __shfl_xor_sync(0xffffffffu, mx0, 1));
        mx0 = fmaxf(mx0, __shfl_xor_sync(0xffffffffu, mx0, 2));
        mx1 = fmaxf(mx1, __shfl_xor_sync(0xffffffffu, mx1, 1));
        mx1 = fmaxf(mx1, __shfl_xor_sync(0xffffffffu, mx1, 2));

        const float mn0 = fmaxf(m0, mx0), mn1 = fmaxf(m1, mx1);
        const float corr0 = __expf(m0 - mn0), corr1 = __expf(m1 - mn1);
        m0 = mn0; m1 = mn1;

        float ls0 = 0.f, ls1 = 0.f;
#pragma unroll
        for (int nt = 0; nt < 8; nt++) {
            sacc[nt][0] = __expf(sacc[nt][0] - mn0);
            sacc[nt][1] = __expf(sacc[nt][1] - mn0);
            sacc[nt][2] = __expf(sacc[nt][2] - mn1);
            sacc[nt][3] = __expf(sacc[nt][3] - mn1);
            ls0 += sacc[nt][0] + sacc[nt][1];
            ls1 += sacc[nt][2] + sacc[nt][3];
        }
        lp0 = lp0 * corr0 + ls0;
        lp1 = lp1 * corr1 + ls1;

#pragma unroll
        for (int ne = 0; ne < 8; ne++) {
            oacc[ne][0] *= corr0; oacc[ne][1] *= corr0;
            oacc[ne][2] *= corr1; oacc[ne][3] *= corr1;
        }

        // ---- pack P (A-fragments for PV), split hi/lo ----
        uint32_t phf[4][4], plf[4][4];
#pragma unroll
        for (int kc = 0; kc < 4; kc++) {
            split2(sacc[2 * kc][0],     sacc[2 * kc][1],     phf[kc][0], plf[kc][0]);
            split2(sacc[2 * kc][2],     sacc[2 * kc][3],     phf[kc][1], plf[kc][1]);
            split2(sacc[2 * kc + 1][0], sacc[2 * kc + 1][1], phf[kc][2], plf[kc][2]);
            split2(sacc[2 * kc + 1][2], sacc[2 * kc + 1][3], phf[kc][3], plf[kc][3]);
        }

        // ---- O += P @ V ----
#pragma unroll
        for (int kc = 0; kc < 4; kc++) {
            const uint32_t kso = (uint32_t)(kc * 16) * 2;
#pragma unroll
            for (int nep = 0; nep < 4; nep++) {
                uint32_t vh4[4], vl4[4];
                const uint32_t off = (uint32_t)(nep * 16 * ASTR) * 2 + kso + lm4;
                LDSM4(vh4, stg + OVH + off);
                LDSM4(vl4, stg + OVL + off);
                MMA16816(oacc[2 * nep],     phf[kc], vh4);
                MMA16816(oacc[2 * nep],     phf[kc], vl4);
                MMA16816(oacc[2 * nep],     plf[kc], vh4);
                MMA16816(oacc[2 * nep + 1], phf[kc], (vh4 + 2));
                MMA16816(oacc[2 * nep + 1], phf[kc], (vl4 + 2));
                MMA16816(oacc[2 * nep + 1], plf[kc], (vh4 + 2));
            }
        }
    }

    // ---- finalize: O / l, split to fp16 hi/lo at [b, n, h*64 + e] ----
    lp0 += __shfl_xor_sync(0xffffffffu, lp0, 1);
    lp0 += __shfl_xor_sync(0xffffffffu, lp0, 2);
    lp1 += __shfl_xor_sync(0xffffffffu, lp1, 1);
    lp1 += __shfl_xor_sync(0xffffffffu, lp1, 2);
    const float inv0 = 1.f / lp0, inv1 = 1.f / lp1;

    const int b = bh >> 4, h = bh & 15;
    const int n0 = qbase + qg, n1 = n0 + 8;
    const size_t o0 = (size_t)(b * N_SEQ + n0) * HID + h * EDIM;
    const size_t o1 = (size_t)(b * N_SEQ + n1) * HID + h * EDIM;
#pragma unroll
    for (int ne = 0; ne < 8; ne++) {
        const int e = ne * 8 + tig * 2;
        uint32_t h2, l2;
        split2h(oacc[ne][0] * inv0, oacc[ne][1] * inv0, h2, l2);
        *(uint32_t*)&g_atth[o0 + e] = h2; *(uint32_t*)&g_attl[o0 + e] = l2;
        split2h(oacc[ne][2] * inv1, oacc[ne][3] * inv1, h2, l2);
        *(uint32_t*)&g_atth[o1 + e] = h2; *(uint32_t*)&g_attl[o1 + e] = l2;
    }
}

// ---------------------------------------------------------------------------
extern "C" void kernel_launch(void* const* d_in, const int* in_sizes, int n_in,
                              void* d_out, int out_size)
{
    (void)in_sizes; (void)n_in; (void)out_size;
    const float* x     = (const float*)d_in[0];
    const float* w_q   = (const float*)d_in[1];
    const float* w_kv  = (const float*)d_in[2];
    const float* w_out = (const float*)d_in[3];
    const float* b_out = (const float*)d_in[4];
    float* out = (float*)d_out;

    void *p_xh, *p_xl, *p_wqh, *p_wkvh, *p_woh, *p_ath, *p_atl;
    cudaGetSymbolAddress(&p_xh, g_xh);     cudaGetSymbolAddress(&p_xl, g_xl);
    cudaGetSymbolAddress(&p_wqh, g_wqh);
    cudaGetSymbolAddress(&p_wkvh, g_wkvh);
    cudaGetSymbolAddress(&p_woh, g_woh);
    cudaGetSymbolAddress(&p_ath, g_atth);  cudaGetSymbolAddress(&p_atl, g_attl);

    const int gemm_smem = STAGES * STAGEB;   // 122880
    cudaFuncSetAttribute(gemm_mma<0>, cudaFuncAttributeMaxDynamicSharedMemorySize, gemm_smem);
    cudaFuncSetAttribute(gemm_mma<1>, cudaFuncAttributeMaxDynamicSharedMemorySize, gemm_smem);
    cudaFuncSetAttribute(gemm_mma<2>, cudaFuncAttributeMaxDynamicSharedMemorySize, gemm_smem);
    const int attn_smem = 2 * ASTGB;         // 73728
    cudaFuncSetAttribute(attn_mma, cudaFuncAttributeMaxDynamicSharedMemorySize, attn_smem);

    // 1) Split x into fp16 hi/lo; weights to fp16 hi only
    split_f16_k<<<(M_TOT * KDIM / 4 + 255) / 256, 256>>>(x, (__half*)p_xh, (__half*)p_xl, M_TOT * KDIM / 4);
    tohalf_k<<<(HID * KDIM / 4 + 255) / 256, 256>>>(w_q, (__half*)p_wqh, HID * KDIM / 4);
    tohalf_k<<<(2 * HID * KDIM / 4 + 255) / 256, 256>>>(w_kv, (__half*)p_wkvh, 2 * HID * KDIM / 4);
    tohalf_k<<<(HID * KDIM / 4 + 255) / 256, 256>>>(w_out, (__half*)p_woh, HID * KDIM / 4);

    // 2) Projections (fp16 2-term mma.sync) -> split-bf16 Q/K/V
    gemm_mma<0><<<dim3(HID / 128, M_TOT / 128), 256, gemm_smem>>>(
        (const __half*)p_xh, (const __half*)p_xl, (const __half*)p_wqh, nullptr, nullptr);
    gemm_mma<1><<<dim3(2 * HID / 128, M_TOT / 128), 256, gemm_smem>>>(
        (const __half*)p_xh, (const __half*)p_xl, (const __half*)p_wkvh, nullptr, nullptr);

    // 3) Attention (bf16 3-term mma.sync flash attention)
    attn_mma<<<dim3(N_SEQ / 128, BH), 256, attn_smem>>>();

    // 4) Output projection + bias (fp16 2-term mma.sync)
    gemm_mma<2><<<dim3(HID / 128, M_TOT / 128), 256, gemm_smem>>>(
        (const __half*)p_ath, (const __half*)p_atl, (const __half*)p_woh, b_out, out);
}

// round 8
// speedup vs baseline: 4.0478x; 1.1755x over previous
#include <cuda_runtime.h>
#include <cuda_bf16.h>
#include <cuda_fp16.h>
#include <cstdint>

// Problem constants
#define B_SZ   4
#define N_SEQ  2048
#define HEADS  16
#define EDIM   64
#define KDIM   1024
#define M_TOT  (B_SZ * N_SEQ)          // 8192
#define HID    (HEADS * EDIM)          // 1024
#define BH     (B_SZ * HEADS)          // 64

// ---------------------------------------------------------------------------
// Scratch (device globals — no allocation allowed)
// ---------------------------------------------------------------------------
// fp16 2-split GEMM operands (A-side split, B-side hi-only)
__device__ __half g_xh[M_TOT * KDIM],  g_xl[M_TOT * KDIM];
__device__ __half g_wqh[HID * KDIM];
__device__ __half g_wkvh[2 * HID * KDIM];
__device__ __half g_woh[HID * KDIM];
__device__ __half g_atth[M_TOT * HID], g_attl[M_TOT * HID];

// fp16 attention operands: Q hi/lo ([bh, n, e]); K hi ([bh, n, e]); V hi transposed ([bh, e, n])
__device__ __half g_qh[BH * N_SEQ * EDIM], g_ql[BH * N_SEQ * EDIM];
__device__ __half g_kh[BH * N_SEQ * EDIM];
__device__ __half g_vth[BH * EDIM * N_SEQ];

// ---------------------------------------------------------------------------
// Base-target-safe PTX helpers (sm_80+ features only)
// ---------------------------------------------------------------------------
__device__ __forceinline__ uint32_t smem_u32(const void* p) {
    uint32_t a;
    asm("{ .reg .u64 t; cvta.to.shared.u64 t, %1; cvt.u32.u64 %0, t; }" : "=r"(a) : "l"(p));
    return a;
}

#define CP16(s, g) \
    asm volatile("cp.async.cg.shared.global [%0], [%1], 16;" :: "r"(s), "l"(g) : "memory")
#define CPCOMMIT() asm volatile("cp.async.commit_group;" ::: "memory")
#define CPWAIT(n)  asm volatile("cp.async.wait_group %0;" :: "n"(n) : "memory")

#define LDSM4(R, addr)                                                            \
    asm volatile("ldmatrix.sync.aligned.m8n8.x4.shared.b16 {%0,%1,%2,%3}, [%4];"  \
        : "=r"((R)[0]), "=r"((R)[1]), "=r"((R)[2]), "=r"((R)[3]) : "r"(addr))

// fp16 mma
#define MMAH16816(d, a, b)                                                        \
    asm volatile("mma.sync.aligned.m16n8k16.row.col.f32.f16.f16.f32 "             \
        "{%0,%1,%2,%3}, {%4,%5,%6,%7}, {%8,%9}, {%0,%1,%2,%3};"                   \
        : "+f"((d)[0]), "+f"((d)[1]), "+f"((d)[2]), "+f"((d)[3])                  \
        : "r"((a)[0]), "r"((a)[1]), "r"((a)[2]), "r"((a)[3]),                     \
          "r"((b)[0]), "r"((b)[1]))

// split pair of fp32 into packed fp16 hi / lo words
__device__ __forceinline__ void split2h(float a, float b, uint32_t& h2, uint32_t& l2) {
    __half2 hh = __floats2half2_rn(a, b);
    float fa = __low2float(hh), fb = __high2float(hh);
    __half2 ll = __floats2half2_rn(a - fa, b - fb);
    h2 = *(uint32_t*)&hh;
    l2 = *(uint32_t*)&ll;
}

// ---------------------------------------------------------------------------
// Split fp32 -> (hi, lo) fp16 pairs   /   fp32 -> fp16 (hi only)
// ---------------------------------------------------------------------------
__global__ __launch_bounds__(256) void split_f16_k(const float* __restrict__ s,
                                                   __half* __restrict__ hi,
                                                   __half* __restrict__ lo, int n4)
{
    int i = blockIdx.x * 256 + threadIdx.x;
    if (i >= n4) return;
    float4 v = ((const float4*)s)[i];
    uint32_t h0, l0, h1, l1;
    split2h(v.x, v.y, h0, l0);
    split2h(v.z, v.w, h1, l1);
    ((uint32_t*)hi)[i * 2 + 0] = h0;
    ((uint32_t*)hi)[i * 2 + 1] = h1;
    ((uint32_t*)lo)[i * 2 + 0] = l0;
    ((uint32_t*)lo)[i * 2 + 1] = l1;
}

__global__ __launch_bounds__(256) void tohalf_k(const float* __restrict__ s,
                                                __half* __restrict__ hi, int n4)
{
    int i = blockIdx.x * 256 + threadIdx.x;
    if (i >= n4) return;
    float4 v = ((const float4*)s)[i];
    ((__half2*)hi)[i * 2 + 0] = __floats2half2_rn(v.x, v.y);
    ((__half2*)hi)[i * 2 + 1] = __floats2half2_rn(v.z, v.w);
}

// ---------------------------------------------------------------------------
// mma.sync GEMM: C[m,c] = sum_k A[m,k]*B[c,k], fp16 2-term split
// (D = Ah*Bh + Al*Bh; B hi-only).
// 128x128 block tile, 8 warps (2x4), 64x32 warp tile, K-chunk 32, 4-stage
// cp.async pipeline, one __syncthreads per chunk, B via paired ldmatrix.x4.
// MODE 0: Q proj -> fp16 hi/lo g_qh/g_ql (scaled by 0.125)
// MODE 1: KV proj -> fp16 g_kh (hi), g_vth (hi, V transposed)
// MODE 2: out proj -> fp32 out + bias
// ---------------------------------------------------------------------------
#define STR     40
#define MATB    (128 * STR * 2)        // 10240 bytes per matrix per stage
#define STAGEB  (3 * MATB)             // 30720 (Ah, Al, Bh)
#define STAGES  4
#define NKC     (KDIM / 32)            // 32 k-chunks

template <int MODE>
__global__ __launch_bounds__(256, 1) void gemm_mma(
    const __half* __restrict__ Agh, const __half* __restrict__ Agl,
    const __half* __restrict__ Bgh,
    const float* __restrict__ bias, float* __restrict__ out)
{
    extern __shared__ char dsm[];
    const uint32_t sb0 = smem_u32(dsm);

    const int tid  = threadIdx.x;
    const int wid  = tid >> 5;
    const int lane = tid & 31;
    const int wm   = wid >> 2;          // 0..1
    const int wn   = wid & 3;           // 0..3
    const int rowBase = blockIdx.y * 128;
    const int colBase = blockIdx.x * 128;

    const int lr  = tid >> 1;
    const int lh  = tid & 1;
    const uint32_t soff = (uint32_t)(lr * STR + lh * 16) * 2;
    const size_t gAoff = (size_t)(rowBase + lr) * KDIM + lh * 16;
    const size_t gBoff = (size_t)(colBase + lr) * KDIM + lh * 16;

    const uint32_t aoff  = (uint32_t)((lane & 15) * STR + ((lane >> 4) << 3)) * 2;
    const uint32_t boff4 = (uint32_t)(((lane & 7) + ((lane >> 4) << 3)) * STR
                                      + (((lane >> 3) & 1) << 3)) * 2;

    float acc[4][4][4];
#pragma unroll
    for (int mi = 0; mi < 4; mi++)
#pragma unroll
        for (int ni = 0; ni < 4; ni++)
#pragma unroll
            for (int q = 0; q < 4; q++) acc[mi][ni][q] = 0.f;

#define LOAD_STAGE(st, ko)                                                   \
    do {                                                                     \
        CP16((st) +            soff,      Agh + gAoff + (ko));               \
        CP16((st) +            soff + 16, Agh + gAoff + (ko) + 8);           \
        CP16((st) + 1 * MATB + soff,      Agl + gAoff + (ko));               \
        CP16((st) + 1 * MATB + soff + 16, Agl + gAoff + (ko) + 8);           \
        CP16((st) + 2 * MATB + soff,      Bgh + gBoff + (ko));               \
        CP16((st) + 2 * MATB + soff + 16, Bgh + gBoff + (ko) + 8);           \
        CPCOMMIT();                                                          \
    } while (0)

#pragma unroll
    for (int s = 0; s < STAGES - 1; s++) {
        LOAD_STAGE(sb0 + s * STAGEB, (size_t)s * 32);
    }

    for (int kc = 0; kc < NKC; kc++) {
        if (kc + 3 <= NKC)      CPWAIT(2);
        else if (kc + 2 == NKC) CPWAIT(1);
        else                    CPWAIT(0);
        __syncthreads();

        const int pre = kc + STAGES - 1;
        if (pre < NKC) LOAD_STAGE(sb0 + (pre & 3) * STAGEB, (size_t)pre * 32);

        const uint32_t st = sb0 + (kc & 3) * STAGEB;
        const uint32_t sAh = st, sAl = st + MATB, sBh = st + 2 * MATB;

#pragma unroll
        for (int ks = 0; ks < 2; ks++) {
            const uint32_t kso = (uint32_t)(ks * 16) * 2;

            uint32_t bh4[2][4];
#pragma unroll
            for (int p = 0; p < 2; p++) {
                const uint32_t nb = (uint32_t)((wn * 32 + p * 16) * STR) * 2 + kso;
                LDSM4(bh4[p], sBh + nb + boff4);
            }
#pragma unroll
            for (int mi = 0; mi < 4; mi++) {
                const uint32_t mb = (uint32_t)((wm * 64 + mi * 16) * STR) * 2 + kso;
                uint32_t ah[4], al[4];
                LDSM4(ah, sAh + mb + aoff);
                LDSM4(al, sAl + mb + aoff);
#pragma unroll
                for (int ni = 0; ni < 4; ni++) {
                    uint32_t* bh = &bh4[ni >> 1][(ni & 1) * 2];
                    MMAH16816(acc[mi][ni], ah, bh);
                    MMAH16816(acc[mi][ni], al, bh);
                }
            }
        }
    }

    // ---- epilogue ----
    const int qrow = lane >> 2;
    const int qcol = lane & 3;
#pragma unroll
    for (int mi = 0; mi < 4; mi++) {
#pragma unroll
        for (int ni = 0; ni < 4; ni++) {
            const int c  = colBase + wn * 32 + ni * 8 + qcol * 2;
            const int m0 = rowBase + wm * 64 + mi * 16 + qrow;
            const int m1 = m0 + 8;
            float2 v0 = make_float2(acc[mi][ni][0], acc[mi][ni][1]);
            float2 v1 = make_float2(acc[mi][ni][2], acc[mi][ni][3]);
            const int b0 = m0 >> 11, n0 = m0 & 2047;
            const int b1 = m1 >> 11, n1 = m1 & 2047;
            if (MODE == 0) {
                // Q: scale by 1/8 (exact), fp16 split, [bh, n, e]
                const int h = c >> 6, e = c & 63;
                const size_t i0 = ((size_t)(b0 * HEADS + h) * N_SEQ + n0) * EDIM + e;
                const size_t i1 = ((size_t)(b1 * HEADS + h) * N_SEQ + n1) * EDIM + e;
                uint32_t h2, l2;
                split2h(v0.x * 0.125f, v0.y * 0.125f, h2, l2);
                *(uint32_t*)&g_qh[i0] = h2; *(uint32_t*)&g_ql[i0] = l2;
                split2h(v1.x * 0.125f, v1.y * 0.125f, h2, l2);
                *(uint32_t*)&g_qh[i1] = h2; *(uint32_t*)&g_ql[i1] = l2;
            } else if (MODE == 1) {
                if (c < HID) {
                    // K: fp16 hi only, [bh, n, e]
                    const int h = c >> 6, e = c & 63;
                    const size_t i0 = ((size_t)(b0 * HEADS + h) * N_SEQ + n0) * EDIM + e;
                    const size_t i1 = ((size_t)(b1 * HEADS + h) * N_SEQ + n1) * EDIM + e;
                    *(__half2*)&g_kh[i0] = __floats2half2_rn(v0.x, v0.y);
                    *(__half2*)&g_kh[i1] = __floats2half2_rn(v1.x, v1.y);
                } else {
                    // V: fp16 hi only, TRANSPOSED [bh, e, n]
                    const int c2 = c - HID;
                    const int h = c2 >> 6, e = c2 & 63;
                    const int bh0 = b0 * HEADS + h, bh1 = b1 * HEADS + h;
                    g_vth[((size_t)bh0 * EDIM + e)     * N_SEQ + n0] = __float2half(v0.x);
                    g_vth[((size_t)bh0 * EDIM + e + 1) * N_SEQ + n0] = __float2half(v0.y);
                    g_vth[((size_t)bh1 * EDIM + e)     * N_SEQ + n1] = __float2half(v1.x);
                    g_vth[((size_t)bh1 * EDIM + e + 1) * N_SEQ + n1] = __float2half(v1.y);
                }
            } else {
                const float2 bb = *(const float2*)&bias[c];
                v0.x += bb.x; v0.y += bb.y;
                v1.x += bb.x; v1.y += bb.y;
                *(float2*)&out[(size_t)m0 * HID + c] = v0;
                *(float2*)&out[(size_t)m1 * HID + c] = v1;
            }
        }
    }
}

// ---------------------------------------------------------------------------
// Tensor-core flash attention (fp16 2-term, fp32 accum, online softmax).
// grid = (N_SEQ/128, BH), 256 threads (8 warps x 16 Q-rows).
// K/V tiles of 64 keys (hi-only), 3-stage cp.async, one sync per tile.
// S = Qh*Kh + Ql*Kh ; O += Ph*Vh + Pl*Vh.
// Output staged as fp16 2-split for the out-projection.
// ---------------------------------------------------------------------------
#define ASTR   72                      // smem row stride in fp16 (144 B)
#define AMATB  (64 * ASTR * 2)         // 9216 bytes per matrix
#define ASTGB  (2 * AMATB)             // 18432 per stage (Kh, Vh)
#define ASTAGES 3
#define NT     (N_SEQ / 64)            // 32 key tiles

__global__ __launch_bounds__(256, 1) void attn_mma()
{
    extern __shared__ char dsm[];
    const uint32_t sb = smem_u32(dsm);

    const int tid  = threadIdx.x;
    const int wid  = tid >> 5;
    const int lane = tid & 31;
    const int qg   = lane >> 2;          // 0..7
    const int tig  = lane & 3;           // 0..3

    const int bh    = blockIdx.y;
    const int qbase = blockIdx.x * 128 + wid * 16;
    const size_t kvbase = (size_t)bh * N_SEQ * EDIM;

    // ---- Q fragments (A operand), resident in registers ----
    uint32_t qhf[4][4], qlf[4][4];
    {
        const size_t q0 = kvbase + (size_t)(qbase + qg) * EDIM;
        const size_t q8 = q0 + 8 * EDIM;
#pragma unroll
        for (int kc = 0; kc < 4; kc++) {
            const int col = kc * 16 + tig * 2;
            qhf[kc][0] = *(const uint32_t*)&g_qh[q0 + col];
            qhf[kc][1] = *(const uint32_t*)&g_qh[q8 + col];
            qhf[kc][2] = *(const uint32_t*)&g_qh[q0 + col + 8];
            qhf[kc][3] = *(const uint32_t*)&g_qh[q8 + col + 8];
            qlf[kc][0] = *(const uint32_t*)&g_ql[q0 + col];
            qlf[kc][1] = *(const uint32_t*)&g_ql[q8 + col];
            qlf[kc][2] = *(const uint32_t*)&g_ql[q0 + col + 8];
            qlf[kc][3] = *(const uint32_t*)&g_ql[q8 + col + 8];
        }
    }

    float oacc[8][4];
#pragma unroll
    for (int ne = 0; ne < 8; ne++)
#pragma unroll
        for (int q = 0; q < 4; q++) oacc[ne][q] = 0.f;
    float m0 = -1e30f, m1 = -1e30f, lp0 = 0.f, lp1 = 0.f;

    const uint32_t OKH = 0, OVH = AMATB;

#define AT_LOAD(stg, kt)                                                        \
    do {                                                                        \
        _Pragma("unroll")                                                       \
        for (int t = 0; t < 2; t++) {                                           \
            const int idx = tid + t * 256;                                      \
            const int r = idx >> 3, ch = idx & 7;                               \
            const uint32_t so = (stg) + (uint32_t)(r * 144 + ch * 16);          \
            const size_t kg = kvbase + (size_t)((kt) * 64 + r) * EDIM + ch * 8; \
            const size_t vg = kvbase + (size_t)r * N_SEQ + (kt) * 64 + ch * 8;  \
            CP16(so + OKH, g_kh  + kg);                                         \
            CP16(so + OVH, g_vth + vg);                                         \
        }                                                                       \
        CPCOMMIT();                                                             \
    } while (0)

    AT_LOAD(sb, 0);
    AT_LOAD(sb + ASTGB, 1);

    const uint32_t lm4 = (uint32_t)(((lane & 7) + ((lane >> 4) << 3)) * ASTR
                                    + (((lane >> 3) & 1) << 3)) * 2;

    for (int kt = 0; kt < NT; kt++) {
        if (kt + 1 < NT) CPWAIT(1); else CPWAIT(0);
        __syncthreads();   // all warps done with buffer (kt-1) -> reusable
        if (kt + 2 < NT) AT_LOAD(sb + ((kt + 2) % ASTAGES) * ASTGB, kt + 2);

        const uint32_t stg = sb + (kt % ASTAGES) * ASTGB;

        // ---- S = Q @ K^T ----
        float sacc[8][4];
#pragma unroll
        for (int nt = 0; nt < 8; nt++)
#pragma unroll
            for (int q = 0; q < 4; q++) sacc[nt][q] = 0.f;

#pragma unroll
        for (int kc = 0; kc < 4; kc++) {
            const uint32_t kso = (uint32_t)(kc * 16) * 2;
#pragma unroll
            for (int ntp = 0; ntp < 4; ntp++) {
                uint32_t kh4[4];
                const uint32_t off = (uint32_t)(ntp * 16 * ASTR) * 2 + kso + lm4;
                LDSM4(kh4, stg + OKH + off);
                MMAH16816(sacc[2 * ntp],     qhf[kc], kh4);
                MMAH16816(sacc[2 * ntp],     qlf[kc], kh4);
                MMAH16816(sacc[2 * ntp + 1], qhf[kc], (kh4 + 2));
                MMAH16816(sacc[2 * ntp + 1], qlf[kc], (kh4 + 2));
            }
        }

        // ---- online softmax ----
        float mx0 = -1e30f, mx1 = -1e30f;
#pragma unroll
        for (int nt = 0; nt < 8; nt++) {
            mx0 = fmaxf(mx0, fmaxf(sacc[nt][0], sacc[nt][1]));
            mx1 = fmaxf(mx1, fmaxf(sacc[nt][2], sacc[nt][3]));
        }
        mx0 = fmaxf(mx0, __shfl_xor_sync(0xffffffffu, mx0, 1));
        mx0 = fmaxf(mx0, __shfl_xor_sync(0xffffffffu, mx0, 2));
        mx1 = fmaxf(mx1, __shfl_xor_sync(0xffffffffu, mx1, 1));
        mx1 = fmaxf(mx1, __shfl_xor_sync(0xffffffffu, mx1, 2));

        const float mn0 = fmaxf(m0, mx0), mn1 = fmaxf(m1, mx1);
        const float corr0 = __expf(m0 - mn0), corr1 = __expf(m1 - mn1);
        m0 = mn0; m1 = mn1;

        float ls0 = 0.f, ls1 = 0.f;
#pragma unroll
        for (int nt = 0; nt < 8; nt++) {
            sacc[nt][0] = __expf(sacc[nt][0] - mn0);
            sacc[nt][1] = __expf(sacc[nt][1] - mn0);
            sacc[nt][2] = __expf(sacc[nt][2] - mn1);
            sacc[nt][3] = __expf(sacc[nt][3] - mn1);
            ls0 += sacc[nt][0] + sacc[nt][1];
            ls1 += sacc[nt][2] + sacc[nt][3];
        }
        lp0 = lp0 * corr0 + ls0;
        lp1 = lp1 * corr1 + ls1;

#pragma unroll
        for (int ne = 0; ne < 8; ne++) {
            oacc[ne][0] *= corr0; oacc[ne][1] *= corr0;
            oacc[ne][2] *= corr1; oacc[ne][3] *= corr1;
        }

        // ---- pack P (A-fragments for PV), fp16 split hi/lo ----
        uint32_t phf[4][4], plf[4][4];
#pragma unroll
        for (int kc = 0; kc < 4; kc++) {
            split2h(sacc[2 * kc][0],     sacc[2 * kc][1],     phf[kc][0], plf[kc][0]);
            split2h(sacc[2 * kc][2],     sacc[2 * kc][3],     phf[kc][1], plf[kc][1]);
            split2h(sacc[2 * kc + 1][0], sacc[2 * kc + 1][1], phf[kc][2], plf[kc][2]);
            split2h(sacc[2 * kc + 1][2], sacc[2 * kc + 1][3], phf[kc][3], plf[kc][3]);
        }

        // ---- O += P @ V ----
#pragma unroll
        for (int kc = 0; kc < 4; kc++) {
            const uint32_t kso = (uint32_t)(kc * 16) * 2;
#pragma unroll
            for (int nep = 0; nep < 4; nep++) {
                uint32_t vh4[4];
                const uint32_t off = (uint32_t)(nep * 16 * ASTR) * 2 + kso + lm4;
                LDSM4(vh4, stg + OVH + off);
                MMAH16816(oacc[2 * nep],     phf[kc], vh4);
                MMAH16816(oacc[2 * nep],     plf[kc], vh4);
                MMAH16816(oacc[2 * nep + 1], phf[kc], (vh4 + 2));
                MMAH16816(oacc[2 * nep + 1], plf[kc], (vh4 + 2));
            }
        }
    }

    // ---- finalize: O / l, fp16 split hi/lo at [b, n, h*64 + e] ----
    lp0 += __shfl_xor_sync(0xffffffffu, lp0, 1);
    lp0 += __shfl_xor_sync(0xffffffffu, lp0, 2);
    lp1 += __shfl_xor_sync(0xffffffffu, lp1, 1);
    lp1 += __shfl_xor_sync(0xffffffffu, lp1, 2);
    const float inv0 = 1.f / lp0, inv1 = 1.f / lp1;

    const int b = bh >> 4, h = bh & 15;
    const int n0 = qbase + qg, n1 = n0 + 8;
    const size_t o0 = (size_t)(b * N_SEQ + n0) * HID + h * EDIM;
    const size_t o1 = (size_t)(b * N_SEQ + n1) * HID + h * EDIM;
#pragma unroll
    for (int ne = 0; ne < 8; ne++) {
        const int e = ne * 8 + tig * 2;
        uint32_t h2, l2;
        split2h(oacc[ne][0] * inv0, oacc[ne][1] * inv0, h2, l2);
        *(uint32_t*)&g_atth[o0 + e] = h2; *(uint32_t*)&g_attl[o0 + e] = l2;
        split2h(oacc[ne][2] * inv1, oacc[ne][3] * inv1, h2, l2);
        *(uint32_t*)&g_atth[o1 + e] = h2; *(uint32_t*)&g_attl[o1 + e] = l2;
    }
}

// ---------------------------------------------------------------------------
extern "C" void kernel_launch(void* const* d_in, const int* in_sizes, int n_in,
                              void* d_out, int out_size)
{
    (void)in_sizes; (void)n_in; (void)out_size;
    const float* x     = (const float*)d_in[0];
    const float* w_q   = (const float*)d_in[1];
    const float* w_kv  = (const float*)d_in[2];
    const float* w_out = (const float*)d_in[3];
    const float* b_out = (const float*)d_in[4];
    float* out = (float*)d_out;

    void *p_xh, *p_xl, *p_wqh, *p_wkvh, *p_woh, *p_ath, *p_atl;
    cudaGetSymbolAddress(&p_xh, g_xh);     cudaGetSymbolAddress(&p_xl, g_xl);
    cudaGetSymbolAddress(&p_wqh, g_wqh);
    cudaGetSymbolAddress(&p_wkvh, g_wkvh);
    cudaGetSymbolAddress(&p_woh, g_woh);
    cudaGetSymbolAddress(&p_ath, g_atth);  cudaGetSymbolAddress(&p_atl, g_attl);

    const int gemm_smem = STAGES * STAGEB;   // 122880
    cudaFuncSetAttribute(gemm_mma<0>, cudaFuncAttributeMaxDynamicSharedMemorySize, gemm_smem);
    cudaFuncSetAttribute(gemm_mma<1>, cudaFuncAttributeMaxDynamicSharedMemorySize, gemm_smem);
    cudaFuncSetAttribute(gemm_mma<2>, cudaFuncAttributeMaxDynamicSharedMemorySize, gemm_smem);
    const int attn_smem = ASTAGES * ASTGB;   // 55296
    cudaFuncSetAttribute(attn_mma, cudaFuncAttributeMaxDynamicSharedMemorySize, attn_smem);

    // 1) Split x into fp16 hi/lo; weights to fp16 hi only
    split_f16_k<<<(M_TOT * KDIM / 4 + 255) / 256, 256>>>(x, (__half*)p_xh, (__half*)p_xl, M_TOT * KDIM / 4);
    tohalf_k<<<(HID * KDIM / 4 + 255) / 256, 256>>>(w_q, (__half*)p_wqh, HID * KDIM / 4);
    tohalf_k<<<(2 * HID * KDIM / 4 + 255) / 256, 256>>>(w_kv, (__half*)p_wkvh, 2 * HID * KDIM / 4);
    tohalf_k<<<(HID * KDIM / 4 + 255) / 256, 256>>>(w_out, (__half*)p_woh, HID * KDIM / 4);

    // 2) Projections (fp16 2-term mma.sync) -> fp16 Q hi/lo, K/V hi
    gemm_mma<0><<<dim3(HID / 128, M_TOT / 128), 256, gemm_smem>>>(
        (const __half*)p_xh, (const __half*)p_xl, (const __half*)p_wqh, nullptr, nullptr);
    gemm_mma<1><<<dim3(2 * HID / 128, M_TOT / 128), 256, gemm_smem>>>(
        (const __half*)p_xh, (const __half*)p_xl, (const __half*)p_wkvh, nullptr, nullptr);

    // 3) Attention (fp16 2-term mma.sync flash attention)
    attn_mma<<<dim3(N_SEQ / 128, BH), 256, attn_smem>>>();

    // 4) Output projection + bias (fp16 2-term mma.sync)
    gemm_mma<2><<<dim3(HID / 128, M_TOT / 128), 256, gemm_smem>>>(
        (const __half*)p_ath, (const __half*)p_atl, (const __half*)p_woh, b_out, out);
}

// round 9
// speedup vs baseline: 4.4617x; 1.1023x over previous
#include <cuda_runtime.h>
#include <cuda_bf16.h>
#include <cuda_fp16.h>
#include <cstdint>

// Problem constants
#define B_SZ   4
#define N_SEQ  2048
#define HEADS  16
#define EDIM   64
#define KDIM   1024
#define M_TOT  (B_SZ * N_SEQ)          // 8192
#define HID    (HEADS * EDIM)          // 1024
#define BH     (B_SZ * HEADS)          // 64

// ---------------------------------------------------------------------------
// Scratch (device globals — no allocation allowed)
// ---------------------------------------------------------------------------
__device__ __half g_xh[M_TOT * KDIM],  g_xl[M_TOT * KDIM];
__device__ __half g_wall[3 * HID * KDIM];          // [w_q ; w_kv] fused, fp16 hi
__device__ __half g_woh[HID * KDIM];
__device__ __half g_atth[M_TOT * HID], g_attl[M_TOT * HID];

// fp16 attention operands: Q hi/lo ([bh, n, e]); K hi ([bh, n, e]); V hi transposed ([bh, e, n])
__device__ __half g_qh[BH * N_SEQ * EDIM], g_ql[BH * N_SEQ * EDIM];
__device__ __half g_kh[BH * N_SEQ * EDIM];
__device__ __half g_vth[BH * EDIM * N_SEQ];

// ---------------------------------------------------------------------------
// Base-target-safe PTX helpers (sm_80+ features only)
// ---------------------------------------------------------------------------
__device__ __forceinline__ uint32_t smem_u32(const void* p) {
    uint32_t a;
    asm("{ .reg .u64 t; cvta.to.shared.u64 t, %1; cvt.u32.u64 %0, t; }" : "=r"(a) : "l"(p));
    return a;
}

#define CP16(s, g) \
    asm volatile("cp.async.cg.shared.global [%0], [%1], 16;" :: "r"(s), "l"(g) : "memory")
#define CPCOMMIT() asm volatile("cp.async.commit_group;" ::: "memory")
#define CPWAIT(n)  asm volatile("cp.async.wait_group %0;" :: "n"(n) : "memory")

#define LDSM4(R, addr)                                                            \
    asm volatile("ldmatrix.sync.aligned.m8n8.x4.shared.b16 {%0,%1,%2,%3}, [%4];"  \
        : "=r"((R)[0]), "=r"((R)[1]), "=r"((R)[2]), "=r"((R)[3]) : "r"(addr))

#define MMAH16816(d, a, b)                                                        \
    asm volatile("mma.sync.aligned.m16n8k16.row.col.f32.f16.f16.f32 "             \
        "{%0,%1,%2,%3}, {%4,%5,%6,%7}, {%8,%9}, {%0,%1,%2,%3};"                   \
        : "+f"((d)[0]), "+f"((d)[1]), "+f"((d)[2]), "+f"((d)[3])                  \
        : "r"((a)[0]), "r"((a)[1]), "r"((a)[2]), "r"((a)[3]),                     \
          "r"((b)[0]), "r"((b)[1]))

// split pair of fp32 into packed fp16 hi / lo words
__device__ __forceinline__ void split2h(float a, float b, uint32_t& h2, uint32_t& l2) {
    __half2 hh = __floats2half2_rn(a, b);
    float fa = __low2float(hh), fb = __high2float(hh);
    __half2 ll = __floats2half2_rn(a - fa, b - fb);
    h2 = *(uint32_t*)&hh;
    l2 = *(uint32_t*)&ll;
}

// ---------------------------------------------------------------------------
// Split fp32 -> (hi, lo) fp16 pairs   /   fp32 -> fp16 (hi only)
// ---------------------------------------------------------------------------
__global__ __launch_bounds__(256) void split_f16_k(const float* __restrict__ s,
                                                   __half* __restrict__ hi,
                                                   __half* __restrict__ lo, int n4)
{
    int i = blockIdx.x * 256 + threadIdx.x;
    if (i >= n4) return;
    float4 v = ((const float4*)s)[i];
    uint32_t h0, l0, h1, l1;
    split2h(v.x, v.y, h0, l0);
    split2h(v.z, v.w, h1, l1);
    ((uint32_t*)hi)[i * 2 + 0] = h0;
    ((uint32_t*)hi)[i * 2 + 1] = h1;
    ((uint32_t*)lo)[i * 2 + 0] = l0;
    ((uint32_t*)lo)[i * 2 + 1] = l1;
}

__global__ __launch_bounds__(256) void tohalf_k(const float* __restrict__ s,
                                                __half* __restrict__ hi, int n4)
{
    int i = blockIdx.x * 256 + threadIdx.x;
    if (i >= n4) return;
    float4 v = ((const float4*)s)[i];
    ((__half2*)hi)[i * 2 + 0] = __floats2half2_rn(v.x, v.y);
    ((__half2*)hi)[i * 2 + 1] = __floats2half2_rn(v.z, v.w);
}

// ---------------------------------------------------------------------------
// mma.sync GEMM: C[m,c] = sum_k A[m,k]*B[c,k], fp16 2-term split
// (D = Ah*Bh + Al*Bh; B hi-only).
// 128x128 block tile, 8 warps (2x4), 64x32 warp tile, K-chunk 32, 3-stage
// cp.async pipeline, 2 CTAs/SM, one __syncthreads per chunk.
// MODE 0: fused QKV proj; c<HID -> Q (x0.125, fp16 split), <2*HID -> K hi,
//         else V hi transposed.
// MODE 1: out proj -> fp32 out + bias
// ---------------------------------------------------------------------------
#define STR     40
#define MATB    (128 * STR * 2)        // 10240 bytes per matrix per stage
#define STAGEB  (3 * MATB)             // 30720 (Ah, Al, Bh)
#define STAGES  3
#define NKC     (KDIM / 32)            // 32 k-chunks

template <int MODE>
__global__ __launch_bounds__(256, 2) void gemm_mma(
    const __half* __restrict__ Agh, const __half* __restrict__ Agl,
    const __half* __restrict__ Bgh,
    const float* __restrict__ bias, float* __restrict__ out)
{
    extern __shared__ char dsm[];
    const uint32_t sb0 = smem_u32(dsm);

    const int tid  = threadIdx.x;
    const int wid  = tid >> 5;
    const int lane = tid & 31;
    const int wm   = wid >> 2;          // 0..1
    const int wn   = wid & 3;           // 0..3
    const int rowBase = blockIdx.y * 128;
    const int colBase = blockIdx.x * 128;

    const int lr  = tid >> 1;
    const int lh  = tid & 1;
    const uint32_t soff = (uint32_t)(lr * STR + lh * 16) * 2;
    const size_t gAoff = (size_t)(rowBase + lr) * KDIM + lh * 16;
    const size_t gBoff = (size_t)(colBase + lr) * KDIM + lh * 16;

    const uint32_t aoff  = (uint32_t)((lane & 15) * STR + ((lane >> 4) << 3)) * 2;
    const uint32_t boff4 = (uint32_t)(((lane & 7) + ((lane >> 4) << 3)) * STR
                                      + (((lane >> 3) & 1) << 3)) * 2;

    float acc[4][4][4];
#pragma unroll
    for (int mi = 0; mi < 4; mi++)
#pragma unroll
        for (int ni = 0; ni < 4; ni++)
#pragma unroll
            for (int q = 0; q < 4; q++) acc[mi][ni][q] = 0.f;

#define LOAD_STAGE(st, ko)                                                   \
    do {                                                                     \
        CP16((st) +            soff,      Agh + gAoff + (ko));               \
        CP16((st) +            soff + 16, Agh + gAoff + (ko) + 8);           \
        CP16((st) + 1 * MATB + soff,      Agl + gAoff + (ko));               \
        CP16((st) + 1 * MATB + soff + 16, Agl + gAoff + (ko) + 8);           \
        CP16((st) + 2 * MATB + soff,      Bgh + gBoff + (ko));               \
        CP16((st) + 2 * MATB + soff + 16, Bgh + gBoff + (ko) + 8);           \
        CPCOMMIT();                                                          \
    } while (0)

    LOAD_STAGE(sb0 +          0, 0);
    LOAD_STAGE(sb0 + STAGEB, 32);

    for (int kc = 0; kc < NKC; kc++) {
        if (kc + 1 < NKC) CPWAIT(1); else CPWAIT(0);
        __syncthreads();   // all warps done computing kc-1 -> its buffer reusable
        if (kc + 2 < NKC) LOAD_STAGE(sb0 + ((kc + 2) % STAGES) * STAGEB, (size_t)(kc + 2) * 32);

        const uint32_t st = sb0 + (kc % STAGES) * STAGEB;
        const uint32_t sAh = st, sAl = st + MATB, sBh = st + 2 * MATB;

#pragma unroll
        for (int ks = 0; ks < 2; ks++) {
            const uint32_t kso = (uint32_t)(ks * 16) * 2;

            uint32_t bh4[2][4];
#pragma unroll
            for (int p = 0; p < 2; p++) {
                const uint32_t nb = (uint32_t)((wn * 32 + p * 16) * STR) * 2 + kso;
                LDSM4(bh4[p], sBh + nb + boff4);
            }
#pragma unroll
            for (int mi = 0; mi < 4; mi++) {
                const uint32_t mb = (uint32_t)((wm * 64 + mi * 16) * STR) * 2 + kso;
                uint32_t ah[4], al[4];
                LDSM4(ah, sAh + mb + aoff);
                LDSM4(al, sAl + mb + aoff);
#pragma unroll
                for (int ni = 0; ni < 4; ni++) {
                    uint32_t* bh = &bh4[ni >> 1][(ni & 1) * 2];
                    MMAH16816(acc[mi][ni], ah, bh);
                    MMAH16816(acc[mi][ni], al, bh);
                }
            }
        }
    }

    // ---- epilogue ----
    const int qrow = lane >> 2;
    const int qcol = lane & 3;
#pragma unroll
    for (int mi = 0; mi < 4; mi++) {
#pragma unroll
        for (int ni = 0; ni < 4; ni++) {
            const int c  = colBase + wn * 32 + ni * 8 + qcol * 2;
            const int m0 = rowBase + wm * 64 + mi * 16 + qrow;
            const int m1 = m0 + 8;
            float2 v0 = make_float2(acc[mi][ni][0], acc[mi][ni][1]);
            float2 v1 = make_float2(acc[mi][ni][2], acc[mi][ni][3]);
            const int b0 = m0 >> 11, n0 = m0 & 2047;
            const int b1 = m1 >> 11, n1 = m1 & 2047;
            if (MODE == 0) {
                if (c < HID) {
                    // Q: scale by 1/8 (exact), fp16 split, [bh, n, e]
                    const int h = c >> 6, e = c & 63;
                    const size_t i0 = ((size_t)(b0 * HEADS + h) * N_SEQ + n0) * EDIM + e;
                    const size_t i1 = ((size_t)(b1 * HEADS + h) * N_SEQ + n1) * EDIM + e;
                    uint32_t h2, l2;
                    split2h(v0.x * 0.125f, v0.y * 0.125f, h2, l2);
                    *(uint32_t*)&g_qh[i0] = h2; *(uint32_t*)&g_ql[i0] = l2;
                    split2h(v1.x * 0.125f, v1.y * 0.125f, h2, l2);
                    *(uint32_t*)&g_qh[i1] = h2; *(uint32_t*)&g_ql[i1] = l2;
                } else if (c < 2 * HID) {
                    // K: fp16 hi only, [bh, n, e]
                    const int c2 = c - HID;
                    const int h = c2 >> 6, e = c2 & 63;
                    const size_t i0 = ((size_t)(b0 * HEADS + h) * N_SEQ + n0) * EDIM + e;
                    const size_t i1 = ((size_t)(b1 * HEADS + h) * N_SEQ + n1) * EDIM + e;
                    *(__half2*)&g_kh[i0] = __floats2half2_rn(v0.x, v0.y);
                    *(__half2*)&g_kh[i1] = __floats2half2_rn(v1.x, v1.y);
                } else {
                    // V: fp16 hi only, TRANSPOSED [bh, e, n]
                    const int c2 = c - 2 * HID;
                    const int h = c2 >> 6, e = c2 & 63;
                    const int bh0 = b0 * HEADS + h, bh1 = b1 * HEADS + h;
                    g_vth[((size_t)bh0 * EDIM + e)     * N_SEQ + n0] = __float2half(v0.x);
                    g_vth[((size_t)bh0 * EDIM + e + 1) * N_SEQ + n0] = __float2half(v0.y);
                    g_vth[((size_t)bh1 * EDIM + e)     * N_SEQ + n1] = __float2half(v1.x);
                    g_vth[((size_t)bh1 * EDIM + e + 1) * N_SEQ + n1] = __float2half(v1.y);
                }
            } else {
                const float2 bb = *(const float2*)&bias[c];
                v0.x += bb.x; v0.y += bb.y;
                v1.x += bb.x; v1.y += bb.y;
                *(float2*)&out[(size_t)m0 * HID + c] = v0;
                *(float2*)&out[(size_t)m1 * HID + c] = v1;
            }
        }
    }
}

// ---------------------------------------------------------------------------
// Tensor-core flash attention (fp16 2-term, fp32 accum, online softmax).
// grid = (N_SEQ/128, BH), 256 threads (8 warps x 16 Q-rows).
// K/V tiles of 64 keys (hi-only), 3-stage cp.async, one sync per tile.
// S = Qh*Kh + Ql*Kh ; O += Ph*Vh + Pl*Vh.
// ---------------------------------------------------------------------------
#define ASTR   72                      // smem row stride in fp16 (144 B)
#define AMATB  (64 * ASTR * 2)         // 9216 bytes per matrix
#define ASTGB  (2 * AMATB)             // 18432 per stage (Kh, Vh)
#define ASTAGES 3
#define NT     (N_SEQ / 64)            // 32 key tiles

__global__ __launch_bounds__(256, 1) void attn_mma()
{
    extern __shared__ char dsm[];
    const uint32_t sb = smem_u32(dsm);

    const int tid  = threadIdx.x;
    const int wid  = tid >> 5;
    const int lane = tid & 31;
    const int qg   = lane >> 2;          // 0..7
    const int tig  = lane & 3;           // 0..3

    const int bh    = blockIdx.y;
    const int qbase = blockIdx.x * 128 + wid * 16;
    const size_t kvbase = (size_t)bh * N_SEQ * EDIM;

    uint32_t qhf[4][4], qlf[4][4];
    {
        const size_t q0 = kvbase + (size_t)(qbase + qg) * EDIM;
        const size_t q8 = q0 + 8 * EDIM;
#pragma unroll
        for (int kc = 0; kc < 4; kc++) {
            const int col = kc * 16 + tig * 2;
            qhf[kc][0] = *(const uint32_t*)&g_qh[q0 + col];
            qhf[kc][1] = *(const uint32_t*)&g_qh[q8 + col];
            qhf[kc][2] = *(const uint32_t*)&g_qh[q0 + col + 8];
            qhf[kc][3] = *(const uint32_t*)&g_qh[q8 + col + 8];
            qlf[kc][0] = *(const uint32_t*)&g_ql[q0 + col];
            qlf[kc][1] = *(const uint32_t*)&g_ql[q8 + col];
            qlf[kc][2] = *(const uint32_t*)&g_ql[q0 + col + 8];
            qlf[kc][3] = *(const uint32_t*)&g_ql[q8 + col + 8];
        }
    }

    float oacc[8][4];
#pragma unroll
    for (int ne = 0; ne < 8; ne++)
#pragma unroll
        for (int q = 0; q < 4; q++) oacc[ne][q] = 0.f;
    float m0 = -1e30f, m1 = -1e30f, lp0 = 0.f, lp1 = 0.f;

    const uint32_t OKH = 0, OVH = AMATB;

#define AT_LOAD(stg, kt)                                                        \
    do {                                                                        \
        _Pragma("unroll")                                                       \
        for (int t = 0; t < 2; t++) {                                           \
            const int idx = tid + t * 256;                                      \
            const int r = idx >> 3, ch = idx & 7;                               \
            const uint32_t so = (stg) + (uint32_t)(r * 144 + ch * 16);          \
            const size_t kg = kvbase + (size_t)((kt) * 64 + r) * EDIM + ch * 8; \
            const size_t vg = kvbase + (size_t)r * N_SEQ + (kt) * 64 + ch * 8;  \
            CP16(so + OKH, g_kh  + kg);                                         \
            CP16(so + OVH, g_vth + vg);                                         \
        }                                                                       \
        CPCOMMIT();                                                             \
    } while (0)

    AT_LOAD(sb, 0);
    AT_LOAD(sb + ASTGB, 1);

    const uint32_t lm4 = (uint32_t)(((lane & 7) + ((lane >> 4) << 3)) * ASTR
                                    + (((lane >> 3) & 1) << 3)) * 2;

    for (int kt = 0; kt < NT; kt++) {
        if (kt + 1 < NT) CPWAIT(1); else CPWAIT(0);
        __syncthreads();
        if (kt + 2 < NT) AT_LOAD(sb + ((kt + 2) % ASTAGES) * ASTGB, kt + 2);

        const uint32_t stg = sb + (kt % ASTAGES) * ASTGB;

        // ---- S = Q @ K^T ----
        float sacc[8][4];
#pragma unroll
        for (int nt = 0; nt < 8; nt++)
#pragma unroll
            for (int q = 0; q < 4; q++) sacc[nt][q] = 0.f;

#pragma unroll
        for (int kc = 0; kc < 4; kc++) {
            const uint32_t kso = (uint32_t)(kc * 16) * 2;
#pragma unroll
            for (int ntp = 0; ntp < 4; ntp++) {
                uint32_t kh4[4];
                const uint32_t off = (uint32_t)(ntp * 16 * ASTR) * 2 + kso + lm4;
                LDSM4(kh4, stg + OKH + off);
                MMAH16816(sacc[2 * ntp],     qhf[kc], kh4);
                MMAH16816(sacc[2 * ntp],     qlf[kc], kh4);
                MMAH16816(sacc[2 * ntp + 1], qhf[kc], (kh4 + 2));
                MMAH16816(sacc[2 * ntp + 1], qlf[kc], (kh4 + 2));
            }
        }

        // ---- online softmax ----
        float mx0 = -1e30f, mx1 = -1e30f;
#pragma unroll
        for (int nt = 0; nt < 8; nt++) {
            mx0 = fmaxf(mx0, fmaxf(sacc[nt][0], sacc[nt][1]));
            mx1 = fmaxf(mx1, fmaxf(sacc[nt][2], sacc[nt][3]));
        }
        mx0 = fmaxf(mx0, __shfl_xor_sync(0xffffffffu, mx0, 1));
        mx0 = fmaxf(mx0, __shfl_xor_sync(0xffffffffu, mx0, 2));
        mx1 = fmaxf(mx1, __shfl_xor_sync(0xffffffffu, mx1, 1));
        mx1 = fmaxf(mx1, __shfl_xor_sync(0xffffffffu, mx1, 2));

        const float mn0 = fmaxf(m0, mx0), mn1 = fmaxf(m1, mx1);
        const float corr0 = __expf(m0 - mn0), corr1 = __expf(m1 - mn1);
        m0 = mn0; m1 = mn1;

        float ls0 = 0.f, ls1 = 0.f;
#pragma unroll
        for (int nt = 0; nt < 8; nt++) {
            sacc[nt][0] = __expf(sacc[nt][0] - mn0);
            sacc[nt][1] = __expf(sacc[nt][1] - mn0);
            sacc[nt][2] = __expf(sacc[nt][2] - mn1);
            sacc[nt][3] = __expf(sacc[nt][3] - mn1);
            ls0 += sacc[nt][0] + sacc[nt][1];
            ls1 += sacc[nt][2] + sacc[nt][3];
        }
        lp0 = lp0 * corr0 + ls0;
        lp1 = lp1 * corr1 + ls1;

#pragma unroll
        for (int ne = 0; ne < 8; ne++) {
            oacc[ne][0] *= corr0; oacc[ne][1] *= corr0;
            oacc[ne][2] *= corr1; oacc[ne][3] *= corr1;
        }

        // ---- pack P (A-fragments for PV), fp16 split hi/lo ----
        uint32_t phf[4][4], plf[4][4];
#pragma unroll
        for (int kc = 0; kc < 4; kc++) {
            split2h(sacc[2 * kc][0],     sacc[2 * kc][1],     phf[kc][0], plf[kc][0]);
            split2h(sacc[2 * kc][2],     sacc[2 * kc][3],     phf[kc][1], plf[kc][1]);
            split2h(sacc[2 * kc + 1][0], sacc[2 * kc + 1][1], phf[kc][2], plf[kc][2]);
            split2h(sacc[2 * kc + 1][2], sacc[2 * kc + 1][3], phf[kc][3], plf[kc][3]);
        }

        // ---- O += P @ V ----
#pragma unroll
        for (int kc = 0; kc < 4; kc++) {
            const uint32_t kso = (uint32_t)(kc * 16) * 2;
#pragma unroll
            for (int nep = 0; nep < 4; nep++) {
                uint32_t vh4[4];
                const uint32_t off = (uint32_t)(nep * 16 * ASTR) * 2 + kso + lm4;
                LDSM4(vh4, stg + OVH + off);
                MMAH16816(oacc[2 * nep],     phf[kc], vh4);
                MMAH16816(oacc[2 * nep],     plf[kc], vh4);
                MMAH16816(oacc[2 * nep + 1], phf[kc], (vh4 + 2));
                MMAH16816(oacc[2 * nep + 1], plf[kc], (vh4 + 2));
            }
        }
    }

    // ---- finalize: O / l, fp16 split hi/lo at [b, n, h*64 + e] ----
    lp0 += __shfl_xor_sync(0xffffffffu, lp0, 1);
    lp0 += __shfl_xor_sync(0xffffffffu, lp0, 2);
    lp1 += __shfl_xor_sync(0xffffffffu, lp1, 1);
    lp1 += __shfl_xor_sync(0xffffffffu, lp1, 2);
    const float inv0 = 1.f / lp0, inv1 = 1.f / lp1;

    const int b = bh >> 4, h = bh & 15;
    const int n0 = qbase + qg, n1 = n0 + 8;
    const size_t o0 = (size_t)(b * N_SEQ + n0) * HID + h * EDIM;
    const size_t o1 = (size_t)(b * N_SEQ + n1) * HID + h * EDIM;
#pragma unroll
    for (int ne = 0; ne < 8; ne++) {
        const int e = ne * 8 + tig * 2;
        uint32_t h2, l2;
        split2h(oacc[ne][0] * inv0, oacc[ne][1] * inv0, h2, l2);
        *(uint32_t*)&g_atth[o0 + e] = h2; *(uint32_t*)&g_attl[o0 + e] = l2;
        split2h(oacc[ne][2] * inv1, oacc[ne][3] * inv1, h2, l2);
        *(uint32_t*)&g_atth[o1 + e] = h2; *(uint32_t*)&g_attl[o1 + e] = l2;
    }
}

// ---------------------------------------------------------------------------
extern "C" void kernel_launch(void* const* d_in, const int* in_sizes, int n_in,
                              void* d_out, int out_size)
{
    (void)in_sizes; (void)n_in; (void)out_size;
    const float* x     = (const float*)d_in[0];
    const float* w_q   = (const float*)d_in[1];
    const float* w_kv  = (const float*)d_in[2];
    const float* w_out = (const float*)d_in[3];
    const float* b_out = (const float*)d_in[4];
    float* out = (float*)d_out;

    void *p_xh, *p_xl, *p_wall, *p_woh, *p_ath, *p_atl;
    cudaGetSymbolAddress(&p_xh, g_xh);     cudaGetSymbolAddress(&p_xl, g_xl);
    cudaGetSymbolAddress(&p_wall, g_wall);
    cudaGetSymbolAddress(&p_woh, g_woh);
    cudaGetSymbolAddress(&p_ath, g_atth);  cudaGetSymbolAddress(&p_atl, g_attl);

    const int gemm_smem = STAGES * STAGEB;   // 92160
    cudaFuncSetAttribute(gemm_mma<0>, cudaFuncAttributeMaxDynamicSharedMemorySize, gemm_smem);
    cudaFuncSetAttribute(gemm_mma<1>, cudaFuncAttributeMaxDynamicSharedMemorySize, gemm_smem);
    const int attn_smem = ASTAGES * ASTGB;   // 55296
    cudaFuncSetAttribute(attn_mma, cudaFuncAttributeMaxDynamicSharedMemorySize, attn_smem);

    // 1) Split x into fp16 hi/lo; weights to fp16 hi only (fused [w_q; w_kv])
    split_f16_k<<<(M_TOT * KDIM / 4 + 255) / 256, 256>>>(x, (__half*)p_xh, (__half*)p_xl, M_TOT * KDIM / 4);
    tohalf_k<<<(HID * KDIM / 4 + 255) / 256, 256>>>(w_q, (__half*)p_wall, HID * KDIM / 4);
    tohalf_k<<<(2 * HID * KDIM / 4 + 255) / 256, 256>>>(w_kv, (__half*)p_wall + HID * KDIM, 2 * HID * KDIM / 4);
    tohalf_k<<<(HID * KDIM / 4 + 255) / 256, 256>>>(w_out, (__half*)p_woh, HID * KDIM / 4);

    // 2) Fused QKV projection (fp16 2-term mma.sync)
    gemm_mma<0><<<dim3(3 * HID / 128, M_TOT / 128), 256, gemm_smem>>>(
        (const __half*)p_xh, (const __half*)p_xl, (const __half*)p_wall, nullptr, nullptr);

    // 3) Attention (fp16 2-term mma.sync flash attention)
    attn_mma<<<dim3(N_SEQ / 128, BH), 256, attn_smem>>>();

    // 4) Output projection + bias (fp16 2-term mma.sync)
    gemm_mma<1><<<dim3(HID / 128, M_TOT / 128), 256, gemm_smem>>>(
        (const __half*)p_ath, (const __half*)p_atl, (const __half*)p_woh, b_out, out);
}

// round 10
// speedup vs baseline: 4.9310x; 1.1052x over previous
#include <cuda_runtime.h>
#include <cuda_bf16.h>
#include <cuda_fp16.h>
#include <cstdint>

// Problem constants
#define B_SZ   4
#define N_SEQ  2048
#define HEADS  16
#define EDIM   64
#define KDIM   1024
#define M_TOT  (B_SZ * N_SEQ)          // 8192
#define HID    (HEADS * EDIM)          // 1024
#define BH     (B_SZ * HEADS)          // 64

// ---------------------------------------------------------------------------
// Scratch (device globals — no allocation allowed)
// ---------------------------------------------------------------------------
__device__ __half g_xh[M_TOT * KDIM],  g_xl[M_TOT * KDIM];
__device__ __half g_wall[3 * HID * KDIM];          // [w_q ; w_kv] fused, fp16 hi
__device__ __half g_woh[HID * KDIM];
__device__ __half g_atth[M_TOT * HID], g_attl[M_TOT * HID];

// fp16 attention operands: Q hi/lo ([bh, n, e]); K hi ([bh, n, e]); V hi transposed ([bh, e, n])
__device__ __half g_qh[BH * N_SEQ * EDIM], g_ql[BH * N_SEQ * EDIM];
__device__ __half g_kh[BH * N_SEQ * EDIM];
__device__ __half g_vth[BH * EDIM * N_SEQ];

// ---------------------------------------------------------------------------
// Base-target-safe PTX helpers (sm_80+ features only)
// ---------------------------------------------------------------------------
__device__ __forceinline__ uint32_t smem_u32(const void* p) {
    uint32_t a;
    asm("{ .reg .u64 t; cvta.to.shared.u64 t, %1; cvt.u32.u64 %0, t; }" : "=r"(a) : "l"(p));
    return a;
}

#define CP16(s, g) \
    asm volatile("cp.async.cg.shared.global [%0], [%1], 16;" :: "r"(s), "l"(g) : "memory")
#define CPCOMMIT() asm volatile("cp.async.commit_group;" ::: "memory")
#define CPWAIT(n)  asm volatile("cp.async.wait_group %0;" :: "n"(n) : "memory")

#define LDSM4(R, addr)                                                            \
    asm volatile("ldmatrix.sync.aligned.m8n8.x4.shared.b16 {%0,%1,%2,%3}, [%4];"  \
        : "=r"((R)[0]), "=r"((R)[1]), "=r"((R)[2]), "=r"((R)[3]) : "r"(addr))

#define MMAH16816(d, a, b)                                                        \
    asm volatile("mma.sync.aligned.m16n8k16.row.col.f32.f16.f16.f32 "             \
        "{%0,%1,%2,%3}, {%4,%5,%6,%7}, {%8,%9}, {%0,%1,%2,%3};"                   \
        : "+f"((d)[0]), "+f"((d)[1]), "+f"((d)[2]), "+f"((d)[3])                  \
        : "r"((a)[0]), "r"((a)[1]), "r"((a)[2]), "r"((a)[3]),                     \
          "r"((b)[0]), "r"((b)[1]))

// split pair of fp32 into packed fp16 hi / lo words
__device__ __forceinline__ void split2h(float a, float b, uint32_t& h2, uint32_t& l2) {
    __half2 hh = __floats2half2_rn(a, b);
    float fa = __low2float(hh), fb = __high2float(hh);
    __half2 ll = __floats2half2_rn(a - fa, b - fb);
    h2 = *(uint32_t*)&hh;
    l2 = *(uint32_t*)&ll;
}

__device__ __forceinline__ uint32_t pack2h(float a, float b) {
    __half2 hh = __floats2half2_rn(a, b);
    return *(uint32_t*)&hh;
}

// ---------------------------------------------------------------------------
// Split fp32 -> (hi, lo) fp16 pairs   /   fp32 -> fp16 (hi only)
// ---------------------------------------------------------------------------
__global__ __launch_bounds__(256) void split_f16_k(const float* __restrict__ s,
                                                   __half* __restrict__ hi,
                                                   __half* __restrict__ lo, int n4)
{
    int i = blockIdx.x * 256 + threadIdx.x;
    if (i >= n4) return;
    float4 v = ((const float4*)s)[i];
    uint32_t h0, l0, h1, l1;
    split2h(v.x, v.y, h0, l0);
    split2h(v.z, v.w, h1, l1);
    ((uint32_t*)hi)[i * 2 + 0] = h0;
    ((uint32_t*)hi)[i * 2 + 1] = h1;
    ((uint32_t*)lo)[i * 2 + 0] = l0;
    ((uint32_t*)lo)[i * 2 + 1] = l1;
}

__global__ __launch_bounds__(256) void tohalf_k(const float* __restrict__ s,
                                                __half* __restrict__ hi, int n4)
{
    int i = blockIdx.x * 256 + threadIdx.x;
    if (i >= n4) return;
    float4 v = ((const float4*)s)[i];
    ((__half2*)hi)[i * 2 + 0] = __floats2half2_rn(v.x, v.y);
    ((__half2*)hi)[i * 2 + 1] = __floats2half2_rn(v.z, v.w);
}

// ---------------------------------------------------------------------------
// mma.sync GEMM: C[m,c] = sum_k A[m,k]*B[c,k], fp16 2-term split
// (D = Ah*Bh + Al*Bh; B hi-only).
// 128x128 block tile, 8 warps in 4(m) x 2(n) grid, 32x64 warp tile
// (128 smem bytes per MMA), K-chunk 32, 3-stage cp.async, 2 CTAs/SM.
// MODE 0: fused QKV proj; MODE 1: out proj -> fp32 out + bias
// ---------------------------------------------------------------------------
#define STR     40
#define MATB    (128 * STR * 2)        // 10240 bytes per matrix per stage
#define STAGEB  (3 * MATB)             // 30720 (Ah, Al, Bh)
#define STAGES  3
#define NKC     (KDIM / 32)            // 32 k-chunks

template <int MODE>
__global__ __launch_bounds__(256, 2) void gemm_mma(
    const __half* __restrict__ Agh, const __half* __restrict__ Agl,
    const __half* __restrict__ Bgh,
    const float* __restrict__ bias, float* __restrict__ out)
{
    extern __shared__ char dsm[];
    const uint32_t sb0 = smem_u32(dsm);

    const int tid  = threadIdx.x;
    const int wid  = tid >> 5;
    const int lane = tid & 31;
    const int wm   = wid & 3;           // 0..3 (m rows of warp grid)
    const int wn   = wid >> 2;          // 0..1 (n cols of warp grid)
    const int rowBase = blockIdx.y * 128;
    const int colBase = blockIdx.x * 128;

    const int lr  = tid >> 1;
    const int lh  = tid & 1;
    const uint32_t soff = (uint32_t)(lr * STR + lh * 16) * 2;
    const size_t gAoff = (size_t)(rowBase + lr) * KDIM + lh * 16;
    const size_t gBoff = (size_t)(colBase + lr) * KDIM + lh * 16;

    const uint32_t aoff  = (uint32_t)((lane & 15) * STR + ((lane >> 4) << 3)) * 2;
    const uint32_t boff4 = (uint32_t)(((lane & 7) + ((lane >> 4) << 3)) * STR
                                      + (((lane >> 3) & 1) << 3)) * 2;

    float acc[2][8][4];
#pragma unroll
    for (int mi = 0; mi < 2; mi++)
#pragma unroll
        for (int ni = 0; ni < 8; ni++)
#pragma unroll
            for (int q = 0; q < 4; q++) acc[mi][ni][q] = 0.f;

#define LOAD_STAGE(st, ko)                                                   \
    do {                                                                     \
        CP16((st) +            soff,      Agh + gAoff + (ko));               \
        CP16((st) +            soff + 16, Agh + gAoff + (ko) + 8);           \
        CP16((st) + 1 * MATB + soff,      Agl + gAoff + (ko));               \
        CP16((st) + 1 * MATB + soff + 16, Agl + gAoff + (ko) + 8);           \
        CP16((st) + 2 * MATB + soff,      Bgh + gBoff + (ko));               \
        CP16((st) + 2 * MATB + soff + 16, Bgh + gBoff + (ko) + 8);           \
        CPCOMMIT();                                                          \
    } while (0)

    LOAD_STAGE(sb0 +      0,  0);
    LOAD_STAGE(sb0 + STAGEB, 32);

    for (int kc = 0; kc < NKC; kc++) {
        if (kc + 1 < NKC) CPWAIT(1); else CPWAIT(0);
        __syncthreads();   // all warps done computing kc-1 -> its buffer reusable
        if (kc + 2 < NKC) LOAD_STAGE(sb0 + ((kc + 2) % STAGES) * STAGEB, (size_t)(kc + 2) * 32);

        const uint32_t st = sb0 + (kc % STAGES) * STAGEB;
        const uint32_t sAh = st, sAl = st + MATB, sBh = st + 2 * MATB;

#pragma unroll
        for (int ks = 0; ks < 2; ks++) {
            const uint32_t kso = (uint32_t)(ks * 16) * 2;

            // B fragments: 4 paired x4 loads cover 8 n-tiles
            uint32_t bh4[4][4];
#pragma unroll
            for (int p = 0; p < 4; p++) {
                const uint32_t nb = (uint32_t)((wn * 64 + p * 16) * STR) * 2 + kso;
                LDSM4(bh4[p], sBh + nb + boff4);
            }
#pragma unroll
            for (int mi = 0; mi < 2; mi++) {
                const uint32_t mb = (uint32_t)((wm * 32 + mi * 16) * STR) * 2 + kso;
                uint32_t ah[4], al[4];
                LDSM4(ah, sAh + mb + aoff);
                LDSM4(al, sAl + mb + aoff);
#pragma unroll
                for (int ni = 0; ni < 8; ni++) {
                    uint32_t* bh = &bh4[ni >> 1][(ni & 1) * 2];
                    MMAH16816(acc[mi][ni], ah, bh);
                    MMAH16816(acc[mi][ni], al, bh);
                }
            }
        }
    }

    // ---- epilogue ----
    const int qrow = lane >> 2;
    const int qcol = lane & 3;
#pragma unroll
    for (int mi = 0; mi < 2; mi++) {
#pragma unroll
        for (int ni = 0; ni < 8; ni++) {
            const int c  = colBase + wn * 64 + ni * 8 + qcol * 2;
            const int m0 = rowBase + wm * 32 + mi * 16 + qrow;
            const int m1 = m0 + 8;
            float2 v0 = make_float2(acc[mi][ni][0], acc[mi][ni][1]);
            float2 v1 = make_float2(acc[mi][ni][2], acc[mi][ni][3]);
            const int b0 = m0 >> 11, n0 = m0 & 2047;
            const int b1 = m1 >> 11, n1 = m1 & 2047;
            if (MODE == 0) {
                if (c < HID) {
                    // Q: scale by 1/8 (exact), fp16 split, [bh, n, e]
                    const int h = c >> 6, e = c & 63;
                    const size_t i0 = ((size_t)(b0 * HEADS + h) * N_SEQ + n0) * EDIM + e;
                    const size_t i1 = ((size_t)(b1 * HEADS + h) * N_SEQ + n1) * EDIM + e;
                    uint32_t h2, l2;
                    split2h(v0.x * 0.125f, v0.y * 0.125f, h2, l2);
                    *(uint32_t*)&g_qh[i0] = h2; *(uint32_t*)&g_ql[i0] = l2;
                    split2h(v1.x * 0.125f, v1.y * 0.125f, h2, l2);
                    *(uint32_t*)&g_qh[i1] = h2; *(uint32_t*)&g_ql[i1] = l2;
                } else if (c < 2 * HID) {
                    // K: fp16 hi only, [bh, n, e]
                    const int c2 = c - HID;
                    const int h = c2 >> 6, e = c2 & 63;
                    const size_t i0 = ((size_t)(b0 * HEADS + h) * N_SEQ + n0) * EDIM + e;
                    const size_t i1 = ((size_t)(b1 * HEADS + h) * N_SEQ + n1) * EDIM + e;
                    *(__half2*)&g_kh[i0] = __floats2half2_rn(v0.x, v0.y);
                    *(__half2*)&g_kh[i1] = __floats2half2_rn(v1.x, v1.y);
                } else {
                    // V: fp16 hi only, TRANSPOSED [bh, e, n]
                    const int c2 = c - 2 * HID;
                    const int h = c2 >> 6, e = c2 & 63;
                    const int bh0 = b0 * HEADS + h, bh1 = b1 * HEADS + h;
                    g_vth[((size_t)bh0 * EDIM + e)     * N_SEQ + n0] = __float2half(v0.x);
                    g_vth[((size_t)bh0 * EDIM + e + 1) * N_SEQ + n0] = __float2half(v0.y);
                    g_vth[((size_t)bh1 * EDIM + e)     * N_SEQ + n1] = __float2half(v1.x);
                    g_vth[((size_t)bh1 * EDIM + e + 1) * N_SEQ + n1] = __float2half(v1.y);
                }
            } else {
                const float2 bb = *(const float2*)&bias[c];
                v0.x += bb.x; v0.y += bb.y;
                v1.x += bb.x; v1.y += bb.y;
                *(float2*)&out[(size_t)m0 * HID + c] = v0;
                *(float2*)&out[(size_t)m1 * HID + c] = v1;
            }
        }
    }
}

// ---------------------------------------------------------------------------
// Tensor-core flash attention (fp16, fp32 accum, online softmax).
// grid = (N_SEQ/128, BH), 256 threads (8 warps x 16 Q-rows).
// K/V tiles of 64 keys (hi-only), 3-stage cp.async, one sync per tile.
// S = Qh*Kh + Ql*Kh (2-term) ; O += Ph*Vh (1-term, P in [0,1]).
// ---------------------------------------------------------------------------
#define ASTR   72                      // smem row stride in fp16 (144 B)
#define AMATB  (64 * ASTR * 2)         // 9216 bytes per matrix
#define ASTGB  (2 * AMATB)             // 18432 per stage (Kh, Vh)
#define ASTAGES 3
#define NT     (N_SEQ / 64)            // 32 key tiles

__global__ __launch_bounds__(256, 1) void attn_mma()
{
    extern __shared__ char dsm[];
    const uint32_t sb = smem_u32(dsm);

    const int tid  = threadIdx.x;
    const int wid  = tid >> 5;
    const int lane = tid & 31;
    const int qg   = lane >> 2;          // 0..7
    const int tig  = lane & 3;           // 0..3

    const int bh    = blockIdx.y;
    const int qbase = blockIdx.x * 128 + wid * 16;
    const size_t kvbase = (size_t)bh * N_SEQ * EDIM;

    uint32_t qhf[4][4], qlf[4][4];
    {
        const size_t q0 = kvbase + (size_t)(qbase + qg) * EDIM;
        const size_t q8 = q0 + 8 * EDIM;
#pragma unroll
        for (int kc = 0; kc < 4; kc++) {
            const int col = kc * 16 + tig * 2;
            qhf[kc][0] = *(const uint32_t*)&g_qh[q0 + col];
            qhf[kc][1] = *(const uint32_t*)&g_qh[q8 + col];
            qhf[kc][2] = *(const uint32_t*)&g_qh[q0 + col + 8];
            qhf[kc][3] = *(const uint32_t*)&g_qh[q8 + col + 8];
            qlf[kc][0] = *(const uint32_t*)&g_ql[q0 + col];
            qlf[kc][1] = *(const uint32_t*)&g_ql[q8 + col];
            qlf[kc][2] = *(const uint32_t*)&g_ql[q0 + col + 8];
            qlf[kc][3] = *(const uint32_t*)&g_ql[q8 + col + 8];
        }
    }

    float oacc[8][4];
#pragma unroll
    for (int ne = 0; ne < 8; ne++)
#pragma unroll
        for (int q = 0; q < 4; q++) oacc[ne][q] = 0.f;
    float m0 = -1e30f, m1 = -1e30f, lp0 = 0.f, lp1 = 0.f;

    const uint32_t OKH = 0, OVH = AMATB;

#define AT_LOAD(stg, kt)                                                        \
    do {                                                                        \
        _Pragma("unroll")                                                       \
        for (int t = 0; t < 2; t++) {                                           \
            const int idx = tid + t * 256;                                      \
            const int r = idx >> 3, ch = idx & 7;                               \
            const uint32_t so = (stg) + (uint32_t)(r * 144 + ch * 16);          \
            const size_t kg = kvbase + (size_t)((kt) * 64 + r) * EDIM + ch * 8; \
            const size_t vg = kvbase + (size_t)r * N_SEQ + (kt) * 64 + ch * 8;  \
            CP16(so + OKH, g_kh  + kg);                                         \
            CP16(so + OVH, g_vth + vg);                                         \
        }                                                                       \
        CPCOMMIT();                                                             \
    } while (0)

    AT_LOAD(sb, 0);
    AT_LOAD(sb + ASTGB, 1);

    const uint32_t lm4 = (uint32_t)(((lane & 7) + ((lane >> 4) << 3)) * ASTR
                                    + (((lane >> 3) & 1) << 3)) * 2;

    for (int kt = 0; kt < NT; kt++) {
        if (kt + 1 < NT) CPWAIT(1); else CPWAIT(0);
        __syncthreads();
        if (kt + 2 < NT) AT_LOAD(sb + ((kt + 2) % ASTAGES) * ASTGB, kt + 2);

        const uint32_t stg = sb + (kt % ASTAGES) * ASTGB;

        // ---- S = Q @ K^T (2-term) ----
        float sacc[8][4];
#pragma unroll
        for (int nt = 0; nt < 8; nt++)
#pragma unroll
            for (int q = 0; q < 4; q++) sacc[nt][q] = 0.f;

#pragma unroll
        for (int kc = 0; kc < 4; kc++) {
            const uint32_t kso = (uint32_t)(kc * 16) * 2;
#pragma unroll
            for (int ntp = 0; ntp < 4; ntp++) {
                uint32_t kh4[4];
                const uint32_t off = (uint32_t)(ntp * 16 * ASTR) * 2 + kso + lm4;
                LDSM4(kh4, stg + OKH + off);
                MMAH16816(sacc[2 * ntp],     qhf[kc], kh4);
                MMAH16816(sacc[2 * ntp],     qlf[kc], kh4);
                MMAH16816(sacc[2 * ntp + 1], qhf[kc], (kh4 + 2));
                MMAH16816(sacc[2 * ntp + 1], qlf[kc], (kh4 + 2));
            }
        }

        // ---- online softmax ----
        float mx0 = -1e30f, mx1 = -1e30f;
#pragma unroll
        for (int nt = 0; nt < 8; nt++) {
            mx0 = fmaxf(mx0, fmaxf(sacc[nt][0], sacc[nt][1]));
            mx1 = fmaxf(mx1, fmaxf(sacc[nt][2], sacc[nt][3]));
        }
        mx0 = fmaxf(mx0, __shfl_xor_sync(0xffffffffu, mx0, 1));
        mx0 = fmaxf(mx0, __shfl_xor_sync(0xffffffffu, mx0, 2));
        mx1 = fmaxf(mx1, __shfl_xor_sync(0xffffffffu, mx1, 1));
        mx1 = fmaxf(mx1, __shfl_xor_sync(0xffffffffu, mx1, 2));

        const float mn0 = fmaxf(m0, mx0), mn1 = fmaxf(m1, mx1);
        const float corr0 = __expf(m0 - mn0), corr1 = __expf(m1 - mn1);
        m0 = mn0; m1 = mn1;

        float ls0 = 0.f, ls1 = 0.f;
#pragma unroll
        for (int nt = 0; nt < 8; nt++) {
            sacc[nt][0] = __expf(sacc[nt][0] - mn0);
            sacc[nt][1] = __expf(sacc[nt][1] - mn0);
            sacc[nt][2] = __expf(sacc[nt][2] - mn1);
            sacc[nt][3] = __expf(sacc[nt][3] - mn1);
            ls0 += sacc[nt][0] + sacc[nt][1];
            ls1 += sacc[nt][2] + sacc[nt][3];
        }
        lp0 = lp0 * corr0 + ls0;
        lp1 = lp1 * corr1 + ls1;

#pragma unroll
        for (int ne = 0; ne < 8; ne++) {
            oacc[ne][0] *= corr0; oacc[ne][1] *= corr0;
            oacc[ne][2] *= corr1; oacc[ne][3] *= corr1;
        }

        // ---- pack P (A-fragments for PV), fp16 hi only ----
        uint32_t phf[4][4];
#pragma unroll
        for (int kc = 0; kc < 4; kc++) {
            phf[kc][0] = pack2h(sacc[2 * kc][0],     sacc[2 * kc][1]);
            phf[kc][1] = pack2h(sacc[2 * kc][2],     sacc[2 * kc][3]);
            phf[kc][2] = pack2h(sacc[2 * kc + 1][0], sacc[2 * kc + 1][1]);
            phf[kc][3] = pack2h(sacc[2 * kc + 1][2], sacc[2 * kc + 1][3]);
        }

        // ---- O += P @ V (1-term) ----
#pragma unroll
        for (int kc = 0; kc < 4; kc++) {
            const uint32_t kso = (uint32_t)(kc * 16) * 2;
#pragma unroll
            for (int nep = 0; nep < 4; nep++) {
                uint32_t vh4[4];
                const uint32_t off = (uint32_t)(nep * 16 * ASTR) * 2 + kso + lm4;
                LDSM4(vh4, stg + OVH + off);
                MMAH16816(oacc[2 * nep],     phf[kc], vh4);
                MMAH16816(oacc[2 * nep + 1], phf[kc], (vh4 + 2));
            }
        }
    }

    // ---- finalize: O / l, fp16 split hi/lo at [b, n, h*64 + e] ----
    lp0 += __shfl_xor_sync(0xffffffffu, lp0, 1);
    lp0 += __shfl_xor_sync(0xffffffffu, lp0, 2);
    lp1 += __shfl_xor_sync(0xffffffffu, lp1, 1);
    lp1 += __shfl_xor_sync(0xffffffffu, lp1, 2);
    const float inv0 = 1.f / lp0, inv1 = 1.f / lp1;

    const int b = bh >> 4, h = bh & 15;
    const int n0 = qbase + qg, n1 = n0 + 8;
    const size_t o0 = (size_t)(b * N_SEQ + n0) * HID + h * EDIM;
    const size_t o1 = (size_t)(b * N_SEQ + n1) * HID + h * EDIM;
#pragma unroll
    for (int ne = 0; ne < 8; ne++) {
        const int e = ne * 8 + tig * 2;
        uint32_t h2, l2;
        split2h(oacc[ne][0] * inv0, oacc[ne][1] * inv0, h2, l2);
        *(uint32_t*)&g_atth[o0 + e] = h2; *(uint32_t*)&g_attl[o0 + e] = l2;
        split2h(oacc[ne][2] * inv1, oacc[ne][3] * inv1, h2, l2);
        *(uint32_t*)&g_atth[o1 + e] = h2; *(uint32_t*)&g_attl[o1 + e] = l2;
    }
}

// ---------------------------------------------------------------------------
extern "C" void kernel_launch(void* const* d_in, const int* in_sizes, int n_in,
                              void* d_out, int out_size)
{
    (void)in_sizes; (void)n_in; (void)out_size;
    const float* x     = (const float*)d_in[0];
    const float* w_q   = (const float*)d_in[1];
    const float* w_kv  = (const float*)d_in[2];
    const float* w_out = (const float*)d_in[3];
    const float* b_out = (const float*)d_in[4];
    float* out = (float*)d_out;

    void *p_xh, *p_xl, *p_wall, *p_woh, *p_ath, *p_atl;
    cudaGetSymbolAddress(&p_xh, g_xh);     cudaGetSymbolAddress(&p_xl, g_xl);
    cudaGetSymbolAddress(&p_wall, g_wall);
    cudaGetSymbolAddress(&p_woh, g_woh);
    cudaGetSymbolAddress(&p_ath, g_atth);  cudaGetSymbolAddress(&p_atl, g_attl);

    const int gemm_smem = STAGES * STAGEB;   // 92160
    cudaFuncSetAttribute(gemm_mma<0>, cudaFuncAttributeMaxDynamicSharedMemorySize, gemm_smem);
    cudaFuncSetAttribute(gemm_mma<1>, cudaFuncAttributeMaxDynamicSharedMemorySize, gemm_smem);
    const int attn_smem = ASTAGES * ASTGB;   // 55296
    cudaFuncSetAttribute(attn_mma, cudaFuncAttributeMaxDynamicSharedMemorySize, attn_smem);

    // 1) Split x into fp16 hi/lo; weights to fp16 hi only (fused [w_q; w_kv])
    split_f16_k<<<(M_TOT * KDIM / 4 + 255) / 256, 256>>>(x, (__half*)p_xh, (__half*)p_xl, M_TOT * KDIM / 4);
    tohalf_k<<<(HID * KDIM / 4 + 255) / 256, 256>>>(w_q, (__half*)p_wall, HID * KDIM / 4);
    tohalf_k<<<(2 * HID * KDIM / 4 + 255) / 256, 256>>>(w_kv, (__half*)p_wall + HID * KDIM, 2 * HID * KDIM / 4);
    tohalf_k<<<(HID * KDIM / 4 + 255) / 256, 256>>>(w_out, (__half*)p_woh, HID * KDIM / 4);

    // 2) Fused QKV projection (fp16 2-term mma.sync)
    gemm_mma<0><<<dim3(3 * HID / 128, M_TOT / 128), 256, gemm_smem>>>(
        (const __half*)p_xh, (const __half*)p_xl, (const __half*)p_wall, nullptr, nullptr);

    // 3) Attention (fp16 mma.sync flash attention, QK 2-term / PV 1-term)
    attn_mma<<<dim3(N_SEQ / 128, BH), 256, attn_smem>>>();

    // 4) Output projection + bias (fp16 2-term mma.sync)
    gemm_mma<1><<<dim3(HID / 128, M_TOT / 128), 256, gemm_smem>>>(
        (const __half*)p_ath, (const __half*)p_atl, (const __half*)p_woh, b_out, out);
}

// round 11
// speedup vs baseline: 5.5838x; 1.1324x over previous
#include <cuda_runtime.h>
#include <cuda_bf16.h>
#include <cuda_fp16.h>
#include <cstdint>

// Problem constants
#define B_SZ   4
#define N_SEQ  2048
#define HEADS  16
#define EDIM   64
#define KDIM   1024
#define M_TOT  (B_SZ * N_SEQ)          // 8192
#define HID    (HEADS * EDIM)          // 1024
#define BH     (B_SZ * HEADS)          // 64

// ---------------------------------------------------------------------------
// Scratch (device globals — no allocation allowed)
// ---------------------------------------------------------------------------
__device__ __half g_xh[M_TOT * KDIM],  g_xl[M_TOT * KDIM];
__device__ __half g_wall[3 * HID * KDIM];          // [w_q ; w_kv] fused, fp16 hi
__device__ __half g_woh[HID * KDIM];
__device__ __half g_atth[M_TOT * HID];             // attention out, fp16 hi only

// fp16 attention operands: Q hi/lo ([bh, n, e]); K hi ([bh, n, e]); V hi transposed ([bh, e, n])
__device__ __half g_qh[BH * N_SEQ * EDIM], g_ql[BH * N_SEQ * EDIM];
__device__ __half g_kh[BH * N_SEQ * EDIM];
__device__ __half g_vth[BH * EDIM * N_SEQ];

// ---------------------------------------------------------------------------
// Base-target-safe PTX helpers (sm_80+ features only)
// ---------------------------------------------------------------------------
__device__ __forceinline__ uint32_t smem_u32(const void* p) {
    uint32_t a;
    asm("{ .reg .u64 t; cvta.to.shared.u64 t, %1; cvt.u32.u64 %0, t; }" : "=r"(a) : "l"(p));
    return a;
}

#define CP16(s, g) \
    asm volatile("cp.async.cg.shared.global [%0], [%1], 16;" :: "r"(s), "l"(g) : "memory")
#define CPCOMMIT() asm volatile("cp.async.commit_group;" ::: "memory")
#define CPWAIT(n)  asm volatile("cp.async.wait_group %0;" :: "n"(n) : "memory")

#define LDSM4(R, addr)                                                            \
    asm volatile("ldmatrix.sync.aligned.m8n8.x4.shared.b16 {%0,%1,%2,%3}, [%4];"  \
        : "=r"((R)[0]), "=r"((R)[1]), "=r"((R)[2]), "=r"((R)[3]) : "r"(addr))

#define MMAH16816(d, a, b)                                                        \
    asm volatile("mma.sync.aligned.m16n8k16.row.col.f32.f16.f16.f32 "             \
        "{%0,%1,%2,%3}, {%4,%5,%6,%7}, {%8,%9}, {%0,%1,%2,%3};"                   \
        : "+f"((d)[0]), "+f"((d)[1]), "+f"((d)[2]), "+f"((d)[3])                  \
        : "r"((a)[0]), "r"((a)[1]), "r"((a)[2]), "r"((a)[3]),                     \
          "r"((b)[0]), "r"((b)[1]))

// split pair of fp32 into packed fp16 hi / lo words
__device__ __forceinline__ void split2h(float a, float b, uint32_t& h2, uint32_t& l2) {
    __half2 hh = __floats2half2_rn(a, b);
    float fa = __low2float(hh), fb = __high2float(hh);
    __half2 ll = __floats2half2_rn(a - fa, b - fb);
    h2 = *(uint32_t*)&hh;
    l2 = *(uint32_t*)&ll;
}

__device__ __forceinline__ uint32_t pack2h(float a, float b) {
    __half2 hh = __floats2half2_rn(a, b);
    return *(uint32_t*)&hh;
}

// ---------------------------------------------------------------------------
// Split fp32 -> (hi, lo) fp16 pairs   /   fp32 -> fp16 (hi only)
// ---------------------------------------------------------------------------
__global__ __launch_bounds__(256) void split_f16_k(const float* __restrict__ s,
                                                   __half* __restrict__ hi,
                                                   __half* __restrict__ lo, int n4)
{
    int i = blockIdx.x * 256 + threadIdx.x;
    if (i >= n4) return;
    float4 v = ((const float4*)s)[i];
    uint32_t h0, l0, h1, l1;
    split2h(v.x, v.y, h0, l0);
    split2h(v.z, v.w, h1, l1);
    ((uint32_t*)hi)[i * 2 + 0] = h0;
    ((uint32_t*)hi)[i * 2 + 1] = h1;
    ((uint32_t*)lo)[i * 2 + 0] = l0;
    ((uint32_t*)lo)[i * 2 + 1] = l1;
}

__global__ __launch_bounds__(256) void tohalf_k(const float* __restrict__ s,
                                                __half* __restrict__ hi, int n4)
{
    int i = blockIdx.x * 256 + threadIdx.x;
    if (i >= n4) return;
    float4 v = ((const float4*)s)[i];
    ((__half2*)hi)[i * 2 + 0] = __floats2half2_rn(v.x, v.y);
    ((__half2*)hi)[i * 2 + 1] = __floats2half2_rn(v.z, v.w);
}

// ---------------------------------------------------------------------------
// mma.sync GEMM: C[m,c] = sum_k A[m,k]*B[c,k], fp16.
// TERMS=2: D = Ah*Bh + Al*Bh (A split).  TERMS=1: D = Ah*Bh.
// 128x128 block tile, 8 warps in 4(m) x 2(n) grid, 32x64 warp tile,
// K-chunk 32, 3-stage cp.async, 2 CTAs/SM.
// MODE 0: fused QKV proj; MODE 1: out proj -> fp32 out + bias
// ---------------------------------------------------------------------------
#define STR     40
#define MATB    (128 * STR * 2)        // 10240 bytes per matrix per stage
#define STAGES  3
#define NKC     (KDIM / 32)            // 32 k-chunks

template <int MODE, int TERMS>
__global__ __launch_bounds__(256, 2) void gemm_mma(
    const __half* __restrict__ Agh, const __half* __restrict__ Agl,
    const __half* __restrict__ Bgh,
    const float* __restrict__ bias, float* __restrict__ out)
{
    constexpr uint32_t TSTAGEB = (TERMS + 1) * MATB;   // Ah [, Al], Bh
    extern __shared__ char dsm[];
    const uint32_t sb0 = smem_u32(dsm);

    const int tid  = threadIdx.x;
    const int wid  = tid >> 5;
    const int lane = tid & 31;
    const int wm   = wid & 3;           // 0..3 (m rows of warp grid)
    const int wn   = wid >> 2;          // 0..1 (n cols of warp grid)
    const int rowBase = blockIdx.y * 128;
    const int colBase = blockIdx.x * 128;

    const int lr  = tid >> 1;
    const int lh  = tid & 1;
    const uint32_t soff = (uint32_t)(lr * STR + lh * 16) * 2;
    const size_t gAoff = (size_t)(rowBase + lr) * KDIM + lh * 16;
    const size_t gBoff = (size_t)(colBase + lr) * KDIM + lh * 16;

    const uint32_t aoff  = (uint32_t)((lane & 15) * STR + ((lane >> 4) << 3)) * 2;
    const uint32_t boff4 = (uint32_t)(((lane & 7) + ((lane >> 4) << 3)) * STR
                                      + (((lane >> 3) & 1) << 3)) * 2;

    float acc[2][8][4];
#pragma unroll
    for (int mi = 0; mi < 2; mi++)
#pragma unroll
        for (int ni = 0; ni < 8; ni++)
#pragma unroll
            for (int q = 0; q < 4; q++) acc[mi][ni][q] = 0.f;

    auto load_stage = [&](uint32_t st, size_t ko) {
        CP16(st + soff,      Agh + gAoff + ko);
        CP16(st + soff + 16, Agh + gAoff + ko + 8);
        if (TERMS == 2) {
            CP16(st + MATB + soff,      Agl + gAoff + ko);
            CP16(st + MATB + soff + 16, Agl + gAoff + ko + 8);
        }
        CP16(st + TERMS * MATB + soff,      Bgh + gBoff + ko);
        CP16(st + TERMS * MATB + soff + 16, Bgh + gBoff + ko + 8);
        CPCOMMIT();
    };

    load_stage(sb0,           0);
    load_stage(sb0 + TSTAGEB, 32);

    for (int kc = 0; kc < NKC; kc++) {
        if (kc + 1 < NKC) CPWAIT(1); else CPWAIT(0);
        __syncthreads();   // all warps done computing kc-1 -> its buffer reusable
        if (kc + 2 < NKC) load_stage(sb0 + ((kc + 2) % STAGES) * TSTAGEB, (size_t)(kc + 2) * 32);

        const uint32_t st = sb0 + (kc % STAGES) * TSTAGEB;
        const uint32_t sAh = st, sAl = st + MATB, sBh = st + TERMS * MATB;

#pragma unroll
        for (int ks = 0; ks < 2; ks++) {
            const uint32_t kso = (uint32_t)(ks * 16) * 2;

            uint32_t bh4[4][4];
#pragma unroll
            for (int p = 0; p < 4; p++) {
                const uint32_t nb = (uint32_t)((wn * 64 + p * 16) * STR) * 2 + kso;
                LDSM4(bh4[p], sBh + nb + boff4);
            }
#pragma unroll
            for (int mi = 0; mi < 2; mi++) {
                const uint32_t mb = (uint32_t)((wm * 32 + mi * 16) * STR) * 2 + kso;
                uint32_t ah[4], al[4];
                LDSM4(ah, sAh + mb + aoff);
                if (TERMS == 2) LDSM4(al, sAl + mb + aoff);
#pragma unroll
                for (int ni = 0; ni < 8; ni++) {
                    uint32_t* bh = &bh4[ni >> 1][(ni & 1) * 2];
                    MMAH16816(acc[mi][ni], ah, bh);
                    if (TERMS == 2) MMAH16816(acc[mi][ni], al, bh);
                }
            }
        }
    }

    // ---- epilogue ----
    const int qrow = lane >> 2;
    const int qcol = lane & 3;
#pragma unroll
    for (int mi = 0; mi < 2; mi++) {
#pragma unroll
        for (int ni = 0; ni < 8; ni++) {
            const int c  = colBase + wn * 64 + ni * 8 + qcol * 2;
            const int m0 = rowBase + wm * 32 + mi * 16 + qrow;
            const int m1 = m0 + 8;
            float2 v0 = make_float2(acc[mi][ni][0], acc[mi][ni][1]);
            float2 v1 = make_float2(acc[mi][ni][2], acc[mi][ni][3]);
            const int b0 = m0 >> 11, n0 = m0 & 2047;
            const int b1 = m1 >> 11, n1 = m1 & 2047;
            if (MODE == 0) {
                if (c < HID) {
                    // Q: scale by 1/8 (exact), fp16 split, [bh, n, e]
                    const int h = c >> 6, e = c & 63;
                    const size_t i0 = ((size_t)(b0 * HEADS + h) * N_SEQ + n0) * EDIM + e;
                    const size_t i1 = ((size_t)(b1 * HEADS + h) * N_SEQ + n1) * EDIM + e;
                    uint32_t h2, l2;
                    split2h(v0.x * 0.125f, v0.y * 0.125f, h2, l2);
                    *(uint32_t*)&g_qh[i0] = h2; *(uint32_t*)&g_ql[i0] = l2;
                    split2h(v1.x * 0.125f, v1.y * 0.125f, h2, l2);
                    *(uint32_t*)&g_qh[i1] = h2; *(uint32_t*)&g_ql[i1] = l2;
                } else if (c < 2 * HID) {
                    // K: fp16 hi only, [bh, n, e]
                    const int c2 = c - HID;
                    const int h = c2 >> 6, e = c2 & 63;
                    const size_t i0 = ((size_t)(b0 * HEADS + h) * N_SEQ + n0) * EDIM + e;
                    const size_t i1 = ((size_t)(b1 * HEADS + h) * N_SEQ + n1) * EDIM + e;
                    *(__half2*)&g_kh[i0] = __floats2half2_rn(v0.x, v0.y);
                    *(__half2*)&g_kh[i1] = __floats2half2_rn(v1.x, v1.y);
                } else {
                    // V: fp16 hi only, TRANSPOSED [bh, e, n]
                    const int c2 = c - 2 * HID;
                    const int h = c2 >> 6, e = c2 & 63;
                    const int bh0 = b0 * HEADS + h, bh1 = b1 * HEADS + h;
                    g_vth[((size_t)bh0 * EDIM + e)     * N_SEQ + n0] = __float2half(v0.x);
                    g_vth[((size_t)bh0 * EDIM + e + 1) * N_SEQ + n0] = __float2half(v0.y);
                    g_vth[((size_t)bh1 * EDIM + e)     * N_SEQ + n1] = __float2half(v1.x);
                    g_vth[((size_t)bh1 * EDIM + e + 1) * N_SEQ + n1] = __float2half(v1.y);
                }
            } else {
                const float2 bb = *(const float2*)&bias[c];
                v0.x += bb.x; v0.y += bb.y;
                v1.x += bb.x; v1.y += bb.y;
                *(float2*)&out[(size_t)m0 * HID + c] = v0;
                *(float2*)&out[(size_t)m1 * HID + c] = v1;
            }
        }
    }
}

// ---------------------------------------------------------------------------
// Tensor-core flash attention (fp16, fp32 accum, online softmax).
// grid = (N_SEQ/128, BH), 256 threads (8 warps x 16 Q-rows), 2 CTAs/SM.
// K/V tiles of 64 keys (hi-only), 3-stage cp.async, one sync per tile.
// S = Qh*Kh + Ql*Kh (2-term) ; O += Ph*Vh (1-term, P in [0,1]).
// Output: fp16 hi only (out-proj is 1-term).
// ---------------------------------------------------------------------------
#define ASTR   72                      // smem row stride in fp16 (144 B)
#define AMATB  (64 * ASTR * 2)         // 9216 bytes per matrix
#define ASTGB  (2 * AMATB)             // 18432 per stage (Kh, Vh)
#define ASTAGES 3
#define NT     (N_SEQ / 64)            // 32 key tiles

__global__ __launch_bounds__(256, 2) void attn_mma()
{
    extern __shared__ char dsm[];
    const uint32_t sb = smem_u32(dsm);

    const int tid  = threadIdx.x;
    const int wid  = tid >> 5;
    const int lane = tid & 31;
    const int qg   = lane >> 2;          // 0..7
    const int tig  = lane & 3;           // 0..3

    const int bh    = blockIdx.y;
    const int qbase = blockIdx.x * 128 + wid * 16;
    const size_t kvbase = (size_t)bh * N_SEQ * EDIM;

    uint32_t qhf[4][4], qlf[4][4];
    {
        const size_t q0 = kvbase + (size_t)(qbase + qg) * EDIM;
        const size_t q8 = q0 + 8 * EDIM;
#pragma unroll
        for (int kc = 0; kc < 4; kc++) {
            const int col = kc * 16 + tig * 2;
            qhf[kc][0] = *(const uint32_t*)&g_qh[q0 + col];
            qhf[kc][1] = *(const uint32_t*)&g_qh[q8 + col];
            qhf[kc][2] = *(const uint32_t*)&g_qh[q0 + col + 8];
            qhf[kc][3] = *(const uint32_t*)&g_qh[q8 + col + 8];
            qlf[kc][0] = *(const uint32_t*)&g_ql[q0 + col];
            qlf[kc][1] = *(const uint32_t*)&g_ql[q8 + col];
            qlf[kc][2] = *(const uint32_t*)&g_ql[q0 + col + 8];
            qlf[kc][3] = *(const uint32_t*)&g_ql[q8 + col + 8];
        }
    }

    float oacc[8][4];
#pragma unroll
    for (int ne = 0; ne < 8; ne++)
#pragma unroll
        for (int q = 0; q < 4; q++) oacc[ne][q] = 0.f;
    float m0 = -1e30f, m1 = -1e30f, lp0 = 0.f, lp1 = 0.f;

    const uint32_t OKH = 0, OVH = AMATB;

#define AT_LOAD(stg, kt)                                                        \
    do {                                                                        \
        _Pragma("unroll")                                                       \
        for (int t = 0; t < 2; t++) {                                           \
            const int idx = tid + t * 256;                                      \
            const int r = idx >> 3, ch = idx & 7;                               \
            const uint32_t so = (stg) + (uint32_t)(r * 144 + ch * 16);          \
            const size_t kg = kvbase + (size_t)((kt) * 64 + r) * EDIM + ch * 8; \
            const size_t vg = kvbase + (size_t)r * N_SEQ + (kt) * 64 + ch * 8;  \
            CP16(so + OKH, g_kh  + kg);                                         \
            CP16(so + OVH, g_vth + vg);                                         \
        }                                                                       \
        CPCOMMIT();                                                             \
    } while (0)

    AT_LOAD(sb, 0);
    AT_LOAD(sb + ASTGB, 1);

    const uint32_t lm4 = (uint32_t)(((lane & 7) + ((lane >> 4) << 3)) * ASTR
                                    + (((lane >> 3) & 1) << 3)) * 2;

    for (int kt = 0; kt < NT; kt++) {
        if (kt + 1 < NT) CPWAIT(1); else CPWAIT(0);
        __syncthreads();
        if (kt + 2 < NT) AT_LOAD(sb + ((kt + 2) % ASTAGES) * ASTGB, kt + 2);

        const uint32_t stg = sb + (kt % ASTAGES) * ASTGB;

        // ---- S = Q @ K^T (2-term) ----
        float sacc[8][4];
#pragma unroll
        for (int nt = 0; nt < 8; nt++)
#pragma unroll
            for (int q = 0; q < 4; q++) sacc[nt][q] = 0.f;

#pragma unroll
        for (int kc = 0; kc < 4; kc++) {
            const uint32_t kso = (uint32_t)(kc * 16) * 2;
#pragma unroll
            for (int ntp = 0; ntp < 4; ntp++) {
                uint32_t kh4[4];
                const uint32_t off = (uint32_t)(ntp * 16 * ASTR) * 2 + kso + lm4;
                LDSM4(kh4, stg + OKH + off);
                MMAH16816(sacc[2 * ntp],     qhf[kc], kh4);
                MMAH16816(sacc[2 * ntp],     qlf[kc], kh4);
                MMAH16816(sacc[2 * ntp + 1], qhf[kc], (kh4 + 2));
                MMAH16816(sacc[2 * ntp + 1], qlf[kc], (kh4 + 2));
            }
        }

        // ---- online softmax ----
        float mx0 = -1e30f, mx1 = -1e30f;
#pragma unroll
        for (int nt = 0; nt < 8; nt++) {
            mx0 = fmaxf(mx0, fmaxf(sacc[nt][0], sacc[nt][1]));
            mx1 = fmaxf(mx1, fmaxf(sacc[nt][2], sacc[nt][3]));
        }
        mx0 = fmaxf(mx0, __shfl_xor_sync(0xffffffffu, mx0, 1));
        mx0 = fmaxf(mx0, __shfl_xor_sync(0xffffffffu, mx0, 2));
        mx1 = fmaxf(mx1, __shfl_xor_sync(0xffffffffu, mx1, 1));
        mx1 = fmaxf(mx1, __shfl_xor_sync(0xffffffffu, mx1, 2));

        const float mn0 = fmaxf(m0, mx0), mn1 = fmaxf(m1, mx1);
        const float corr0 = __expf(m0 - mn0), corr1 = __expf(m1 - mn1);
        m0 = mn0; m1 = mn1;

        float ls0 = 0.f, ls1 = 0.f;
#pragma unroll
        for (int nt = 0; nt < 8; nt++) {
            sacc[nt][0] = __expf(sacc[nt][0] - mn0);
            sacc[nt][1] = __expf(sacc[nt][1] - mn0);
            sacc[nt][2] = __expf(sacc[nt][2] - mn1);
            sacc[nt][3] = __expf(sacc[nt][3] - mn1);
            ls0 += sacc[nt][0] + sacc[nt][1];
            ls1 += sacc[nt][2] + sacc[nt][3];
        }
        lp0 = lp0 * corr0 + ls0;
        lp1 = lp1 * corr1 + ls1;

#pragma unroll
        for (int ne = 0; ne < 8; ne++) {
            oacc[ne][0] *= corr0; oacc[ne][1] *= corr0;
            oacc[ne][2] *= corr1; oacc[ne][3] *= corr1;
        }

        // ---- pack P (A-fragments for PV), fp16 hi only ----
        uint32_t phf[4][4];
#pragma unroll
        for (int kc = 0; kc < 4; kc++) {
            phf[kc][0] = pack2h(sacc[2 * kc][0],     sacc[2 * kc][1]);
            phf[kc][1] = pack2h(sacc[2 * kc][2],     sacc[2 * kc][3]);
            phf[kc][2] = pack2h(sacc[2 * kc + 1][0], sacc[2 * kc + 1][1]);
            phf[kc][3] = pack2h(sacc[2 * kc + 1][2], sacc[2 * kc + 1][3]);
        }

        // ---- O += P @ V (1-term) ----
#pragma unroll
        for (int kc = 0; kc < 4; kc++) {
            const uint32_t kso = (uint32_t)(kc * 16) * 2;
#pragma unroll
            for (int nep = 0; nep < 4; nep++) {
                uint32_t vh4[4];
                const uint32_t off = (uint32_t)(nep * 16 * ASTR) * 2 + kso + lm4;
                LDSM4(vh4, stg + OVH + off);
                MMAH16816(oacc[2 * nep],     phf[kc], vh4);
                MMAH16816(oacc[2 * nep + 1], phf[kc], (vh4 + 2));
            }
        }
    }

    // ---- finalize: O / l, fp16 hi at [b, n, h*64 + e] ----
    lp0 += __shfl_xor_sync(0xffffffffu, lp0, 1);
    lp0 += __shfl_xor_sync(0xffffffffu, lp0, 2);
    lp1 += __shfl_xor_sync(0xffffffffu, lp1, 1);
    lp1 += __shfl_xor_sync(0xffffffffu, lp1, 2);
    const float inv0 = 1.f / lp0, inv1 = 1.f / lp1;

    const int b = bh >> 4, h = bh & 15;
    const int n0 = qbase + qg, n1 = n0 + 8;
    const size_t o0 = (size_t)(b * N_SEQ + n0) * HID + h * EDIM;
    const size_t o1 = (size_t)(b * N_SEQ + n1) * HID + h * EDIM;
#pragma unroll
    for (int ne = 0; ne < 8; ne++) {
        const int e = ne * 8 + tig * 2;
        *(uint32_t*)&g_atth[o0 + e] = pack2h(oacc[ne][0] * inv0, oacc[ne][1] * inv0);
        *(uint32_t*)&g_atth[o1 + e] = pack2h(oacc[ne][2] * inv1, oacc[ne][3] * inv1);
    }
}

// ---------------------------------------------------------------------------
extern "C" void kernel_launch(void* const* d_in, const int* in_sizes, int n_in,
                              void* d_out, int out_size)
{
    (void)in_sizes; (void)n_in; (void)out_size;
    const float* x     = (const float*)d_in[0];
    const float* w_q   = (const float*)d_in[1];
    const float* w_kv  = (const float*)d_in[2];
    const float* w_out = (const float*)d_in[3];
    const float* b_out = (const float*)d_in[4];
    float* out = (float*)d_out;

    void *p_xh, *p_xl, *p_wall, *p_woh, *p_ath;
    cudaGetSymbolAddress(&p_xh, g_xh);     cudaGetSymbolAddress(&p_xl, g_xl);
    cudaGetSymbolAddress(&p_wall, g_wall);
    cudaGetSymbolAddress(&p_woh, g_woh);
    cudaGetSymbolAddress(&p_ath, g_atth);

    const int gemm_smem2 = STAGES * 3 * MATB;   // 92160 (TERMS=2)
    const int gemm_smem1 = STAGES * 2 * MATB;   // 61440 (TERMS=1)
    cudaFuncSetAttribute((const void*)gemm_mma<0, 2>, cudaFuncAttributeMaxDynamicSharedMemorySize, gemm_smem2);
    cudaFuncSetAttribute((const void*)gemm_mma<1, 1>, cudaFuncAttributeMaxDynamicSharedMemorySize, gemm_smem1);
    const int attn_smem = ASTAGES * ASTGB;      // 55296
    cudaFuncSetAttribute(attn_mma, cudaFuncAttributeMaxDynamicSharedMemorySize, attn_smem);

    // 1) Split x into fp16 hi/lo; weights to fp16 hi only (fused [w_q; w_kv])
    split_f16_k<<<(M_TOT * KDIM / 4 + 255) / 256, 256>>>(x, (__half*)p_xh, (__half*)p_xl, M_TOT * KDIM / 4);
    tohalf_k<<<(HID * KDIM / 4 + 255) / 256, 256>>>(w_q, (__half*)p_wall, HID * KDIM / 4);
    tohalf_k<<<(2 * HID * KDIM / 4 + 255) / 256, 256>>>(w_kv, (__half*)p_wall + HID * KDIM, 2 * HID * KDIM / 4);
    tohalf_k<<<(HID * KDIM / 4 + 255) / 256, 256>>>(w_out, (__half*)p_woh, HID * KDIM / 4);

    // 2) Fused QKV projection (fp16 2-term mma.sync)
    gemm_mma<0, 2><<<dim3(3 * HID / 128, M_TOT / 128), 256, gemm_smem2>>>(
        (const __half*)p_xh, (const __half*)p_xl, (const __half*)p_wall, nullptr, nullptr);

    // 3) Attention (fp16 mma.sync flash attention, QK 2-term / PV 1-term)
    attn_mma<<<dim3(N_SEQ / 128, BH), 256, attn_smem>>>();

    // 4) Output projection + bias (fp16 1-term mma.sync)
    gemm_mma<1, 1><<<dim3(HID / 128, M_TOT / 128), 256, gemm_smem1>>>(
        (const __half*)p_ath, nullptr, (const __half*)p_woh, b_out, out);
}

// round 12
// speedup vs baseline: 6.1962x; 1.1097x over previous
#include <cuda_runtime.h>
#include <cuda_bf16.h>
#include <cuda_fp16.h>
#include <cstdint>

// Problem constants
#define B_SZ   4
#define N_SEQ  2048
#define HEADS  16
#define EDIM   64
#define KDIM   1024
#define M_TOT  (B_SZ * N_SEQ)          // 8192
#define HID    (HEADS * EDIM)          // 1024
#define BH     (B_SZ * HEADS)          // 64

// ---------------------------------------------------------------------------
// Scratch (device globals — no allocation allowed)
// ---------------------------------------------------------------------------
__device__ __half g_xh[M_TOT * KDIM],  g_xl[M_TOT * KDIM];
__device__ __half g_wall[3 * HID * KDIM];          // [w_q ; w_kv], fp16 hi
__device__ __half g_woh[HID * KDIM];
__device__ __half g_atth[M_TOT * HID];             // attention out, fp16 hi only

// fp16 attention operands: Q hi/lo ([bh, n, e]); K hi ([bh, n, e]); V hi transposed ([bh, e, n])
__device__ __half g_qh[BH * N_SEQ * EDIM], g_ql[BH * N_SEQ * EDIM];
__device__ __half g_kh[BH * N_SEQ * EDIM];
__device__ __half g_vth[BH * EDIM * N_SEQ];

// ---------------------------------------------------------------------------
// Base-target-safe PTX helpers (sm_80+ features only)
// ---------------------------------------------------------------------------
__device__ __forceinline__ uint32_t smem_u32(const void* p) {
    uint32_t a;
    asm("{ .reg .u64 t; cvta.to.shared.u64 t, %1; cvt.u32.u64 %0, t; }" : "=r"(a) : "l"(p));
    return a;
}

#define CP16(s, g) \
    asm volatile("cp.async.cg.shared.global [%0], [%1], 16;" :: "r"(s), "l"(g) : "memory")
#define CPCOMMIT() asm volatile("cp.async.commit_group;" ::: "memory")
#define CPWAIT(n)  asm volatile("cp.async.wait_group %0;" :: "n"(n) : "memory")

#define LDSM4(R, addr)                                                            \
    asm volatile("ldmatrix.sync.aligned.m8n8.x4.shared.b16 {%0,%1,%2,%3}, [%4];"  \
        : "=r"((R)[0]), "=r"((R)[1]), "=r"((R)[2]), "=r"((R)[3]) : "r"(addr))

#define MMAH16816(d, a, b)                                                        \
    asm volatile("mma.sync.aligned.m16n8k16.row.col.f32.f16.f16.f32 "             \
        "{%0,%1,%2,%3}, {%4,%5,%6,%7}, {%8,%9}, {%0,%1,%2,%3};"                   \
        : "+f"((d)[0]), "+f"((d)[1]), "+f"((d)[2]), "+f"((d)[3])                  \
        : "r"((a)[0]), "r"((a)[1]), "r"((a)[2]), "r"((a)[3]),                     \
          "r"((b)[0]), "r"((b)[1]))

// split pair of fp32 into packed fp16 hi / lo words
__device__ __forceinline__ void split2h(float a, float b, uint32_t& h2, uint32_t& l2) {
    __half2 hh = __floats2half2_rn(a, b);
    float fa = __low2float(hh), fb = __high2float(hh);
    __half2 ll = __floats2half2_rn(a - fa, b - fb);
    h2 = *(uint32_t*)&hh;
    l2 = *(uint32_t*)&ll;
}

__device__ __forceinline__ uint32_t pack2h(float a, float b) {
    __half2 hh = __floats2half2_rn(a, b);
    return *(uint32_t*)&hh;
}

// ---------------------------------------------------------------------------
// Split fp32 -> (hi, lo) fp16 pairs   /   fp32 -> fp16 (hi only)
// ---------------------------------------------------------------------------
__global__ __launch_bounds__(256) void split_f16_k(const float* __restrict__ s,
                                                   __half* __restrict__ hi,
                                                   __half* __restrict__ lo, int n4)
{
    int i = blockIdx.x * 256 + threadIdx.x;
    if (i >= n4) return;
    float4 v = ((const float4*)s)[i];
    uint32_t h0, l0, h1, l1;
    split2h(v.x, v.y, h0, l0);
    split2h(v.z, v.w, h1, l1);
    ((uint32_t*)hi)[i * 2 + 0] = h0;
    ((uint32_t*)hi)[i * 2 + 1] = h1;
    ((uint32_t*)lo)[i * 2 + 0] = l0;
    ((uint32_t*)lo)[i * 2 + 1] = l1;
}

__global__ __launch_bounds__(256) void tohalf_k(const float* __restrict__ s,
                                                __half* __restrict__ hi, int n4)
{
    int i = blockIdx.x * 256 + threadIdx.x;
    if (i >= n4) return;
    float4 v = ((const float4*)s)[i];
    ((__half2*)hi)[i * 2 + 0] = __floats2half2_rn(v.x, v.y);
    ((__half2*)hi)[i * 2 + 1] = __floats2half2_rn(v.z, v.w);
}

// ---------------------------------------------------------------------------
// mma.sync GEMM: C[m,c] = sum_k A[m,k]*B[c,k], fp16.
// TERMS=2: D = Ah*Bh + Al*Bh (A split).  TERMS=1: D = Ah*Bh.
// 128x128 block tile, 8 warps in 4(m) x 2(n) grid, 32x64 warp tile,
// K-chunk 32, 3-stage cp.async, 2 CTAs/SM.
// MODE 0: Q proj (TERMS=2) -> fp16 split g_qh/g_ql (x0.125)
// MODE 1: KV proj (TERMS=1) -> K hi, V hi transposed
// MODE 2: out proj (TERMS=1) -> fp32 out + bias
// ---------------------------------------------------------------------------
#define STR     40
#define MATB    (128 * STR * 2)        // 10240 bytes per matrix per stage
#define STAGES  3
#define NKC     (KDIM / 32)            // 32 k-chunks

template <int MODE, int TERMS>
__global__ __launch_bounds__(256, 2) void gemm_mma(
    const __half* __restrict__ Agh, const __half* __restrict__ Agl,
    const __half* __restrict__ Bgh,
    const float* __restrict__ bias, float* __restrict__ out)
{
    constexpr uint32_t TSTAGEB = (TERMS + 1) * MATB;   // Ah [, Al], Bh
    extern __shared__ char dsm[];
    const uint32_t sb0 = smem_u32(dsm);

    const int tid  = threadIdx.x;
    const int wid  = tid >> 5;
    const int lane = tid & 31;
    const int wm   = wid & 3;           // 0..3 (m rows of warp grid)
    const int wn   = wid >> 2;          // 0..1 (n cols of warp grid)
    const int rowBase = blockIdx.y * 128;
    const int colBase = blockIdx.x * 128;

    const int lr  = tid >> 1;
    const int lh  = tid & 1;
    const uint32_t soff = (uint32_t)(lr * STR + lh * 16) * 2;
    const size_t gAoff = (size_t)(rowBase + lr) * KDIM + lh * 16;
    const size_t gBoff = (size_t)(colBase + lr) * KDIM + lh * 16;

    const uint32_t aoff  = (uint32_t)((lane & 15) * STR + ((lane >> 4) << 3)) * 2;
    const uint32_t boff4 = (uint32_t)(((lane & 7) + ((lane >> 4) << 3)) * STR
                                      + (((lane >> 3) & 1) << 3)) * 2;

    float acc[2][8][4];
#pragma unroll
    for (int mi = 0; mi < 2; mi++)
#pragma unroll
        for (int ni = 0; ni < 8; ni++)
#pragma unroll
            for (int q = 0; q < 4; q++) acc[mi][ni][q] = 0.f;

    auto load_stage = [&](uint32_t st, size_t ko) {
        CP16(st + soff,      Agh + gAoff + ko);
        CP16(st + soff + 16, Agh + gAoff + ko + 8);
        if (TERMS == 2) {
            CP16(st + MATB + soff,      Agl + gAoff + ko);
            CP16(st + MATB + soff + 16, Agl + gAoff + ko + 8);
        }
        CP16(st + TERMS * MATB + soff,      Bgh + gBoff + ko);
        CP16(st + TERMS * MATB + soff + 16, Bgh + gBoff + ko + 8);
        CPCOMMIT();
    };

    load_stage(sb0,           0);
    load_stage(sb0 + TSTAGEB, 32);

    for (int kc = 0; kc < NKC; kc++) {
        if (kc + 1 < NKC) CPWAIT(1); else CPWAIT(0);
        __syncthreads();   // all warps done computing kc-1 -> its buffer reusable
        if (kc + 2 < NKC) load_stage(sb0 + ((kc + 2) % STAGES) * TSTAGEB, (size_t)(kc + 2) * 32);

        const uint32_t st = sb0 + (kc % STAGES) * TSTAGEB;
        const uint32_t sAh = st, sAl = st + MATB, sBh = st + TERMS * MATB;

#pragma unroll
        for (int ks = 0; ks < 2; ks++) {
            const uint32_t kso = (uint32_t)(ks * 16) * 2;

            uint32_t bh4[4][4];
#pragma unroll
            for (int p = 0; p < 4; p++) {
                const uint32_t nb = (uint32_t)((wn * 64 + p * 16) * STR) * 2 + kso;
                LDSM4(bh4[p], sBh + nb + boff4);
            }
#pragma unroll
            for (int mi = 0; mi < 2; mi++) {
                const uint32_t mb = (uint32_t)((wm * 32 + mi * 16) * STR) * 2 + kso;
                uint32_t ah[4], al[4];
                LDSM4(ah, sAh + mb + aoff);
                if (TERMS == 2) LDSM4(al, sAl + mb + aoff);
#pragma unroll
                for (int ni = 0; ni < 8; ni++) {
                    uint32_t* bh = &bh4[ni >> 1][(ni & 1) * 2];
                    MMAH16816(acc[mi][ni], ah, bh);
                    if (TERMS == 2) MMAH16816(acc[mi][ni], al, bh);
                }
            }
        }
    }

    // ---- epilogue ----
    const int qrow = lane >> 2;
    const int qcol = lane & 3;
#pragma unroll
    for (int mi = 0; mi < 2; mi++) {
#pragma unroll
        for (int ni = 0; ni < 8; ni++) {
            const int c  = colBase + wn * 64 + ni * 8 + qcol * 2;
            const int m0 = rowBase + wm * 32 + mi * 16 + qrow;
            const int m1 = m0 + 8;
            float2 v0 = make_float2(acc[mi][ni][0], acc[mi][ni][1]);
            float2 v1 = make_float2(acc[mi][ni][2], acc[mi][ni][3]);
            const int b0 = m0 >> 11, n0 = m0 & 2047;
            const int b1 = m1 >> 11, n1 = m1 & 2047;
            if (MODE == 0) {
                // Q: scale by 1/8 (exact), fp16 split, [bh, n, e]
                const int h = c >> 6, e = c & 63;
                const size_t i0 = ((size_t)(b0 * HEADS + h) * N_SEQ + n0) * EDIM + e;
                const size_t i1 = ((size_t)(b1 * HEADS + h) * N_SEQ + n1) * EDIM + e;
                uint32_t h2, l2;
                split2h(v0.x * 0.125f, v0.y * 0.125f, h2, l2);
                *(uint32_t*)&g_qh[i0] = h2; *(uint32_t*)&g_ql[i0] = l2;
                split2h(v1.x * 0.125f, v1.y * 0.125f, h2, l2);
                *(uint32_t*)&g_qh[i1] = h2; *(uint32_t*)&g_ql[i1] = l2;
            } else if (MODE == 1) {
                if (c < HID) {
                    // K: fp16 hi only, [bh, n, e]
                    const int h = c >> 6, e = c & 63;
                    const size_t i0 = ((size_t)(b0 * HEADS + h) * N_SEQ + n0) * EDIM + e;
                    const size_t i1 = ((size_t)(b1 * HEADS + h) * N_SEQ + n1) * EDIM + e;
                    *(__half2*)&g_kh[i0] = __floats2half2_rn(v0.x, v0.y);
                    *(__half2*)&g_kh[i1] = __floats2half2_rn(v1.x, v1.y);
                } else {
                    // V: fp16 hi only, TRANSPOSED [bh, e, n]
                    const int c2 = c - HID;
                    const int h = c2 >> 6, e = c2 & 63;
                    const int bh0 = b0 * HEADS + h, bh1 = b1 * HEADS + h;
                    g_vth[((size_t)bh0 * EDIM + e)     * N_SEQ + n0] = __float2half(v0.x);
                    g_vth[((size_t)bh0 * EDIM + e + 1) * N_SEQ + n0] = __float2half(v0.y);
                    g_vth[((size_t)bh1 * EDIM + e)     * N_SEQ + n1] = __float2half(v1.x);
                    g_vth[((size_t)bh1 * EDIM + e + 1) * N_SEQ + n1] = __float2half(v1.y);
                }
            } else {
                const float2 bb = *(const float2*)&bias[c];
                v0.x += bb.x; v0.y += bb.y;
                v1.x += bb.x; v1.y += bb.y;
                *(float2*)&out[(size_t)m0 * HID + c] = v0;
                *(float2*)&out[(size_t)m1 * HID + c] = v1;
            }
        }
    }
}

// ---------------------------------------------------------------------------
// Tensor-core flash attention (fp16, fp32 accum, online softmax).
// grid = (N_SEQ/128, BH), 256 threads (8 warps x 16 Q-rows), 2 CTAs/SM.
// K/V tiles of 64 keys (hi-only), 3-stage cp.async, one sync per tile.
// S = Qh*Kh + Ql*Kh (2-term) ; O += Ph*Vh (1-term, P in [0,1]).
// ---------------------------------------------------------------------------
#define ASTR   72                      // smem row stride in fp16 (144 B)
#define AMATB  (64 * ASTR * 2)         // 9216 bytes per matrix
#define ASTGB  (2 * AMATB)             // 18432 per stage (Kh, Vh)
#define ASTAGES 3
#define NT     (N_SEQ / 64)            // 32 key tiles

__global__ __launch_bounds__(256, 2) void attn_mma()
{
    extern __shared__ char dsm[];
    const uint32_t sb = smem_u32(dsm);

    const int tid  = threadIdx.x;
    const int wid  = tid >> 5;
    const int lane = tid & 31;
    const int qg   = lane >> 2;          // 0..7
    const int tig  = lane & 3;           // 0..3

    const int bh    = blockIdx.y;
    const int qbase = blockIdx.x * 128 + wid * 16;
    const size_t kvbase = (size_t)bh * N_SEQ * EDIM;

    uint32_t qhf[4][4], qlf[4][4];
    {
        const size_t q0 = kvbase + (size_t)(qbase + qg) * EDIM;
        const size_t q8 = q0 + 8 * EDIM;
#pragma unroll
        for (int kc = 0; kc < 4; kc++) {
            const int col = kc * 16 + tig * 2;
            qhf[kc][0] = *(const uint32_t*)&g_qh[q0 + col];
            qhf[kc][1] = *(const uint32_t*)&g_qh[q8 + col];
            qhf[kc][2] = *(const uint32_t*)&g_qh[q0 + col + 8];
            qhf[kc][3] = *(const uint32_t*)&g_qh[q8 + col + 8];
            qlf[kc][0] = *(const uint32_t*)&g_ql[q0 + col];
            qlf[kc][1] = *(const uint32_t*)&g_ql[q8 + col];
            qlf[kc][2] = *(const uint32_t*)&g_ql[q0 + col + 8];
            qlf[kc][3] = *(const uint32_t*)&g_ql[q8 + col + 8];
        }
    }

    float oacc[8][4];
#pragma unroll
    for (int ne = 0; ne < 8; ne++)
#pragma unroll
        for (int q = 0; q < 4; q++) oacc[ne][q] = 0.f;
    float m0 = -1e30f, m1 = -1e30f, lp0 = 0.f, lp1 = 0.f;

    const uint32_t OKH = 0, OVH = AMATB;

#define AT_LOAD(stg, kt)                                                        \
    do {                                                                        \
        _Pragma("unroll")                                                       \
        for (int t = 0; t < 2; t++) {                                           \
            const int idx = tid + t * 256;                                      \
            const int r = idx >> 3, ch = idx & 7;                               \
            const uint32_t so = (stg) + (uint32_t)(r * 144 + ch * 16);          \
            const size_t kg = kvbase + (size_t)((kt) * 64 + r) * EDIM + ch * 8; \
            const size_t vg = kvbase + (size_t)r * N_SEQ + (kt) * 64 + ch * 8;  \
            CP16(so + OKH, g_kh  + kg);                                         \
            CP16(so + OVH, g_vth + vg);                                         \
        }                                                                       \
        CPCOMMIT();                                                             \
    } while (0)

    AT_LOAD(sb, 0);
    AT_LOAD(sb + ASTGB, 1);

    const uint32_t lm4 = (uint32_t)(((lane & 7) + ((lane >> 4) << 3)) * ASTR
                                    + (((lane >> 3) & 1) << 3)) * 2;

    for (int kt = 0; kt < NT; kt++) {
        if (kt + 1 < NT) CPWAIT(1); else CPWAIT(0);
        __syncthreads();
        if (kt + 2 < NT) AT_LOAD(sb + ((kt + 2) % ASTAGES) * ASTGB, kt + 2);

        const uint32_t stg = sb + (kt % ASTAGES) * ASTGB;

        // ---- S = Q @ K^T (2-term) ----
        float sacc[8][4];
#pragma unroll
        for (int nt = 0; nt < 8; nt++)
#pragma unroll
            for (int q = 0; q < 4; q++) sacc[nt][q] = 0.f;

#pragma unroll
        for (int kc = 0; kc < 4; kc++) {
            const uint32_t kso = (uint32_t)(kc * 16) * 2;
#pragma unroll
            for (int ntp = 0; ntp < 4; ntp++) {
                uint32_t kh4[4];
                const uint32_t off = (uint32_t)(ntp * 16 * ASTR) * 2 + kso + lm4;
                LDSM4(kh4, stg + OKH + off);
                MMAH16816(sacc[2 * ntp],     qhf[kc], kh4);
                MMAH16816(sacc[2 * ntp],     qlf[kc], kh4);
                MMAH16816(sacc[2 * ntp + 1], qhf[kc], (kh4 + 2));
                MMAH16816(sacc[2 * ntp + 1], qlf[kc], (kh4 + 2));
            }
        }

        // ---- online softmax ----
        float mx0 = -1e30f, mx1 = -1e30f;
#pragma unroll
        for (int nt = 0; nt < 8; nt++) {
            mx0 = fmaxf(mx0, fmaxf(sacc[nt][0], sacc[nt][1]));
            mx1 = fmaxf(mx1, fmaxf(sacc[nt][2], sacc[nt][3]));
        }
        mx0 = fmaxf(mx0, __shfl_xor_sync(0xffffffffu, mx0, 1));
        mx0 = fmaxf(mx0, __shfl_xor_sync(0xffffffffu, mx0, 2));
        mx1 = fmaxf(mx1, __shfl_xor_sync(0xffffffffu, mx1, 1));
        mx1 = fmaxf(mx1, __shfl_xor_sync(0xffffffffu, mx1, 2));

        const float mn0 = fmaxf(m0, mx0), mn1 = fmaxf(m1, mx1);
        const float corr0 = __expf(m0 - mn0), corr1 = __expf(m1 - mn1);
        m0 = mn0; m1 = mn1;

        float ls0 = 0.f, ls1 = 0.f;
#pragma unroll
        for (int nt = 0; nt < 8; nt++) {
            sacc[nt][0] = __expf(sacc[nt][0] - mn0);
            sacc[nt][1] = __expf(sacc[nt][1] - mn0);
            sacc[nt][2] = __expf(sacc[nt][2] - mn1);
            sacc[nt][3] = __expf(sacc[nt][3] - mn1);
            ls0 += sacc[nt][0] + sacc[nt][1];
            ls1 += sacc[nt][2] + sacc[nt][3];
        }
        lp0 = lp0 * corr0 + ls0;
        lp1 = lp1 * corr1 + ls1;

#pragma unroll
        for (int ne = 0; ne < 8; ne++) {
            oacc[ne][0] *= corr0; oacc[ne][1] *= corr0;
            oacc[ne][2] *= corr1; oacc[ne][3] *= corr1;
        }

        // ---- pack P (A-fragments for PV), fp16 hi only ----
        uint32_t phf[4][4];
#pragma unroll
        for (int kc = 0; kc < 4; kc++) {
            phf[kc][0] = pack2h(sacc[2 * kc][0],     sacc[2 * kc][1]);
            phf[kc][1] = pack2h(sacc[2 * kc][2],     sacc[2 * kc][3]);
            phf[kc][2] = pack2h(sacc[2 * kc + 1][0], sacc[2 * kc + 1][1]);
            phf[kc][3] = pack2h(sacc[2 * kc + 1][2], sacc[2 * kc + 1][3]);
        }

        // ---- O += P @ V (1-term) ----
#pragma unroll
        for (int kc = 0; kc < 4; kc++) {
            const uint32_t kso = (uint32_t)(kc * 16) * 2;
#pragma unroll
            for (int nep = 0; nep < 4; nep++) {
                uint32_t vh4[4];
                const uint32_t off = (uint32_t)(nep * 16 * ASTR) * 2 + kso + lm4;
                LDSM4(vh4, stg + OVH + off);
                MMAH16816(oacc[2 * nep],     phf[kc], vh4);
                MMAH16816(oacc[2 * nep + 1], phf[kc], (vh4 + 2));
            }
        }
    }

    // ---- finalize: O / l, fp16 hi at [b, n, h*64 + e] ----
    lp0 += __shfl_xor_sync(0xffffffffu, lp0, 1);
    lp0 += __shfl_xor_sync(0xffffffffu, lp0, 2);
    lp1 += __shfl_xor_sync(0xffffffffu, lp1, 1);
    lp1 += __shfl_xor_sync(0xffffffffu, lp1, 2);
    const float inv0 = 1.f / lp0, inv1 = 1.f / lp1;

    const int b = bh >> 4, h = bh & 15;
    const int n0 = qbase + qg, n1 = n0 + 8;
    const size_t o0 = (size_t)(b * N_SEQ + n0) * HID + h * EDIM;
    const size_t o1 = (size_t)(b * N_SEQ + n1) * HID + h * EDIM;
#pragma unroll
    for (int ne = 0; ne < 8; ne++) {
        const int e = ne * 8 + tig * 2;
        *(uint32_t*)&g_atth[o0 + e] = pack2h(oacc[ne][0] * inv0, oacc[ne][1] * inv0);
        *(uint32_t*)&g_atth[o1 + e] = pack2h(oacc[ne][2] * inv1, oacc[ne][3] * inv1);
    }
}

// ---------------------------------------------------------------------------
extern "C" void kernel_launch(void* const* d_in, const int* in_sizes, int n_in,
                              void* d_out, int out_size)
{
    (void)in_sizes; (void)n_in; (void)out_size;
    const float* x     = (const float*)d_in[0];
    const float* w_q   = (const float*)d_in[1];
    const float* w_kv  = (const float*)d_in[2];
    const float* w_out = (const float*)d_in[3];
    const float* b_out = (const float*)d_in[4];
    float* out = (float*)d_out;

    void *p_xh, *p_xl, *p_wall, *p_woh, *p_ath;
    cudaGetSymbolAddress(&p_xh, g_xh);     cudaGetSymbolAddress(&p_xl, g_xl);
    cudaGetSymbolAddress(&p_wall, g_wall);
    cudaGetSymbolAddress(&p_woh, g_woh);
    cudaGetSymbolAddress(&p_ath, g_atth);

    const int gemm_smem2 = STAGES * 3 * MATB;   // 92160 (TERMS=2)
    const int gemm_smem1 = STAGES * 2 * MATB;   // 61440 (TERMS=1)
    cudaFuncSetAttribute((const void*)gemm_mma<0, 2>, cudaFuncAttributeMaxDynamicSharedMemorySize, gemm_smem2);
    cudaFuncSetAttribute((const void*)gemm_mma<1, 1>, cudaFuncAttributeMaxDynamicSharedMemorySize, gemm_smem1);
    cudaFuncSetAttribute((const void*)gemm_mma<2, 1>, cudaFuncAttributeMaxDynamicSharedMemorySize, gemm_smem1);
    const int attn_smem = ASTAGES * ASTGB;      // 55296
    cudaFuncSetAttribute(attn_mma, cudaFuncAttributeMaxDynamicSharedMemorySize, attn_smem);

    // 1) Split x into fp16 hi/lo; weights to fp16 hi only
    split_f16_k<<<(M_TOT * KDIM / 4 + 255) / 256, 256>>>(x, (__half*)p_xh, (__half*)p_xl, M_TOT * KDIM / 4);
    tohalf_k<<<(HID * KDIM / 4 + 255) / 256, 256>>>(w_q, (__half*)p_wall, HID * KDIM / 4);
    tohalf_k<<<(2 * HID * KDIM / 4 + 255) / 256, 256>>>(w_kv, (__half*)p_wall + HID * KDIM, 2 * HID * KDIM / 4);
    tohalf_k<<<(HID * KDIM / 4 + 255) / 256, 256>>>(w_out, (__half*)p_woh, HID * KDIM / 4);

    // 2) Q projection (2-term: Q feeds precision-critical logits)
    gemm_mma<0, 2><<<dim3(HID / 128, M_TOT / 128), 256, gemm_smem2>>>(
        (const __half*)p_xh, (const __half*)p_xl, (const __half*)p_wall, nullptr, nullptr);

    // 3) KV projection (1-term: K/V are fp16-rounded on store anyway)
    gemm_mma<1, 1><<<dim3(2 * HID / 128, M_TOT / 128), 256, gemm_smem1>>>(
        (const __half*)p_xh, nullptr, (const __half*)p_wall + HID * KDIM, nullptr, nullptr);

    // 4) Attention (fp16 mma.sync flash attention, QK 2-term / PV 1-term)
    attn_mma<<<dim3(N_SEQ / 128, BH), 256, attn_smem>>>();

    // 5) Output projection + bias (fp16 1-term mma.sync)
    gemm_mma<2, 1><<<dim3(HID / 128, M_TOT / 128), 256, gemm_smem1>>>(
        (const __half*)p_ath, nullptr, (const __half*)p_woh, b_out, out);
}